// round 1
// baseline (speedup 1.0000x reference)
#include <cuda_runtime.h>
#include <math.h>

#define Bc  2
#define SQc 2048
#define SKc 2048
#define Dc  1024
#define Hc  16
#define DHc 64
#define NTOK (Bc*SQc)          // 4096 rows for Q-side and K-side alike (SQ==SK)
#define ELEMS (Bc*SQc*Dc)

// ---------------- scratch (static device arrays; no allocation) ----------------
__device__ float g_Qn[ELEMS];   // LN(Q)
__device__ float g_Kn[ELEMS];   // LN(K)
__device__ float g_Q1[ELEMS];   // Q projection
__device__ float g_K1[ELEMS];   // K projection
__device__ float g_V1[ELEMS];   // V projection
__device__ float g_O1[ELEMS];   // attention output
__device__ float g_O2[ELEMS];   // relu(Qn @ Wo^T + bo)

// ---------------- LayerNorm over last dim (D=1024), one block per row ----------
__global__ __launch_bounds__(256) void ln_kernel(const float* __restrict__ x,
                                                 const float* __restrict__ g,
                                                 const float* __restrict__ b,
                                                 float* __restrict__ y) {
    int row = blockIdx.x;
    int t = threadIdx.x;
    const float4* xr = (const float4*)(x + (size_t)row * Dc);
    float4 v = xr[t];
    float s  = v.x + v.y + v.z + v.w;
    float ss = v.x*v.x + v.y*v.y + v.z*v.z + v.w*v.w;
    #pragma unroll
    for (int o = 16; o > 0; o >>= 1) {
        s  += __shfl_xor_sync(0xffffffffu, s,  o);
        ss += __shfl_xor_sync(0xffffffffu, ss, o);
    }
    __shared__ float red[2][8];
    int w = t >> 5, l = t & 31;
    if (l == 0) { red[0][w] = s; red[1][w] = ss; }
    __syncthreads();
    float st = 0.f, sst = 0.f;
    #pragma unroll
    for (int i = 0; i < 8; i++) { st += red[0][i]; sst += red[1][i]; }
    float mean = st * (1.0f / Dc);
    float var  = sst * (1.0f / Dc) - mean * mean;
    float rstd = rsqrtf(var + 1e-5f);
    float4 gg = ((const float4*)g)[t];
    float4 bb = ((const float4*)b)[t];
    float4 o;
    o.x = (v.x - mean) * rstd * gg.x + bb.x;
    o.y = (v.y - mean) * rstd * gg.y + bb.y;
    o.z = (v.z - mean) * rstd * gg.z + bb.z;
    o.w = (v.w - mean) * rstd * gg.w + bb.w;
    ((float4*)(y + (size_t)row * Dc))[t] = o;
}

// ---------------- fused residual-add + LayerNorm (final) ------------------------
__global__ __launch_bounds__(256) void final_ln_kernel(const float* __restrict__ Q,
                                                       const float* __restrict__ O1,
                                                       const float* __restrict__ O2,
                                                       const float* __restrict__ g,
                                                       const float* __restrict__ b,
                                                       float* __restrict__ out) {
    int row = blockIdx.x;
    int t = threadIdx.x;
    size_t base = (size_t)row * Dc;
    float4 q  = ((const float4*)(Q  + base))[t];
    float4 o1 = ((const float4*)(O1 + base))[t];
    float4 o2 = ((const float4*)(O2 + base))[t];
    float4 v;
    v.x = q.x + o1.x + o2.x;
    v.y = q.y + o1.y + o2.y;
    v.z = q.z + o1.z + o2.z;
    v.w = q.w + o1.w + o2.w;
    float s  = v.x + v.y + v.z + v.w;
    float ss = v.x*v.x + v.y*v.y + v.z*v.z + v.w*v.w;
    #pragma unroll
    for (int o = 16; o > 0; o >>= 1) {
        s  += __shfl_xor_sync(0xffffffffu, s,  o);
        ss += __shfl_xor_sync(0xffffffffu, ss, o);
    }
    __shared__ float red[2][8];
    int w = t >> 5, l = t & 31;
    if (l == 0) { red[0][w] = s; red[1][w] = ss; }
    __syncthreads();
    float st = 0.f, sst = 0.f;
    #pragma unroll
    for (int i = 0; i < 8; i++) { st += red[0][i]; sst += red[1][i]; }
    float mean = st * (1.0f / Dc);
    float var  = sst * (1.0f / Dc) - mean * mean;
    float rstd = rsqrtf(var + 1e-5f);
    float4 gg = ((const float4*)g)[t];
    float4 bb = ((const float4*)b)[t];
    float4 o;
    o.x = (v.x - mean) * rstd * gg.x + bb.x;
    o.y = (v.y - mean) * rstd * gg.y + bb.y;
    o.z = (v.z - mean) * rstd * gg.z + bb.z;
    o.w = (v.w - mean) * rstd * gg.w + bb.w;
    ((float4*)(out + base))[t] = o;
}

// ---------------- C[M,1024] = A[M,1024] @ W[1024,1024]^T + bias (opt relu) -----
// BM=128, BN=64, BK=16, 256 threads, 8x4 per-thread microtile.
#define GBM 128
#define GBN 64
#define GBK 16
__global__ __launch_bounds__(256) void gemm_kernel(const float* __restrict__ A,
                                                   const float* __restrict__ W,
                                                   const float* __restrict__ bias,
                                                   float* __restrict__ C,
                                                   int relu) {
    __shared__ float AsT[GBK][132];  // [k][m], padded
    __shared__ float WsT[GBK][68];   // [k][n], padded
    int tid = threadIdx.x;
    int tx = tid & 15, ty = tid >> 4;
    int m0 = blockIdx.y * GBM;
    int n0 = blockIdx.x * GBN;

    int arow = tid >> 1, ak = (tid & 1) * 8;   // A tile: 128 rows x 16 k
    int wrow = tid >> 2, wk = (tid & 3) * 4;   // W tile: 64 rows x 16 k
    const float* Aptr = A + (size_t)(m0 + arow) * Dc + ak;
    const float* Wptr = W + (size_t)(n0 + wrow) * Dc + wk;

    float acc[8][4];
    #pragma unroll
    for (int i = 0; i < 8; i++)
        #pragma unroll
        for (int j = 0; j < 4; j++) acc[i][j] = 0.f;

    for (int kt = 0; kt < Dc; kt += GBK) {
        float4 a0 = *(const float4*)(Aptr + kt);
        float4 a1 = *(const float4*)(Aptr + kt + 4);
        float4 w0 = *(const float4*)(Wptr + kt);
        AsT[ak+0][arow] = a0.x; AsT[ak+1][arow] = a0.y;
        AsT[ak+2][arow] = a0.z; AsT[ak+3][arow] = a0.w;
        AsT[ak+4][arow] = a1.x; AsT[ak+5][arow] = a1.y;
        AsT[ak+6][arow] = a1.z; AsT[ak+7][arow] = a1.w;
        WsT[wk+0][wrow] = w0.x; WsT[wk+1][wrow] = w0.y;
        WsT[wk+2][wrow] = w0.z; WsT[wk+3][wrow] = w0.w;
        __syncthreads();
        #pragma unroll
        for (int k = 0; k < GBK; k++) {
            float4 aA = *(const float4*)&AsT[k][ty * 8];
            float4 aB = *(const float4*)&AsT[k][ty * 8 + 4];
            float4 bb = *(const float4*)&WsT[k][tx * 4];
            float av[8] = {aA.x, aA.y, aA.z, aA.w, aB.x, aB.y, aB.z, aB.w};
            float bv[4] = {bb.x, bb.y, bb.z, bb.w};
            #pragma unroll
            for (int i = 0; i < 8; i++)
                #pragma unroll
                for (int j = 0; j < 4; j++)
                    acc[i][j] += av[i] * bv[j];
        }
        __syncthreads();
    }

    float4 b4 = *(const float4*)(bias + n0 + tx * 4);
    float bv[4] = {b4.x, b4.y, b4.z, b4.w};
    #pragma unroll
    for (int i = 0; i < 8; i++) {
        int m = m0 + ty * 8 + i;
        float4 o;
        float c0 = acc[i][0] + bv[0];
        float c1 = acc[i][1] + bv[1];
        float c2 = acc[i][2] + bv[2];
        float c3 = acc[i][3] + bv[3];
        if (relu) {
            c0 = fmaxf(c0, 0.f); c1 = fmaxf(c1, 0.f);
            c2 = fmaxf(c2, 0.f); c3 = fmaxf(c3, 0.f);
        }
        o.x = c0; o.y = c1; o.z = c2; o.w = c3;
        *(float4*)(C + (size_t)m * Dc + n0 + tx * 4) = o;
    }
}

// ---------------- flash attention, fp32. 64 q-rows x 32 k-cols tiles -----------
// grid: (SQ/64, H, B), 256 threads (16x16), thread owns 4 rows x 2 s-cols / 4 v-cols.
#define ABQ 64
#define ABK 32
__global__ __launch_bounds__(256) void attn_kernel(const float* __restrict__ Q1,
                                                   const float* __restrict__ K1,
                                                   const float* __restrict__ V1,
                                                   const int* __restrict__ mask,
                                                   float* __restrict__ O1) {
    __shared__ float QsT[64][72];  // [d][r]
    __shared__ float KsT[64][40];  // [d][c]
    __shared__ float Vs[32][72];   // [c][dv]
    __shared__ float Ps[64][40];   // [r][c]
    __shared__ int   ms[32];

    int tid = threadIdx.x;
    int tx = tid & 15, ty = tid >> 4;
    int q0 = blockIdx.x * ABQ;
    int h  = blockIdx.y;
    int b  = blockIdx.z;
    const size_t qbase = (size_t)b * SQc * Dc + (size_t)h * DHc;
    const size_t kbase = (size_t)b * SKc * Dc + (size_t)h * DHc;

    // load Q tile transposed: QsT[d][r]
    {
        int r = tid >> 2, d0 = (tid & 3) * 16;
        const float* p = Q1 + qbase + (size_t)(q0 + r) * Dc + d0;
        #pragma unroll
        for (int j = 0; j < 16; j += 4) {
            float4 v = *(const float4*)(p + j);
            QsT[d0 + j + 0][r] = v.x;
            QsT[d0 + j + 1][r] = v.y;
            QsT[d0 + j + 2][r] = v.z;
            QsT[d0 + j + 3][r] = v.w;
        }
    }

    float O[4][4];
    float mrun[4], lrun[4];
    #pragma unroll
    for (int i = 0; i < 4; i++) {
        mrun[i] = -INFINITY; lrun[i] = 0.f;
        #pragma unroll
        for (int j = 0; j < 4; j++) O[i][j] = 0.f;
    }
    int r0 = ty * 4, c0 = tx * 2, dv0 = tx * 4;
    const float scale = 0.03125f;  // 1/sqrt(1024)

    int cr = tid >> 3, dl0 = (tid & 7) * 8;
    for (int k0 = 0; k0 < SKc; k0 += ABK) {
        // load K (transposed), V (natural), mask
        const float* kp = K1 + kbase + (size_t)(k0 + cr) * Dc + dl0;
        const float* vp = V1 + kbase + (size_t)(k0 + cr) * Dc + dl0;
        float4 ka = *(const float4*)kp;
        float4 kb = *(const float4*)(kp + 4);
        KsT[dl0 + 0][cr] = ka.x; KsT[dl0 + 1][cr] = ka.y;
        KsT[dl0 + 2][cr] = ka.z; KsT[dl0 + 3][cr] = ka.w;
        KsT[dl0 + 4][cr] = kb.x; KsT[dl0 + 5][cr] = kb.y;
        KsT[dl0 + 6][cr] = kb.z; KsT[dl0 + 7][cr] = kb.w;
        float4 va = *(const float4*)vp;
        float4 vb = *(const float4*)(vp + 4);
        *(float4*)&Vs[cr][dl0]     = va;
        *(float4*)&Vs[cr][dl0 + 4] = vb;
        if (tid < 32) ms[tid] = mask[b * SKc + k0 + tid];
        __syncthreads();

        // S = Q K^T
        float s[4][2];
        #pragma unroll
        for (int i = 0; i < 4; i++) { s[i][0] = 0.f; s[i][1] = 0.f; }
        #pragma unroll
        for (int d = 0; d < 64; d++) {
            float4 q4 = *(const float4*)&QsT[d][r0];
            float2 k2 = *(const float2*)&KsT[d][c0];
            s[0][0] += q4.x * k2.x; s[0][1] += q4.x * k2.y;
            s[1][0] += q4.y * k2.x; s[1][1] += q4.y * k2.y;
            s[2][0] += q4.z * k2.x; s[2][1] += q4.z * k2.y;
            s[3][0] += q4.w * k2.x; s[3][1] += q4.w * k2.y;
        }

        // mask + scale, row max
        int mk0 = ms[c0], mk1 = ms[c0 + 1];
        float f0 = mk0 ? 1.f : 0.f, f1 = mk1 ? 1.f : 0.f;
        float mloc[4];
        #pragma unroll
        for (int i = 0; i < 4; i++) {
            float s0 = mk0 ? s[i][0] * scale : -1e12f;
            float s1 = mk1 ? s[i][1] * scale : -1e12f;
            s[i][0] = s0; s[i][1] = s1;
            mloc[i] = fmaxf(s0, s1);
        }
        #pragma unroll
        for (int o = 8; o > 0; o >>= 1)
            #pragma unroll
            for (int i = 0; i < 4; i++)
                mloc[i] = fmaxf(mloc[i], __shfl_xor_sync(0xffffffffu, mloc[i], o));

        float corr[4], rs[4];
        #pragma unroll
        for (int i = 0; i < 4; i++) {
            float mnew = fmaxf(mrun[i], mloc[i]);
            corr[i] = __expf(mrun[i] - mnew);
            mrun[i] = mnew;
            float p0 = __expf(s[i][0] - mnew);
            float p1 = __expf(s[i][1] - mnew);
            rs[i] = p0 + p1;                       // denominator includes masked (==0 after underflow)
            Ps[r0 + i][c0]     = p0 * f0;          // numerator masked post-softmax
            Ps[r0 + i][c0 + 1] = p1 * f1;
        }
        #pragma unroll
        for (int o = 8; o > 0; o >>= 1)
            #pragma unroll
            for (int i = 0; i < 4; i++)
                rs[i] += __shfl_xor_sync(0xffffffffu, rs[i], o);
        #pragma unroll
        for (int i = 0; i < 4; i++) {
            lrun[i] = lrun[i] * corr[i] + rs[i];
            #pragma unroll
            for (int j = 0; j < 4; j++) O[i][j] *= corr[i];
        }
        __syncthreads();

        // O += P V
        #pragma unroll
        for (int c = 0; c < 32; c++) {
            float4 v4 = *(const float4*)&Vs[c][dv0];
            float p0 = Ps[r0 + 0][c];
            float p1 = Ps[r0 + 1][c];
            float p2 = Ps[r0 + 2][c];
            float p3 = Ps[r0 + 3][c];
            O[0][0] += p0 * v4.x; O[0][1] += p0 * v4.y; O[0][2] += p0 * v4.z; O[0][3] += p0 * v4.w;
            O[1][0] += p1 * v4.x; O[1][1] += p1 * v4.y; O[1][2] += p1 * v4.z; O[1][3] += p1 * v4.w;
            O[2][0] += p2 * v4.x; O[2][1] += p2 * v4.y; O[2][2] += p2 * v4.z; O[2][3] += p2 * v4.w;
            O[3][0] += p3 * v4.x; O[3][1] += p3 * v4.y; O[3][2] += p3 * v4.z; O[3][3] += p3 * v4.w;
        }
        __syncthreads();
    }

    #pragma unroll
    for (int i = 0; i < 4; i++) {
        float inv = 1.0f / lrun[i];
        float4 o;
        o.x = O[i][0] * inv; o.y = O[i][1] * inv;
        o.z = O[i][2] * inv; o.w = O[i][3] * inv;
        *(float4*)(O1 + qbase + (size_t)(q0 + r0 + i) * Dc + dv0) = o;
    }
}

// ---------------- launch -------------------------------------------------------
extern "C" void kernel_launch(void* const* d_in, const int* in_sizes, int n_in,
                              void* d_out, int out_size) {
    const float* Q       = (const float*)d_in[0];
    const float* K       = (const float*)d_in[1];
    const int*   padm    = (const int*)d_in[2];
    const float* Wq      = (const float*)d_in[3];
    const float* Wk      = (const float*)d_in[4];
    const float* Wv      = (const float*)d_in[5];
    const float* Wo      = (const float*)d_in[6];
    const float* bq      = (const float*)d_in[7];
    const float* bk      = (const float*)d_in[8];
    const float* bv      = (const float*)d_in[9];
    const float* bo      = (const float*)d_in[10];
    const float* ln_q_g  = (const float*)d_in[11];
    const float* ln_q_b  = (const float*)d_in[12];
    const float* ln_kv_g = (const float*)d_in[13];
    const float* ln_kv_b = (const float*)d_in[14];
    const float* ln_f_g  = (const float*)d_in[15];
    const float* ln_f_b  = (const float*)d_in[16];
    float* out = (float*)d_out;

    float *pQn, *pKn, *pQ1, *pK1, *pV1, *pO1, *pO2;
    cudaGetSymbolAddress((void**)&pQn, g_Qn);
    cudaGetSymbolAddress((void**)&pKn, g_Kn);
    cudaGetSymbolAddress((void**)&pQ1, g_Q1);
    cudaGetSymbolAddress((void**)&pK1, g_K1);
    cudaGetSymbolAddress((void**)&pV1, g_V1);
    cudaGetSymbolAddress((void**)&pO1, g_O1);
    cudaGetSymbolAddress((void**)&pO2, g_O2);

    ln_kernel<<<NTOK, 256>>>(Q, ln_q_g, ln_q_b, pQn);
    ln_kernel<<<NTOK, 256>>>(K, ln_kv_g, ln_kv_b, pKn);

    dim3 ggrid(Dc / GBN, NTOK / GBM);  // (16, 32)
    gemm_kernel<<<ggrid, 256>>>(pQn, Wq, bq, pQ1, 0);
    gemm_kernel<<<ggrid, 256>>>(pKn, Wk, bk, pK1, 0);
    gemm_kernel<<<ggrid, 256>>>(pKn, Wv, bv, pV1, 0);
    gemm_kernel<<<ggrid, 256>>>(pQn, Wo, bo, pO2, 1);

    dim3 agrid(SQc / ABQ, Hc, Bc);     // (32, 16, 2)
    attn_kernel<<<agrid, 256>>>(pQ1, pK1, pV1, padm, pO1);

    final_ln_kernel<<<NTOK, 256>>>(Q, pO1, pO2, ln_f_g, ln_f_b, out);
}

// round 3
// speedup vs baseline: 1.6248x; 1.6248x over previous
#include <cuda_runtime.h>
#include <math.h>

#define Bc  2
#define SQc 2048
#define SKc 2048
#define Dc  1024
#define Hc  16
#define DHc 64
#define NTOK (Bc*SQc)          // 4096 rows for Q-side and K-side alike (SQ==SK)
#define ELEMS (Bc*SQc*Dc)

// ---------------- scratch (static device arrays; no allocation) ----------------
__device__ float g_Qn[ELEMS];   // LN(Q)
__device__ float g_Kn[ELEMS];   // LN(K)
__device__ float g_Q1[ELEMS];   // Q projection
__device__ float g_K1[ELEMS];   // K projection
__device__ float g_V1[ELEMS];   // V projection
__device__ float g_O1[ELEMS];   // attention output
__device__ float g_O2[ELEMS];   // relu(Qn @ Wo^T + bo)

// ---------------- LayerNorm over last dim (D=1024), one block per row ----------
__global__ __launch_bounds__(256) void ln_kernel(const float* __restrict__ x,
                                                 const float* __restrict__ g,
                                                 const float* __restrict__ b,
                                                 float* __restrict__ y) {
    int row = blockIdx.x;
    int t = threadIdx.x;
    const float4* xr = (const float4*)(x + (size_t)row * Dc);
    float4 v = xr[t];
    float s  = v.x + v.y + v.z + v.w;
    float ss = v.x*v.x + v.y*v.y + v.z*v.z + v.w*v.w;
    #pragma unroll
    for (int o = 16; o > 0; o >>= 1) {
        s  += __shfl_xor_sync(0xffffffffu, s,  o);
        ss += __shfl_xor_sync(0xffffffffu, ss, o);
    }
    __shared__ float red[2][8];
    int w = t >> 5, l = t & 31;
    if (l == 0) { red[0][w] = s; red[1][w] = ss; }
    __syncthreads();
    float st = 0.f, sst = 0.f;
    #pragma unroll
    for (int i = 0; i < 8; i++) { st += red[0][i]; sst += red[1][i]; }
    float mean = st * (1.0f / Dc);
    float var  = sst * (1.0f / Dc) - mean * mean;
    float rstd = rsqrtf(var + 1e-5f);
    float4 gg = ((const float4*)g)[t];
    float4 bb = ((const float4*)b)[t];
    float4 o;
    o.x = (v.x - mean) * rstd * gg.x + bb.x;
    o.y = (v.y - mean) * rstd * gg.y + bb.y;
    o.z = (v.z - mean) * rstd * gg.z + bb.z;
    o.w = (v.w - mean) * rstd * gg.w + bb.w;
    ((float4*)(y + (size_t)row * Dc))[t] = o;
}

// ---------------- fused residual-add + LayerNorm (final) ------------------------
__global__ __launch_bounds__(256) void final_ln_kernel(const float* __restrict__ Q,
                                                       const float* __restrict__ O1,
                                                       const float* __restrict__ O2,
                                                       const float* __restrict__ g,
                                                       const float* __restrict__ b,
                                                       float* __restrict__ out) {
    int row = blockIdx.x;
    int t = threadIdx.x;
    size_t base = (size_t)row * Dc;
    float4 q  = ((const float4*)(Q  + base))[t];
    float4 o1 = ((const float4*)(O1 + base))[t];
    float4 o2 = ((const float4*)(O2 + base))[t];
    float4 v;
    v.x = q.x + o1.x + o2.x;
    v.y = q.y + o1.y + o2.y;
    v.z = q.z + o1.z + o2.z;
    v.w = q.w + o1.w + o2.w;
    float s  = v.x + v.y + v.z + v.w;
    float ss = v.x*v.x + v.y*v.y + v.z*v.z + v.w*v.w;
    #pragma unroll
    for (int o = 16; o > 0; o >>= 1) {
        s  += __shfl_xor_sync(0xffffffffu, s,  o);
        ss += __shfl_xor_sync(0xffffffffu, ss, o);
    }
    __shared__ float red[2][8];
    int w = t >> 5, l = t & 31;
    if (l == 0) { red[0][w] = s; red[1][w] = ss; }
    __syncthreads();
    float st = 0.f, sst = 0.f;
    #pragma unroll
    for (int i = 0; i < 8; i++) { st += red[0][i]; sst += red[1][i]; }
    float mean = st * (1.0f / Dc);
    float var  = sst * (1.0f / Dc) - mean * mean;
    float rstd = rsqrtf(var + 1e-5f);
    float4 gg = ((const float4*)g)[t];
    float4 bb = ((const float4*)b)[t];
    float4 o;
    o.x = (v.x - mean) * rstd * gg.x + bb.x;
    o.y = (v.y - mean) * rstd * gg.y + bb.y;
    o.z = (v.z - mean) * rstd * gg.z + bb.z;
    o.w = (v.w - mean) * rstd * gg.w + bb.w;
    ((float4*)(out + base))[t] = o;
}

// ---------------- C[M,1024] = A[M,1024] @ W[1024,1024]^T + bias (opt relu) -----
// BM=128, BN=64, BK=16, 256 threads, 8x4 per-thread microtile.
#define GBM 128
#define GBN 64
#define GBK 16
__global__ __launch_bounds__(256) void gemm_kernel(const float* __restrict__ A,
                                                   const float* __restrict__ W,
                                                   const float* __restrict__ bias,
                                                   float* __restrict__ C,
                                                   int relu) {
    __shared__ float AsT[GBK][132];  // [k][m], padded
    __shared__ float WsT[GBK][68];   // [k][n], padded
    int tid = threadIdx.x;
    int tx = tid & 15, ty = tid >> 4;
    int m0 = blockIdx.y * GBM;
    int n0 = blockIdx.x * GBN;

    int arow = tid >> 1, ak = (tid & 1) * 8;   // A tile: 128 rows x 16 k
    int wrow = tid >> 2, wk = (tid & 3) * 4;   // W tile: 64 rows x 16 k
    const float* Aptr = A + (size_t)(m0 + arow) * Dc + ak;
    const float* Wptr = W + (size_t)(n0 + wrow) * Dc + wk;

    float acc[8][4];
    #pragma unroll
    for (int i = 0; i < 8; i++)
        #pragma unroll
        for (int j = 0; j < 4; j++) acc[i][j] = 0.f;

    for (int kt = 0; kt < Dc; kt += GBK) {
        float4 a0 = *(const float4*)(Aptr + kt);
        float4 a1 = *(const float4*)(Aptr + kt + 4);
        float4 w0 = *(const float4*)(Wptr + kt);
        AsT[ak+0][arow] = a0.x; AsT[ak+1][arow] = a0.y;
        AsT[ak+2][arow] = a0.z; AsT[ak+3][arow] = a0.w;
        AsT[ak+4][arow] = a1.x; AsT[ak+5][arow] = a1.y;
        AsT[ak+6][arow] = a1.z; AsT[ak+7][arow] = a1.w;
        WsT[wk+0][wrow] = w0.x; WsT[wk+1][wrow] = w0.y;
        WsT[wk+2][wrow] = w0.z; WsT[wk+3][wrow] = w0.w;
        __syncthreads();
        #pragma unroll
        for (int k = 0; k < GBK; k++) {
            float4 aA = *(const float4*)&AsT[k][ty * 8];
            float4 aB = *(const float4*)&AsT[k][ty * 8 + 4];
            float4 bb = *(const float4*)&WsT[k][tx * 4];
            float av[8] = {aA.x, aA.y, aA.z, aA.w, aB.x, aB.y, aB.z, aB.w};
            float bv[4] = {bb.x, bb.y, bb.z, bb.w};
            #pragma unroll
            for (int i = 0; i < 8; i++)
                #pragma unroll
                for (int j = 0; j < 4; j++)
                    acc[i][j] += av[i] * bv[j];
        }
        __syncthreads();
    }

    float4 b4 = *(const float4*)(bias + n0 + tx * 4);
    float bv[4] = {b4.x, b4.y, b4.z, b4.w};
    #pragma unroll
    for (int i = 0; i < 8; i++) {
        int m = m0 + ty * 8 + i;
        float4 o;
        float c0 = acc[i][0] + bv[0];
        float c1 = acc[i][1] + bv[1];
        float c2 = acc[i][2] + bv[2];
        float c3 = acc[i][3] + bv[3];
        if (relu) {
            c0 = fmaxf(c0, 0.f); c1 = fmaxf(c1, 0.f);
            c2 = fmaxf(c2, 0.f); c3 = fmaxf(c3, 0.f);
        }
        o.x = c0; o.y = c1; o.z = c2; o.w = c3;
        *(float4*)(C + (size_t)m * Dc + n0 + tx * 4) = o;
    }
}

// ---------------- flash attention, fp32. 64 q-rows x 32 k-cols tiles -----------
// grid: (SQ/64, H, B), 256 threads (16x16), thread owns 4 rows x 2 s-cols / 4 v-cols.
#define ABQ 64
#define ABK 32
__global__ __launch_bounds__(256) void attn_kernel(const float* __restrict__ Q1,
                                                   const float* __restrict__ K1,
                                                   const float* __restrict__ V1,
                                                   const int* __restrict__ mask,
                                                   float* __restrict__ O1) {
    __shared__ float QsT[64][72];  // [d][r]
    __shared__ float KsT[64][40];  // [d][c]
    __shared__ float Vs[32][72];   // [c][dv]
    __shared__ float Ps[64][40];   // [r][c]
    __shared__ int   ms[32];

    int tid = threadIdx.x;
    int tx = tid & 15, ty = tid >> 4;
    int q0 = blockIdx.x * ABQ;
    int h  = blockIdx.y;
    int b  = blockIdx.z;
    const size_t qbase = (size_t)b * SQc * Dc + (size_t)h * DHc;
    const size_t kbase = (size_t)b * SKc * Dc + (size_t)h * DHc;

    // load Q tile transposed: QsT[d][r]
    {
        int r = tid >> 2, d0 = (tid & 3) * 16;
        const float* p = Q1 + qbase + (size_t)(q0 + r) * Dc + d0;
        #pragma unroll
        for (int j = 0; j < 16; j += 4) {
            float4 v = *(const float4*)(p + j);
            QsT[d0 + j + 0][r] = v.x;
            QsT[d0 + j + 1][r] = v.y;
            QsT[d0 + j + 2][r] = v.z;
            QsT[d0 + j + 3][r] = v.w;
        }
    }

    float O[4][4];
    float mrun[4], lrun[4];
    #pragma unroll
    for (int i = 0; i < 4; i++) {
        mrun[i] = -INFINITY; lrun[i] = 0.f;
        #pragma unroll
        for (int j = 0; j < 4; j++) O[i][j] = 0.f;
    }
    int r0 = ty * 4, c0 = tx * 2, dv0 = tx * 4;
    const float scale = 0.03125f;  // 1/sqrt(1024)

    int cr = tid >> 3, dl0 = (tid & 7) * 8;
    for (int k0 = 0; k0 < SKc; k0 += ABK) {
        // load K (transposed), V (natural), mask
        const float* kp = K1 + kbase + (size_t)(k0 + cr) * Dc + dl0;
        const float* vp = V1 + kbase + (size_t)(k0 + cr) * Dc + dl0;
        float4 ka = *(const float4*)kp;
        float4 kb = *(const float4*)(kp + 4);
        KsT[dl0 + 0][cr] = ka.x; KsT[dl0 + 1][cr] = ka.y;
        KsT[dl0 + 2][cr] = ka.z; KsT[dl0 + 3][cr] = ka.w;
        KsT[dl0 + 4][cr] = kb.x; KsT[dl0 + 5][cr] = kb.y;
        KsT[dl0 + 6][cr] = kb.z; KsT[dl0 + 7][cr] = kb.w;
        float4 va = *(const float4*)vp;
        float4 vb = *(const float4*)(vp + 4);
        *(float4*)&Vs[cr][dl0]     = va;
        *(float4*)&Vs[cr][dl0 + 4] = vb;
        if (tid < 32) ms[tid] = mask[b * SKc + k0 + tid];
        __syncthreads();

        // S = Q K^T
        float s[4][2];
        #pragma unroll
        for (int i = 0; i < 4; i++) { s[i][0] = 0.f; s[i][1] = 0.f; }
        #pragma unroll
        for (int d = 0; d < 64; d++) {
            float4 q4 = *(const float4*)&QsT[d][r0];
            float2 k2 = *(const float2*)&KsT[d][c0];
            s[0][0] += q4.x * k2.x; s[0][1] += q4.x * k2.y;
            s[1][0] += q4.y * k2.x; s[1][1] += q4.y * k2.y;
            s[2][0] += q4.z * k2.x; s[2][1] += q4.z * k2.y;
            s[3][0] += q4.w * k2.x; s[3][1] += q4.w * k2.y;
        }

        // mask + scale, row max
        int mk0 = ms[c0], mk1 = ms[c0 + 1];
        float f0 = mk0 ? 1.f : 0.f, f1 = mk1 ? 1.f : 0.f;
        float mloc[4];
        #pragma unroll
        for (int i = 0; i < 4; i++) {
            float s0 = mk0 ? s[i][0] * scale : -1e12f;
            float s1 = mk1 ? s[i][1] * scale : -1e12f;
            s[i][0] = s0; s[i][1] = s1;
            mloc[i] = fmaxf(s0, s1);
        }
        #pragma unroll
        for (int o = 8; o > 0; o >>= 1)
            #pragma unroll
            for (int i = 0; i < 4; i++)
                mloc[i] = fmaxf(mloc[i], __shfl_xor_sync(0xffffffffu, mloc[i], o));

        float corr[4], rs[4];
        #pragma unroll
        for (int i = 0; i < 4; i++) {
            float mnew = fmaxf(mrun[i], mloc[i]);
            corr[i] = __expf(mrun[i] - mnew);
            mrun[i] = mnew;
            float p0 = __expf(s[i][0] - mnew);
            float p1 = __expf(s[i][1] - mnew);
            rs[i] = p0 + p1;                       // denominator includes masked (==0 after underflow)
            Ps[r0 + i][c0]     = p0 * f0;          // numerator masked post-softmax
            Ps[r0 + i][c0 + 1] = p1 * f1;
        }
        #pragma unroll
        for (int o = 8; o > 0; o >>= 1)
            #pragma unroll
            for (int i = 0; i < 4; i++)
                rs[i] += __shfl_xor_sync(0xffffffffu, rs[i], o);
        #pragma unroll
        for (int i = 0; i < 4; i++) {
            lrun[i] = lrun[i] * corr[i] + rs[i];
            #pragma unroll
            for (int j = 0; j < 4; j++) O[i][j] *= corr[i];
        }
        __syncthreads();

        // O += P V
        #pragma unroll
        for (int c = 0; c < 32; c++) {
            float4 v4 = *(const float4*)&Vs[c][dv0];
            float p0 = Ps[r0 + 0][c];
            float p1 = Ps[r0 + 1][c];
            float p2 = Ps[r0 + 2][c];
            float p3 = Ps[r0 + 3][c];
            O[0][0] += p0 * v4.x; O[0][1] += p0 * v4.y; O[0][2] += p0 * v4.z; O[0][3] += p0 * v4.w;
            O[1][0] += p1 * v4.x; O[1][1] += p1 * v4.y; O[1][2] += p1 * v4.z; O[1][3] += p1 * v4.w;
            O[2][0] += p2 * v4.x; O[2][1] += p2 * v4.y; O[2][2] += p2 * v4.z; O[2][3] += p2 * v4.w;
            O[3][0] += p3 * v4.x; O[3][1] += p3 * v4.y; O[3][2] += p3 * v4.z; O[3][3] += p3 * v4.w;
        }
        __syncthreads();
    }

    #pragma unroll
    for (int i = 0; i < 4; i++) {
        float inv = 1.0f / lrun[i];
        float4 o;
        o.x = O[i][0] * inv; o.y = O[i][1] * inv;
        o.z = O[i][2] * inv; o.w = O[i][3] * inv;
        *(float4*)(O1 + qbase + (size_t)(q0 + r0 + i) * Dc + dv0) = o;
    }
}

// ---------------- launch -------------------------------------------------------
extern "C" void kernel_launch(void* const* d_in, const int* in_sizes, int n_in,
                              void* d_out, int out_size) {
    const float* Q       = (const float*)d_in[0];
    const float* K       = (const float*)d_in[1];
    const int*   padm    = (const int*)d_in[2];
    const float* Wq      = (const float*)d_in[3];
    const float* Wk      = (const float*)d_in[4];
    const float* Wv      = (const float*)d_in[5];
    const float* Wo      = (const float*)d_in[6];
    const float* bq      = (const float*)d_in[7];
    const float* bk      = (const float*)d_in[8];
    const float* bv      = (const float*)d_in[9];
    const float* bo      = (const float*)d_in[10];
    const float* ln_q_g  = (const float*)d_in[11];
    const float* ln_q_b  = (const float*)d_in[12];
    const float* ln_kv_g = (const float*)d_in[13];
    const float* ln_kv_b = (const float*)d_in[14];
    const float* ln_f_g  = (const float*)d_in[15];
    const float* ln_f_b  = (const float*)d_in[16];
    float* out = (float*)d_out;

    float *pQn, *pKn, *pQ1, *pK1, *pV1, *pO1, *pO2;
    cudaGetSymbolAddress((void**)&pQn, g_Qn);
    cudaGetSymbolAddress((void**)&pKn, g_Kn);
    cudaGetSymbolAddress((void**)&pQ1, g_Q1);
    cudaGetSymbolAddress((void**)&pK1, g_K1);
    cudaGetSymbolAddress((void**)&pV1, g_V1);
    cudaGetSymbolAddress((void**)&pO1, g_O1);
    cudaGetSymbolAddress((void**)&pO2, g_O2);

    ln_kernel<<<NTOK, 256>>>(Q, ln_q_g, ln_q_b, pQn);
    ln_kernel<<<NTOK, 256>>>(K, ln_kv_g, ln_kv_b, pKn);

    dim3 ggrid(Dc / GBN, NTOK / GBM);  // (16, 32)
    gemm_kernel<<<ggrid, 256>>>(pQn, Wq, bq, pQ1, 0);
    gemm_kernel<<<ggrid, 256>>>(pKn, Wk, bk, pK1, 0);
    gemm_kernel<<<ggrid, 256>>>(pKn, Wv, bv, pV1, 0);
    gemm_kernel<<<ggrid, 256>>>(pQn, Wo, bo, pO2, 1);

    dim3 agrid(SQc / ABQ, Hc, Bc);     // (32, 16, 2)
    attn_kernel<<<agrid, 256>>>(pQ1, pK1, pV1, padm, pO1);

    final_ln_kernel<<<NTOK, 256>>>(Q, pO1, pO2, ln_f_g, ln_f_b, out);
}

// round 6
// speedup vs baseline: 6.9361x; 4.2689x over previous
#include <cuda_runtime.h>
#include <cuda_bf16.h>
#include <cstdint>
#include <math.h>

#define Bc  2
#define SQc 2048
#define SKc 2048
#define Dc  1024
#define Hc  16
#define DHc 64
#define NTOK (Bc*SQc)
#define ELEMS (Bc*SQc*Dc)

typedef __nv_bfloat16 bf16;

// ---------------- scratch (static device arrays; no allocation) ----------------
__device__ bf16  g_Qh[ELEMS], g_Ql[ELEMS];     // LN(Q) split hi/lo
__device__ bf16  g_Kh[ELEMS], g_Kl[ELEMS];     // LN(K) split hi/lo
__device__ bf16  g_Wqh[Dc*Dc], g_Wql[Dc*Dc];
__device__ bf16  g_Wkh[Dc*Dc], g_Wkl[Dc*Dc];
__device__ bf16  g_Wvh[Dc*Dc], g_Wvl[Dc*Dc];
__device__ bf16  g_Woh[Dc*Dc], g_Wol[Dc*Dc];
__device__ bf16  g_Q1b[ELEMS], g_K1b[ELEMS], g_V1b[ELEMS];  // projections (bf16, attention inputs)
__device__ float g_O1[ELEMS];   // attention output
__device__ float g_O2[ELEMS];   // relu(Qn @ Wo^T + bo)

// ---------------- PTX helpers (all plain sm_80-era: no 'a' features) ------------
__device__ __forceinline__ uint32_t smem_u32(const void* p) {
    uint32_t a;
    asm("{ .reg .u64 t; cvta.to.shared.u64 t, %1; cvt.u32.u64 %0, t; }" : "=r"(a) : "l"(p));
    return a;
}
__device__ __forceinline__ void cpa16(uint32_t saddr, const void* g) {
    asm volatile("cp.async.cg.shared.global [%0], [%1], 16;" :: "r"(saddr), "l"(g) : "memory");
}
__device__ __forceinline__ void cp_commit() {
    asm volatile("cp.async.commit_group;" ::: "memory");
}
template<int N> __device__ __forceinline__ void cp_wait() {
    asm volatile("cp.async.wait_group %0;" :: "n"(N) : "memory");
}
__device__ __forceinline__ void ldm4(uint32_t* r, uint32_t a) {
    asm volatile("ldmatrix.sync.aligned.m8n8.x4.shared.b16 {%0,%1,%2,%3}, [%4];"
        : "=r"(r[0]), "=r"(r[1]), "=r"(r[2]), "=r"(r[3]) : "r"(a));
}
__device__ __forceinline__ void ldm4t(uint32_t* r, uint32_t a) {
    asm volatile("ldmatrix.sync.aligned.m8n8.x4.trans.shared.b16 {%0,%1,%2,%3}, [%4];"
        : "=r"(r[0]), "=r"(r[1]), "=r"(r[2]), "=r"(r[3]) : "r"(a));
}
__device__ __forceinline__ void mmabf(float* d, const uint32_t* a, const uint32_t* b) {
    asm volatile("mma.sync.aligned.m16n8k16.row.col.f32.bf16.bf16.f32 "
        "{%0,%1,%2,%3}, {%4,%5,%6,%7}, {%8,%9}, {%0,%1,%2,%3};"
        : "+f"(d[0]), "+f"(d[1]), "+f"(d[2]), "+f"(d[3])
        : "r"(a[0]), "r"(a[1]), "r"(a[2]), "r"(a[3]), "r"(b[0]), "r"(b[1]));
}
__device__ __forceinline__ uint32_t packbf2(float lo, float hi) {
    __nv_bfloat162 t = __floats2bfloat162_rn(lo, hi);   // lo -> .x (low half)
    return *(uint32_t*)&t;
}

// ---------------- LayerNorm + bf16 hi/lo split ---------------------------------
__global__ __launch_bounds__(256) void ln_split_kernel(const float* __restrict__ x,
                                                       const float* __restrict__ g,
                                                       const float* __restrict__ b,
                                                       bf16* __restrict__ hi,
                                                       bf16* __restrict__ lo) {
    int row = blockIdx.x;
    int t = threadIdx.x;
    const float4* xr = (const float4*)(x + (size_t)row * Dc);
    float4 v = xr[t];
    float s  = v.x + v.y + v.z + v.w;
    float ss = v.x*v.x + v.y*v.y + v.z*v.z + v.w*v.w;
    #pragma unroll
    for (int o = 16; o > 0; o >>= 1) {
        s  += __shfl_xor_sync(0xffffffffu, s,  o);
        ss += __shfl_xor_sync(0xffffffffu, ss, o);
    }
    __shared__ float red[2][8];
    int w = t >> 5, l = t & 31;
    if (l == 0) { red[0][w] = s; red[1][w] = ss; }
    __syncthreads();
    float st = 0.f, sst = 0.f;
    #pragma unroll
    for (int i = 0; i < 8; i++) { st += red[0][i]; sst += red[1][i]; }
    float mean = st * (1.0f / Dc);
    float var  = sst * (1.0f / Dc) - mean * mean;
    float rstd = rsqrtf(var + 1e-5f);
    float4 gg = ((const float4*)g)[t];
    float4 bb = ((const float4*)b)[t];
    float o0 = (v.x - mean) * rstd * gg.x + bb.x;
    float o1 = (v.y - mean) * rstd * gg.y + bb.y;
    float o2 = (v.z - mean) * rstd * gg.z + bb.z;
    float o3 = (v.w - mean) * rstd * gg.w + bb.w;
    size_t base = (size_t)row * Dc + t * 4;
    bf16 h0 = __float2bfloat16_rn(o0), h1 = __float2bfloat16_rn(o1);
    bf16 h2 = __float2bfloat16_rn(o2), h3 = __float2bfloat16_rn(o3);
    bf16 l0 = __float2bfloat16_rn(o0 - __bfloat162float(h0));
    bf16 l1 = __float2bfloat16_rn(o1 - __bfloat162float(h1));
    bf16 l2 = __float2bfloat16_rn(o2 - __bfloat162float(h2));
    bf16 l3 = __float2bfloat16_rn(o3 - __bfloat162float(h3));
    __nv_bfloat162 hA; hA.x = h0; hA.y = h1;
    __nv_bfloat162 hB; hB.x = h2; hB.y = h3;
    __nv_bfloat162 lA; lA.x = l0; lA.y = l1;
    __nv_bfloat162 lB; lB.x = l2; lB.y = l3;
    *(__nv_bfloat162*)(hi + base)     = hA;
    *(__nv_bfloat162*)(hi + base + 2) = hB;
    *(__nv_bfloat162*)(lo + base)     = lA;
    *(__nv_bfloat162*)(lo + base + 2) = lB;
}

// ---------------- weight split fp32 -> bf16 hi/lo -------------------------------
__global__ __launch_bounds__(256) void wsplit_kernel(const float* __restrict__ W,
                                                     bf16* __restrict__ hi,
                                                     bf16* __restrict__ lo) {
    int i = blockIdx.x * 256 + threadIdx.x;
    float4 v = ((const float4*)W)[i];
    bf16 h0 = __float2bfloat16_rn(v.x), h1 = __float2bfloat16_rn(v.y);
    bf16 h2 = __float2bfloat16_rn(v.z), h3 = __float2bfloat16_rn(v.w);
    bf16 l0 = __float2bfloat16_rn(v.x - __bfloat162float(h0));
    bf16 l1 = __float2bfloat16_rn(v.y - __bfloat162float(h1));
    bf16 l2 = __float2bfloat16_rn(v.z - __bfloat162float(h2));
    bf16 l3 = __float2bfloat16_rn(v.w - __bfloat162float(h3));
    __nv_bfloat162 hA; hA.x = h0; hA.y = h1;
    __nv_bfloat162 hB; hB.x = h2; hB.y = h3;
    __nv_bfloat162 lA; lA.x = l0; lA.y = l1;
    __nv_bfloat162 lB; lB.x = l2; lB.y = l3;
    size_t base = (size_t)i * 4;
    *(__nv_bfloat162*)(hi + base)     = hA;
    *(__nv_bfloat162*)(hi + base + 2) = hB;
    *(__nv_bfloat162*)(lo + base)     = lA;
    *(__nv_bfloat162*)(lo + base + 2) = lB;
}

// ---------------- HMMA bf16x3 GEMM: C[4096,1024] = A @ W^T + bias ---------------
// BM=128, BN=128, BK=32; 256 thr, warps 4(M)x2(N), warp tile 32x64.
// smem per stage: Ah,Al,Wh,Wl tiles 128x32 bf16, pitch 40 bf16 (80B). stage=40960B.
#define GSTG 40960
#define GSMEM (2*GSTG)
__global__ __launch_bounds__(256) void gemm_mma_kernel(const bf16* __restrict__ Ah,
                                                       const bf16* __restrict__ Al,
                                                       const bf16* __restrict__ Wh,
                                                       const bf16* __restrict__ Wl,
                                                       const float* __restrict__ bias,
                                                       float* __restrict__ Cf,
                                                       bf16* __restrict__ Cb,
                                                       int mode) {   // 0: bf16 out, 1: fp32+relu out
    extern __shared__ char sm[];
    uint32_t sb = smem_u32(sm);
    int tid = threadIdx.x, lane = tid & 31, warp = tid >> 5;
    int m0 = blockIdx.y * 128, n0 = blockIdx.x * 128;
    const bf16* Ahg = Ah + (size_t)m0 * Dc;
    const bf16* Alg = Al + (size_t)m0 * Dc;
    const bf16* Whg = Wh + (size_t)n0 * Dc;
    const bf16* Wlg = Wl + (size_t)n0 * Dc;

    auto ldstage = [&](int st, int k0) {
        uint32_t s0 = sb + st * GSTG;
        #pragma unroll
        for (int i = 0; i < 2; i++) {
            int idx = tid + i * 256;
            int r = idx >> 2, c = idx & 3;
            uint32_t so = r * 80 + c * 16;
            size_t   go = (size_t)r * Dc + k0 + c * 8;
            cpa16(s0 +         so, Ahg + go);
            cpa16(s0 + 10240 + so, Alg + go);
            cpa16(s0 + 20480 + so, Whg + go);
            cpa16(s0 + 30720 + so, Wlg + go);
        }
    };

    ldstage(0, 0);
    cp_commit();

    int wm = (warp >> 1) * 32, wn = (warp & 1) * 64;
    int g8 = lane >> 3, r8 = lane & 7;
    uint32_t aoffl = (lane & 15) * 80 + (lane >> 4) * 16;
    uint32_t boffl = ((g8 >> 1) * 8 + r8) * 80 + (g8 & 1) * 16;

    float acc[2][8][4];
    #pragma unroll
    for (int mt = 0; mt < 2; mt++)
        #pragma unroll
        for (int nt = 0; nt < 8; nt++)
            #pragma unroll
            for (int j = 0; j < 4; j++) acc[mt][nt][j] = 0.f;

    #pragma unroll 1
    for (int c = 0; c < 32; c++) {
        int st = c & 1;
        if (c + 1 < 32) { ldstage(st ^ 1, (c + 1) * 32); cp_commit(); cp_wait<1>(); }
        else            { cp_wait<0>(); }
        __syncthreads();

        uint32_t SA = sb + st * GSTG;
        #pragma unroll
        for (int ks = 0; ks < 2; ks++) {
            uint32_t ah[2][4], al[2][4];
            #pragma unroll
            for (int mt = 0; mt < 2; mt++) {
                uint32_t abase = SA + (wm + mt * 16) * 80 + aoffl + ks * 32;
                ldm4(ah[mt], abase);
                ldm4(al[mt], abase + 10240);
            }
            #pragma unroll
            for (int np = 0; np < 4; np++) {
                uint32_t bh[4], bl[4];
                uint32_t bbase = SA + 20480 + (wn + np * 16) * 80 + boffl + ks * 32;
                ldm4(bh, bbase);
                ldm4(bl, bbase + 10240);
                #pragma unroll
                for (int mt = 0; mt < 2; mt++) {
                    mmabf(acc[mt][2*np],   ah[mt], bh);
                    mmabf(acc[mt][2*np+1], ah[mt], bh + 2);
                    mmabf(acc[mt][2*np],   ah[mt], bl);
                    mmabf(acc[mt][2*np+1], ah[mt], bl + 2);
                    mmabf(acc[mt][2*np],   al[mt], bh);
                    mmabf(acc[mt][2*np+1], al[mt], bh + 2);
                }
            }
        }
        __syncthreads();
    }

    int cq = 2 * (lane & 3);
    #pragma unroll
    for (int mt = 0; mt < 2; mt++) {
        int row0 = m0 + wm + mt * 16 + (lane >> 2);
        #pragma unroll
        for (int nt = 0; nt < 8; nt++) {
            int col = n0 + wn + nt * 8 + cq;
            float b0 = bias[col], b1 = bias[col + 1];
            float c00 = acc[mt][nt][0] + b0, c01 = acc[mt][nt][1] + b1;
            float c10 = acc[mt][nt][2] + b0, c11 = acc[mt][nt][3] + b1;
            if (mode == 1) {
                c00 = fmaxf(c00, 0.f); c01 = fmaxf(c01, 0.f);
                c10 = fmaxf(c10, 0.f); c11 = fmaxf(c11, 0.f);
                float2 v0 = make_float2(c00, c01);
                float2 v1 = make_float2(c10, c11);
                *(float2*)(Cf + (size_t)row0 * Dc + col)       = v0;
                *(float2*)(Cf + (size_t)(row0 + 8) * Dc + col) = v1;
            } else {
                *(uint32_t*)(Cb + (size_t)row0 * Dc + col)       = packbf2(c00, c01);
                *(uint32_t*)(Cb + (size_t)(row0 + 8) * Dc + col) = packbf2(c10, c11);
            }
        }
    }
}

// ---------------- HMMA flash attention (no-max variant) -------------------------
// Block: 128 q-rows x 1 head. 8 warps x 16 rows. k-chunks of 64, double-buffered.
// smem: Q 128x64 (pitch 72 bf16 =144B) | K[2] 64x64 | V[2] 64x64 | mask[2] 64 ints
#define AQ_OFF   0
#define AK_OFF   18432
#define AV_OFF   36864
#define AM_OFF   55296
#define ASMEM    55808
__global__ __launch_bounds__(256) void attn_mma_kernel(const bf16* __restrict__ Qb,
                                                       const bf16* __restrict__ Kb,
                                                       const bf16* __restrict__ Vb,
                                                       const int* __restrict__ mask,
                                                       float* __restrict__ O1) {
    extern __shared__ char sm[];
    uint32_t sb = smem_u32(sm);
    int tid = threadIdx.x, lane = tid & 31, warp = tid >> 5;
    int q0 = blockIdx.x * 128;
    int h  = blockIdx.y;
    int b  = blockIdx.z;
    const bf16* Qg = Qb + ((size_t)(b * SQc + q0)) * Dc + h * DHc;
    const bf16* Kg = Kb + ((size_t)b * SKc) * Dc + h * DHc;
    const bf16* Vg = Vb + ((size_t)b * SKc) * Dc + h * DHc;
    const int*  mg = mask + b * SKc;

    auto ldkv = [&](int st, int k0) {
        #pragma unroll
        for (int i = 0; i < 2; i++) {
            int idx = tid + i * 256;
            int r = idx >> 3, c = idx & 7;
            uint32_t so = r * 144 + c * 16;
            size_t   go = (size_t)(k0 + r) * Dc + c * 8;
            cpa16(sb + AK_OFF + st * 9216 + so, Kg + go);
            cpa16(sb + AV_OFF + st * 9216 + so, Vg + go);
        }
        if (tid < 16) cpa16(sb + AM_OFF + st * 256 + tid * 16, mg + k0 + tid * 4);
    };

    // preload Q + chunk 0 (one commit group)
    #pragma unroll
    for (int i = 0; i < 4; i++) {
        int idx = tid + i * 256;
        int r = idx >> 3, c = idx & 7;
        cpa16(sb + AQ_OFF + r * 144 + c * 16, Qg + (size_t)r * Dc + c * 8);
    }
    ldkv(0, 0);
    cp_commit();

    int m0 = warp * 16;
    int g8 = lane >> 3, r8 = lane & 7;
    int cq = 2 * (lane & 3);
    uint32_t qaddr = sb + AQ_OFF + (m0 + (lane & 15)) * 144 + (lane >> 4) * 16;
    uint32_t klane = ((g8 >> 1) * 8 + r8) * 144 + (g8 & 1) * 16;
    uint32_t vlane = ((g8 & 1) * 8 + r8) * 144 + (g8 >> 1) * 16;
    const float SC = 0.03125f;  // 1/sqrt(1024)

    float o[8][4];
    #pragma unroll
    for (int dt = 0; dt < 8; dt++)
        #pragma unroll
        for (int j = 0; j < 4; j++) o[dt][j] = 0.f;
    float ls0 = 0.f, ls1 = 0.f;

    #pragma unroll 1
    for (int c = 0; c < 32; c++) {
        int st = c & 1;
        if (c + 1 < 32) { ldkv(st ^ 1, (c + 1) * 64); cp_commit(); cp_wait<1>(); }
        else            { cp_wait<0>(); }
        __syncthreads();

        uint32_t Kst = sb + AK_OFF + st * 9216 + klane;
        uint32_t Vst = sb + AV_OFF + st * 9216 + vlane;
        const int* mp = (const int*)(sm + AM_OFF + st * 256);

        // S = Q K^T  (warp: 16 x 64)
        float s_[8][4];
        #pragma unroll
        for (int nt = 0; nt < 8; nt++)
            #pragma unroll
            for (int j = 0; j < 4; j++) s_[nt][j] = 0.f;
        #pragma unroll
        for (int ks = 0; ks < 4; ks++) {
            uint32_t aq[4];
            ldm4(aq, qaddr + ks * 32);
            #pragma unroll
            for (int np = 0; np < 4; np++) {
                uint32_t bk[4];
                ldm4(bk, Kst + np * 2304 + ks * 32);
                mmabf(s_[2*np],   aq, bk);
                mmabf(s_[2*np+1], aq, bk + 2);
            }
        }

        // exp + mask (no max subtraction: scores bounded, exp fits fp32)
        uint32_t pr0[8], pr1[8];
        #pragma unroll
        for (int nt = 0; nt < 8; nt++) {
            float f0 = (float)mp[nt * 8 + cq];
            float f1 = (float)mp[nt * 8 + cq + 1];
            float p0 = __expf(s_[nt][0] * SC) * f0;
            float p1 = __expf(s_[nt][1] * SC) * f1;
            float p2 = __expf(s_[nt][2] * SC) * f0;
            float p3 = __expf(s_[nt][3] * SC) * f1;
            ls0 += p0 + p1;
            ls1 += p2 + p3;
            pr0[nt] = packbf2(p0, p1);
            pr1[nt] = packbf2(p2, p3);
        }

        // O += P V   (P A-fragments straight from registers; V via ldmatrix.trans)
        #pragma unroll
        for (int ks2 = 0; ks2 < 4; ks2++) {
            uint32_t pf[4] = { pr0[2*ks2], pr1[2*ks2], pr0[2*ks2+1], pr1[2*ks2+1] };
            #pragma unroll
            for (int dp = 0; dp < 4; dp++) {
                uint32_t bv[4];
                ldm4t(bv, Vst + ks2 * 2304 + dp * 32);
                mmabf(o[2*dp],   pf, bv);
                mmabf(o[2*dp+1], pf, bv + 2);
            }
        }
        __syncthreads();
    }

    // normalize + write
    ls0 += __shfl_xor_sync(0xffffffffu, ls0, 1);
    ls0 += __shfl_xor_sync(0xffffffffu, ls0, 2);
    ls1 += __shfl_xor_sync(0xffffffffu, ls1, 1);
    ls1 += __shfl_xor_sync(0xffffffffu, ls1, 2);
    float i0 = 1.f / ls0, i1 = 1.f / ls1;
    int row0 = q0 + m0 + (lane >> 2);
    float* Or0 = O1 + ((size_t)(b * SQc) + row0) * Dc + h * DHc + cq;
    float* Or1 = Or0 + (size_t)8 * Dc;
    #pragma unroll
    for (int dt = 0; dt < 8; dt++) {
        float2 v0 = make_float2(o[dt][0] * i0, o[dt][1] * i0);
        float2 v1 = make_float2(o[dt][2] * i1, o[dt][3] * i1);
        *(float2*)(Or0 + dt * 8) = v0;
        *(float2*)(Or1 + dt * 8) = v1;
    }
}

// ---------------- fused residual-add + LayerNorm (final) ------------------------
__global__ __launch_bounds__(256) void final_ln_kernel(const float* __restrict__ Q,
                                                       const float* __restrict__ O1,
                                                       const float* __restrict__ O2,
                                                       const float* __restrict__ g,
                                                       const float* __restrict__ b,
                                                       float* __restrict__ out) {
    int row = blockIdx.x;
    int t = threadIdx.x;
    size_t base = (size_t)row * Dc;
    float4 q  = ((const float4*)(Q  + base))[t];
    float4 o1 = ((const float4*)(O1 + base))[t];
    float4 o2 = ((const float4*)(O2 + base))[t];
    float4 v;
    v.x = q.x + o1.x + o2.x;
    v.y = q.y + o1.y + o2.y;
    v.z = q.z + o1.z + o2.z;
    v.w = q.w + o1.w + o2.w;
    float s  = v.x + v.y + v.z + v.w;
    float ss = v.x*v.x + v.y*v.y + v.z*v.z + v.w*v.w;
    #pragma unroll
    for (int o = 16; o > 0; o >>= 1) {
        s  += __shfl_xor_sync(0xffffffffu, s,  o);
        ss += __shfl_xor_sync(0xffffffffu, ss, o);
    }
    __shared__ float red[2][8];
    int w = t >> 5, l = t & 31;
    if (l == 0) { red[0][w] = s; red[1][w] = ss; }
    __syncthreads();
    float st = 0.f, sst = 0.f;
    #pragma unroll
    for (int i = 0; i < 8; i++) { st += red[0][i]; sst += red[1][i]; }
    float mean = st * (1.0f / Dc);
    float var  = sst * (1.0f / Dc) - mean * mean;
    float rstd = rsqrtf(var + 1e-5f);
    float4 gg = ((const float4*)g)[t];
    float4 bb = ((const float4*)b)[t];
    float4 o;
    o.x = (v.x - mean) * rstd * gg.x + bb.x;
    o.y = (v.y - mean) * rstd * gg.y + bb.y;
    o.z = (v.z - mean) * rstd * gg.z + bb.z;
    o.w = (v.w - mean) * rstd * gg.w + bb.w;
    ((float4*)(out + base))[t] = o;
}

// ---------------- launch -------------------------------------------------------
extern "C" void kernel_launch(void* const* d_in, const int* in_sizes, int n_in,
                              void* d_out, int out_size) {
    const float* Q       = (const float*)d_in[0];
    const float* K       = (const float*)d_in[1];
    const int*   padm    = (const int*)d_in[2];
    const float* Wq      = (const float*)d_in[3];
    const float* Wk      = (const float*)d_in[4];
    const float* Wv      = (const float*)d_in[5];
    const float* Wo      = (const float*)d_in[6];
    const float* bq      = (const float*)d_in[7];
    const float* bk      = (const float*)d_in[8];
    const float* bv      = (const float*)d_in[9];
    const float* bo      = (const float*)d_in[10];
    const float* ln_q_g  = (const float*)d_in[11];
    const float* ln_q_b  = (const float*)d_in[12];
    const float* ln_kv_g = (const float*)d_in[13];
    const float* ln_kv_b = (const float*)d_in[14];
    const float* ln_f_g  = (const float*)d_in[15];
    const float* ln_f_b  = (const float*)d_in[16];
    float* out = (float*)d_out;

    bf16 *pQh, *pQl, *pKh, *pKl;
    bf16 *pWqh, *pWql, *pWkh, *pWkl, *pWvh, *pWvl, *pWoh, *pWol;
    bf16 *pQ1b, *pK1b, *pV1b;
    float *pO1, *pO2;
    cudaGetSymbolAddress((void**)&pQh, g_Qh);   cudaGetSymbolAddress((void**)&pQl, g_Ql);
    cudaGetSymbolAddress((void**)&pKh, g_Kh);   cudaGetSymbolAddress((void**)&pKl, g_Kl);
    cudaGetSymbolAddress((void**)&pWqh, g_Wqh); cudaGetSymbolAddress((void**)&pWql, g_Wql);
    cudaGetSymbolAddress((void**)&pWkh, g_Wkh); cudaGetSymbolAddress((void**)&pWkl, g_Wkl);
    cudaGetSymbolAddress((void**)&pWvh, g_Wvh); cudaGetSymbolAddress((void**)&pWvl, g_Wvl);
    cudaGetSymbolAddress((void**)&pWoh, g_Woh); cudaGetSymbolAddress((void**)&pWol, g_Wol);
    cudaGetSymbolAddress((void**)&pQ1b, g_Q1b);
    cudaGetSymbolAddress((void**)&pK1b, g_K1b);
    cudaGetSymbolAddress((void**)&pV1b, g_V1b);
    cudaGetSymbolAddress((void**)&pO1, g_O1);
    cudaGetSymbolAddress((void**)&pO2, g_O2);

    cudaFuncSetAttribute(gemm_mma_kernel, cudaFuncAttributeMaxDynamicSharedMemorySize, GSMEM);
    cudaFuncSetAttribute(attn_mma_kernel, cudaFuncAttributeMaxDynamicSharedMemorySize, ASMEM);

    ln_split_kernel<<<NTOK, 256>>>(Q, ln_q_g, ln_q_b, pQh, pQl);
    ln_split_kernel<<<NTOK, 256>>>(K, ln_kv_g, ln_kv_b, pKh, pKl);

    int wsgrid = (Dc * Dc / 4) / 256;  // 1024
    wsplit_kernel<<<wsgrid, 256>>>(Wq, pWqh, pWql);
    wsplit_kernel<<<wsgrid, 256>>>(Wk, pWkh, pWkl);
    wsplit_kernel<<<wsgrid, 256>>>(Wv, pWvh, pWvl);
    wsplit_kernel<<<wsgrid, 256>>>(Wo, pWoh, pWol);

    dim3 ggrid(Dc / 128, NTOK / 128);  // (8, 32)
    gemm_mma_kernel<<<ggrid, 256, GSMEM>>>(pQh, pQl, pWqh, pWql, bq, nullptr, pQ1b, 0);
    gemm_mma_kernel<<<ggrid, 256, GSMEM>>>(pKh, pKl, pWkh, pWkl, bk, nullptr, pK1b, 0);
    gemm_mma_kernel<<<ggrid, 256, GSMEM>>>(pKh, pKl, pWvh, pWvl, bv, nullptr, pV1b, 0);
    gemm_mma_kernel<<<ggrid, 256, GSMEM>>>(pQh, pQl, pWoh, pWol, bo, pO2, nullptr, 1);

    dim3 agrid(SQc / 128, Hc, Bc);     // (16, 16, 2)
    attn_mma_kernel<<<agrid, 256, ASMEM>>>(pQ1b, pK1b, pV1b, padm, pO1);

    final_ln_kernel<<<NTOK, 256>>>(Q, pO1, pO2, ln_f_g, ln_f_b, out);
}

// round 7
// speedup vs baseline: 8.5094x; 1.2268x over previous
#include <cuda_runtime.h>
#include <cuda_bf16.h>
#include <cstdint>
#include <math.h>

#define Bc  2
#define SQc 2048
#define SKc 2048
#define Dc  1024
#define Hc  16
#define DHc 64
#define NTOK (Bc*SQc)
#define ELEMS (Bc*SQc*Dc)

typedef __nv_bfloat16 bf16;

// ---------------- scratch (static device arrays; no allocation) ----------------
__device__ bf16  g_Qh[ELEMS], g_Ql[ELEMS];     // LN(Q) split hi/lo (lo for Wo path)
__device__ bf16  g_Kh[ELEMS];                  // LN(K) bf16
__device__ bf16  g_Wqh[Dc*Dc], g_Wkh[Dc*Dc], g_Wvh[Dc*Dc];
__device__ bf16  g_Woh[Dc*Dc], g_Wol[Dc*Dc];
__device__ bf16  g_Q1b[ELEMS], g_K1b[ELEMS], g_V1b[ELEMS];  // projections (bf16)
__device__ float g_O1[ELEMS];   // attention output
__device__ float g_O2[ELEMS];   // relu(Qn @ Wo^T + bo)

// ---------------- PTX helpers (plain sm_80-era; compute_103 virtual arch) -------
__device__ __forceinline__ uint32_t smem_u32(const void* p) {
    uint32_t a;
    asm("{ .reg .u64 t; cvta.to.shared.u64 t, %1; cvt.u32.u64 %0, t; }" : "=r"(a) : "l"(p));
    return a;
}
__device__ __forceinline__ void cpa16(uint32_t saddr, const void* g) {
    asm volatile("cp.async.cg.shared.global [%0], [%1], 16;" :: "r"(saddr), "l"(g) : "memory");
}
__device__ __forceinline__ void cp_commit() {
    asm volatile("cp.async.commit_group;" ::: "memory");
}
template<int N> __device__ __forceinline__ void cp_wait() {
    asm volatile("cp.async.wait_group %0;" :: "n"(N) : "memory");
}
__device__ __forceinline__ void ldm4(uint32_t* r, uint32_t a) {
    asm volatile("ldmatrix.sync.aligned.m8n8.x4.shared.b16 {%0,%1,%2,%3}, [%4];"
        : "=r"(r[0]), "=r"(r[1]), "=r"(r[2]), "=r"(r[3]) : "r"(a));
}
__device__ __forceinline__ void ldm4t(uint32_t* r, uint32_t a) {
    asm volatile("ldmatrix.sync.aligned.m8n8.x4.trans.shared.b16 {%0,%1,%2,%3}, [%4];"
        : "=r"(r[0]), "=r"(r[1]), "=r"(r[2]), "=r"(r[3]) : "r"(a));
}
__device__ __forceinline__ void mmabf(float* d, const uint32_t* a, const uint32_t* b) {
    asm volatile("mma.sync.aligned.m16n8k16.row.col.f32.bf16.bf16.f32 "
        "{%0,%1,%2,%3}, {%4,%5,%6,%7}, {%8,%9}, {%0,%1,%2,%3};"
        : "+f"(d[0]), "+f"(d[1]), "+f"(d[2]), "+f"(d[3])
        : "r"(a[0]), "r"(a[1]), "r"(a[2]), "r"(a[3]), "r"(b[0]), "r"(b[1]));
}
__device__ __forceinline__ uint32_t packbf2(float lo, float hi) {
    __nv_bfloat162 t = __floats2bfloat162_rn(lo, hi);
    return *(uint32_t*)&t;
}

// ---------------- LayerNorm + bf16 (optionally hi/lo split) ---------------------
__global__ __launch_bounds__(256) void ln_split_kernel(const float* __restrict__ x,
                                                       const float* __restrict__ g,
                                                       const float* __restrict__ b,
                                                       bf16* __restrict__ hi,
                                                       bf16* __restrict__ lo) {
    int row = blockIdx.x;
    int t = threadIdx.x;
    const float4* xr = (const float4*)(x + (size_t)row * Dc);
    float4 v = xr[t];
    float s  = v.x + v.y + v.z + v.w;
    float ss = v.x*v.x + v.y*v.y + v.z*v.z + v.w*v.w;
    #pragma unroll
    for (int o = 16; o > 0; o >>= 1) {
        s  += __shfl_xor_sync(0xffffffffu, s,  o);
        ss += __shfl_xor_sync(0xffffffffu, ss, o);
    }
    __shared__ float red[2][8];
    int w = t >> 5, l = t & 31;
    if (l == 0) { red[0][w] = s; red[1][w] = ss; }
    __syncthreads();
    float st = 0.f, sst = 0.f;
    #pragma unroll
    for (int i = 0; i < 8; i++) { st += red[0][i]; sst += red[1][i]; }
    float mean = st * (1.0f / Dc);
    float var  = sst * (1.0f / Dc) - mean * mean;
    float rstd = rsqrtf(var + 1e-5f);
    float4 gg = ((const float4*)g)[t];
    float4 bb = ((const float4*)b)[t];
    float o0 = (v.x - mean) * rstd * gg.x + bb.x;
    float o1 = (v.y - mean) * rstd * gg.y + bb.y;
    float o2 = (v.z - mean) * rstd * gg.z + bb.z;
    float o3 = (v.w - mean) * rstd * gg.w + bb.w;
    size_t base = (size_t)row * Dc + t * 4;
    bf16 h0 = __float2bfloat16_rn(o0), h1 = __float2bfloat16_rn(o1);
    bf16 h2 = __float2bfloat16_rn(o2), h3 = __float2bfloat16_rn(o3);
    __nv_bfloat162 hA; hA.x = h0; hA.y = h1;
    __nv_bfloat162 hB; hB.x = h2; hB.y = h3;
    *(__nv_bfloat162*)(hi + base)     = hA;
    *(__nv_bfloat162*)(hi + base + 2) = hB;
    if (lo) {
        bf16 l0 = __float2bfloat16_rn(o0 - __bfloat162float(h0));
        bf16 l1 = __float2bfloat16_rn(o1 - __bfloat162float(h1));
        bf16 l2 = __float2bfloat16_rn(o2 - __bfloat162float(h2));
        bf16 l3 = __float2bfloat16_rn(o3 - __bfloat162float(h3));
        __nv_bfloat162 lA; lA.x = l0; lA.y = l1;
        __nv_bfloat162 lB; lB.x = l2; lB.y = l3;
        *(__nv_bfloat162*)(lo + base)     = lA;
        *(__nv_bfloat162*)(lo + base + 2) = lB;
    }
}

// ---------------- merged weight conversion --------------------------------------
// blocks [0,1024): Wq->hi; [1024,2048): Wk; [2048,3072): Wv; [3072,4096): Wo hi+lo
__global__ __launch_bounds__(256) void wconv_kernel(const float* __restrict__ Wq,
                                                    const float* __restrict__ Wk,
                                                    const float* __restrict__ Wv,
                                                    const float* __restrict__ Wo,
                                                    bf16* __restrict__ qh,
                                                    bf16* __restrict__ kh,
                                                    bf16* __restrict__ vh,
                                                    bf16* __restrict__ oh,
                                                    bf16* __restrict__ ol) {
    int m = blockIdx.x >> 10;
    int i = (blockIdx.x & 1023) * 256 + threadIdx.x;   // over Dc*Dc/4
    const float* W = (m == 0) ? Wq : (m == 1) ? Wk : (m == 2) ? Wv : Wo;
    bf16* hi = (m == 0) ? qh : (m == 1) ? kh : (m == 2) ? vh : oh;
    float4 v = ((const float4*)W)[i];
    bf16 h0 = __float2bfloat16_rn(v.x), h1 = __float2bfloat16_rn(v.y);
    bf16 h2 = __float2bfloat16_rn(v.z), h3 = __float2bfloat16_rn(v.w);
    __nv_bfloat162 hA; hA.x = h0; hA.y = h1;
    __nv_bfloat162 hB; hB.x = h2; hB.y = h3;
    size_t base = (size_t)i * 4;
    *(__nv_bfloat162*)(hi + base)     = hA;
    *(__nv_bfloat162*)(hi + base + 2) = hB;
    if (m == 3) {
        bf16 l0 = __float2bfloat16_rn(v.x - __bfloat162float(h0));
        bf16 l1 = __float2bfloat16_rn(v.y - __bfloat162float(h1));
        bf16 l2 = __float2bfloat16_rn(v.z - __bfloat162float(h2));
        bf16 l3 = __float2bfloat16_rn(v.w - __bfloat162float(h3));
        __nv_bfloat162 lA; lA.x = l0; lA.y = l1;
        __nv_bfloat162 lB; lB.x = l2; lB.y = l3;
        *(__nv_bfloat162*)(ol + base)     = lA;
        *(__nv_bfloat162*)(ol + base + 2) = lB;
    }
}

// ---------------- HMMA GEMM, all 4 projections in one launch --------------------
// grid (8, 32, 4); z: 0=Q1(Qh*Wq), 1=K1(Kh*Wk), 2=V1(Kh*Wv), 3=O2(Qh/Ql*Wo x3,relu)
// BM=128, BN=128, BK=32; 256 thr, warps 4(M)x2(N), warp tile 32x64.
#define GSTG 40960
#define GSMEM (2*GSTG)
__global__ __launch_bounds__(256) void gemm_all_kernel(const bf16* __restrict__ Qh,
                                                       const bf16* __restrict__ Ql,
                                                       const bf16* __restrict__ Kh,
                                                       const bf16* __restrict__ Wqh,
                                                       const bf16* __restrict__ Wkh,
                                                       const bf16* __restrict__ Wvh,
                                                       const bf16* __restrict__ Woh,
                                                       const bf16* __restrict__ Wol,
                                                       const float* __restrict__ bq,
                                                       const float* __restrict__ bk,
                                                       const float* __restrict__ bv,
                                                       const float* __restrict__ bo,
                                                       bf16* __restrict__ Q1b,
                                                       bf16* __restrict__ K1b,
                                                       bf16* __restrict__ V1b,
                                                       float* __restrict__ O2) {
    extern __shared__ char sm[];
    uint32_t sb = smem_u32(sm);
    int tid = threadIdx.x, lane = tid & 31, warp = tid >> 5;
    int z = blockIdx.z;
    int m0 = blockIdx.y * 128, n0 = blockIdx.x * 128;

    const bf16* A  = (z == 0 || z == 3) ? Qh : Kh;
    const bf16* Al = Ql;                               // used only when z==3
    const bf16* Wh = (z == 0) ? Wqh : (z == 1) ? Wkh : (z == 2) ? Wvh : Woh;
    const bf16* Wl = Wol;
    const float* bias = (z == 0) ? bq : (z == 1) ? bk : (z == 2) ? bv : bo;
    bf16* Cb = (z == 0) ? Q1b : (z == 1) ? K1b : V1b;
    int triple = (z == 3);

    const bf16* Ahg = A  + (size_t)m0 * Dc;
    const bf16* Alg = Al + (size_t)m0 * Dc;
    const bf16* Whg = Wh + (size_t)n0 * Dc;
    const bf16* Wlg = Wl + (size_t)n0 * Dc;

    auto ldstage = [&](int st, int k0) {
        uint32_t s0 = sb + st * GSTG;
        #pragma unroll
        for (int i = 0; i < 2; i++) {
            int idx = tid + i * 256;
            int r = idx >> 2, c = idx & 3;
            uint32_t so = r * 80 + c * 16;
            size_t   go = (size_t)r * Dc + k0 + c * 8;
            cpa16(s0 +         so, Ahg + go);
            cpa16(s0 + 20480 + so, Whg + go);
            if (triple) {
                cpa16(s0 + 10240 + so, Alg + go);
                cpa16(s0 + 30720 + so, Wlg + go);
            }
        }
    };

    ldstage(0, 0);
    cp_commit();

    int wm = (warp >> 1) * 32, wn = (warp & 1) * 64;
    int g8 = lane >> 3, r8 = lane & 7;
    uint32_t aoffl = (lane & 15) * 80 + (lane >> 4) * 16;
    uint32_t boffl = ((g8 >> 1) * 8 + r8) * 80 + (g8 & 1) * 16;

    float acc[2][8][4];
    #pragma unroll
    for (int mt = 0; mt < 2; mt++)
        #pragma unroll
        for (int nt = 0; nt < 8; nt++)
            #pragma unroll
            for (int j = 0; j < 4; j++) acc[mt][nt][j] = 0.f;

    #pragma unroll 1
    for (int c = 0; c < 32; c++) {
        int st = c & 1;
        if (c + 1 < 32) { ldstage(st ^ 1, (c + 1) * 32); cp_commit(); cp_wait<1>(); }
        else            { cp_wait<0>(); }
        __syncthreads();

        uint32_t SA = sb + st * GSTG;
        #pragma unroll
        for (int ks = 0; ks < 2; ks++) {
            uint32_t ah[2][4], al[2][4];
            #pragma unroll
            for (int mt = 0; mt < 2; mt++) {
                uint32_t abase = SA + (wm + mt * 16) * 80 + aoffl + ks * 32;
                ldm4(ah[mt], abase);
                if (triple) ldm4(al[mt], abase + 10240);
            }
            #pragma unroll
            for (int np = 0; np < 4; np++) {
                uint32_t bh[4], bl[4];
                uint32_t bbase = SA + 20480 + (wn + np * 16) * 80 + boffl + ks * 32;
                ldm4(bh, bbase);
                if (triple) ldm4(bl, bbase + 10240);
                #pragma unroll
                for (int mt = 0; mt < 2; mt++) {
                    mmabf(acc[mt][2*np],   ah[mt], bh);
                    mmabf(acc[mt][2*np+1], ah[mt], bh + 2);
                    if (triple) {
                        mmabf(acc[mt][2*np],   ah[mt], bl);
                        mmabf(acc[mt][2*np+1], ah[mt], bl + 2);
                        mmabf(acc[mt][2*np],   al[mt], bh);
                        mmabf(acc[mt][2*np+1], al[mt], bh + 2);
                    }
                }
            }
        }
        __syncthreads();
    }

    int cq = 2 * (lane & 3);
    #pragma unroll
    for (int mt = 0; mt < 2; mt++) {
        int row0 = m0 + wm + mt * 16 + (lane >> 2);
        #pragma unroll
        for (int nt = 0; nt < 8; nt++) {
            int col = n0 + wn + nt * 8 + cq;
            float b0 = bias[col], b1 = bias[col + 1];
            float c00 = acc[mt][nt][0] + b0, c01 = acc[mt][nt][1] + b1;
            float c10 = acc[mt][nt][2] + b0, c11 = acc[mt][nt][3] + b1;
            if (triple) {
                c00 = fmaxf(c00, 0.f); c01 = fmaxf(c01, 0.f);
                c10 = fmaxf(c10, 0.f); c11 = fmaxf(c11, 0.f);
                float2 v0 = make_float2(c00, c01);
                float2 v1 = make_float2(c10, c11);
                *(float2*)(O2 + (size_t)row0 * Dc + col)       = v0;
                *(float2*)(O2 + (size_t)(row0 + 8) * Dc + col) = v1;
            } else {
                *(uint32_t*)(Cb + (size_t)row0 * Dc + col)       = packbf2(c00, c01);
                *(uint32_t*)(Cb + (size_t)(row0 + 8) * Dc + col) = packbf2(c10, c11);
            }
        }
    }
}

// ---------------- HMMA flash attention (no-max variant) -------------------------
#define AQ_OFF   0
#define AK_OFF   18432
#define AV_OFF   36864
#define AM_OFF   55296
#define ASMEM    55808
__global__ __launch_bounds__(256) void attn_mma_kernel(const bf16* __restrict__ Qb,
                                                       const bf16* __restrict__ Kb,
                                                       const bf16* __restrict__ Vb,
                                                       const int* __restrict__ mask,
                                                       float* __restrict__ O1) {
    extern __shared__ char sm[];
    uint32_t sb = smem_u32(sm);
    int tid = threadIdx.x, lane = tid & 31, warp = tid >> 5;
    int q0 = blockIdx.x * 128;
    int h  = blockIdx.y;
    int b  = blockIdx.z;
    const bf16* Qg = Qb + ((size_t)(b * SQc + q0)) * Dc + h * DHc;
    const bf16* Kg = Kb + ((size_t)b * SKc) * Dc + h * DHc;
    const bf16* Vg = Vb + ((size_t)b * SKc) * Dc + h * DHc;
    const int*  mg = mask + b * SKc;

    auto ldkv = [&](int st, int k0) {
        #pragma unroll
        for (int i = 0; i < 2; i++) {
            int idx = tid + i * 256;
            int r = idx >> 3, c = idx & 7;
            uint32_t so = r * 144 + c * 16;
            size_t   go = (size_t)(k0 + r) * Dc + c * 8;
            cpa16(sb + AK_OFF + st * 9216 + so, Kg + go);
            cpa16(sb + AV_OFF + st * 9216 + so, Vg + go);
        }
        if (tid < 16) cpa16(sb + AM_OFF + st * 256 + tid * 16, mg + k0 + tid * 4);
    };

    #pragma unroll
    for (int i = 0; i < 4; i++) {
        int idx = tid + i * 256;
        int r = idx >> 3, c = idx & 7;
        cpa16(sb + AQ_OFF + r * 144 + c * 16, Qg + (size_t)r * Dc + c * 8);
    }
    ldkv(0, 0);
    cp_commit();

    int m0 = warp * 16;
    int g8 = lane >> 3, r8 = lane & 7;
    int cq = 2 * (lane & 3);
    uint32_t qaddr = sb + AQ_OFF + (m0 + (lane & 15)) * 144 + (lane >> 4) * 16;
    uint32_t klane = ((g8 >> 1) * 8 + r8) * 144 + (g8 & 1) * 16;
    uint32_t vlane = ((g8 & 1) * 8 + r8) * 144 + (g8 >> 1) * 16;
    const float SC = 0.03125f;

    float o[8][4];
    #pragma unroll
    for (int dt = 0; dt < 8; dt++)
        #pragma unroll
        for (int j = 0; j < 4; j++) o[dt][j] = 0.f;
    float ls0 = 0.f, ls1 = 0.f;

    #pragma unroll 1
    for (int c = 0; c < 32; c++) {
        int st = c & 1;
        if (c + 1 < 32) { ldkv(st ^ 1, (c + 1) * 64); cp_commit(); cp_wait<1>(); }
        else            { cp_wait<0>(); }
        __syncthreads();

        uint32_t Kst = sb + AK_OFF + st * 9216 + klane;
        uint32_t Vst = sb + AV_OFF + st * 9216 + vlane;
        const int* mp = (const int*)(sm + AM_OFF + st * 256);

        float s_[8][4];
        #pragma unroll
        for (int nt = 0; nt < 8; nt++)
            #pragma unroll
            for (int j = 0; j < 4; j++) s_[nt][j] = 0.f;
        #pragma unroll
        for (int ks = 0; ks < 4; ks++) {
            uint32_t aq[4];
            ldm4(aq, qaddr + ks * 32);
            #pragma unroll
            for (int np = 0; np < 4; np++) {
                uint32_t bk[4];
                ldm4(bk, Kst + np * 2304 + ks * 32);
                mmabf(s_[2*np],   aq, bk);
                mmabf(s_[2*np+1], aq, bk + 2);
            }
        }

        uint32_t pr0[8], pr1[8];
        #pragma unroll
        for (int nt = 0; nt < 8; nt++) {
            float f0 = (float)mp[nt * 8 + cq];
            float f1 = (float)mp[nt * 8 + cq + 1];
            float p0 = __expf(s_[nt][0] * SC) * f0;
            float p1 = __expf(s_[nt][1] * SC) * f1;
            float p2 = __expf(s_[nt][2] * SC) * f0;
            float p3 = __expf(s_[nt][3] * SC) * f1;
            ls0 += p0 + p1;
            ls1 += p2 + p3;
            pr0[nt] = packbf2(p0, p1);
            pr1[nt] = packbf2(p2, p3);
        }

        #pragma unroll
        for (int ks2 = 0; ks2 < 4; ks2++) {
            uint32_t pf[4] = { pr0[2*ks2], pr1[2*ks2], pr0[2*ks2+1], pr1[2*ks2+1] };
            #pragma unroll
            for (int dp = 0; dp < 4; dp++) {
                uint32_t bv[4];
                ldm4t(bv, Vst + ks2 * 2304 + dp * 32);
                mmabf(o[2*dp],   pf, bv);
                mmabf(o[2*dp+1], pf, bv + 2);
            }
        }
        __syncthreads();
    }

    ls0 += __shfl_xor_sync(0xffffffffu, ls0, 1);
    ls0 += __shfl_xor_sync(0xffffffffu, ls0, 2);
    ls1 += __shfl_xor_sync(0xffffffffu, ls1, 1);
    ls1 += __shfl_xor_sync(0xffffffffu, ls1, 2);
    float i0 = 1.f / ls0, i1 = 1.f / ls1;
    int row0 = q0 + m0 + (lane >> 2);
    float* Or0 = O1 + ((size_t)(b * SQc) + row0) * Dc + h * DHc + cq;
    float* Or1 = Or0 + (size_t)8 * Dc;
    #pragma unroll
    for (int dt = 0; dt < 8; dt++) {
        float2 v0 = make_float2(o[dt][0] * i0, o[dt][1] * i0);
        float2 v1 = make_float2(o[dt][2] * i1, o[dt][3] * i1);
        *(float2*)(Or0 + dt * 8) = v0;
        *(float2*)(Or1 + dt * 8) = v1;
    }
}

// ---------------- fused residual-add + LayerNorm (final) ------------------------
__global__ __launch_bounds__(256) void final_ln_kernel(const float* __restrict__ Q,
                                                       const float* __restrict__ O1,
                                                       const float* __restrict__ O2,
                                                       const float* __restrict__ g,
                                                       const float* __restrict__ b,
                                                       float* __restrict__ out) {
    int row = blockIdx.x;
    int t = threadIdx.x;
    size_t base = (size_t)row * Dc;
    float4 q  = ((const float4*)(Q  + base))[t];
    float4 o1 = ((const float4*)(O1 + base))[t];
    float4 o2 = ((const float4*)(O2 + base))[t];
    float4 v;
    v.x = q.x + o1.x + o2.x;
    v.y = q.y + o1.y + o2.y;
    v.z = q.z + o1.z + o2.z;
    v.w = q.w + o1.w + o2.w;
    float s  = v.x + v.y + v.z + v.w;
    float ss = v.x*v.x + v.y*v.y + v.z*v.z + v.w*v.w;
    #pragma unroll
    for (int o = 16; o > 0; o >>= 1) {
        s  += __shfl_xor_sync(0xffffffffu, s,  o);
        ss += __shfl_xor_sync(0xffffffffu, ss, o);
    }
    __shared__ float red[2][8];
    int w = t >> 5, l = t & 31;
    if (l == 0) { red[0][w] = s; red[1][w] = ss; }
    __syncthreads();
    float st = 0.f, sst = 0.f;
    #pragma unroll
    for (int i = 0; i < 8; i++) { st += red[0][i]; sst += red[1][i]; }
    float mean = st * (1.0f / Dc);
    float var  = sst * (1.0f / Dc) - mean * mean;
    float rstd = rsqrtf(var + 1e-5f);
    float4 gg = ((const float4*)g)[t];
    float4 bb = ((const float4*)b)[t];
    float4 o;
    o.x = (v.x - mean) * rstd * gg.x + bb.x;
    o.y = (v.y - mean) * rstd * gg.y + bb.y;
    o.z = (v.z - mean) * rstd * gg.z + bb.z;
    o.w = (v.w - mean) * rstd * gg.w + bb.w;
    ((float4*)(out + base))[t] = o;
}

// ---------------- launch -------------------------------------------------------
extern "C" void kernel_launch(void* const* d_in, const int* in_sizes, int n_in,
                              void* d_out, int out_size) {
    const float* Q       = (const float*)d_in[0];
    const float* K       = (const float*)d_in[1];
    const int*   padm    = (const int*)d_in[2];
    const float* Wq      = (const float*)d_in[3];
    const float* Wk      = (const float*)d_in[4];
    const float* Wv      = (const float*)d_in[5];
    const float* Wo      = (const float*)d_in[6];
    const float* bq      = (const float*)d_in[7];
    const float* bk      = (const float*)d_in[8];
    const float* bv      = (const float*)d_in[9];
    const float* bo      = (const float*)d_in[10];
    const float* ln_q_g  = (const float*)d_in[11];
    const float* ln_q_b  = (const float*)d_in[12];
    const float* ln_kv_g = (const float*)d_in[13];
    const float* ln_kv_b = (const float*)d_in[14];
    const float* ln_f_g  = (const float*)d_in[15];
    const float* ln_f_b  = (const float*)d_in[16];
    float* out = (float*)d_out;

    bf16 *pQh, *pQl, *pKh;
    bf16 *pWqh, *pWkh, *pWvh, *pWoh, *pWol;
    bf16 *pQ1b, *pK1b, *pV1b;
    float *pO1, *pO2;
    cudaGetSymbolAddress((void**)&pQh, g_Qh);   cudaGetSymbolAddress((void**)&pQl, g_Ql);
    cudaGetSymbolAddress((void**)&pKh, g_Kh);
    cudaGetSymbolAddress((void**)&pWqh, g_Wqh);
    cudaGetSymbolAddress((void**)&pWkh, g_Wkh);
    cudaGetSymbolAddress((void**)&pWvh, g_Wvh);
    cudaGetSymbolAddress((void**)&pWoh, g_Woh); cudaGetSymbolAddress((void**)&pWol, g_Wol);
    cudaGetSymbolAddress((void**)&pQ1b, g_Q1b);
    cudaGetSymbolAddress((void**)&pK1b, g_K1b);
    cudaGetSymbolAddress((void**)&pV1b, g_V1b);
    cudaGetSymbolAddress((void**)&pO1, g_O1);
    cudaGetSymbolAddress((void**)&pO2, g_O2);

    cudaFuncSetAttribute(gemm_all_kernel, cudaFuncAttributeMaxDynamicSharedMemorySize, GSMEM);
    cudaFuncSetAttribute(attn_mma_kernel, cudaFuncAttributeMaxDynamicSharedMemorySize, ASMEM);

    ln_split_kernel<<<NTOK, 256>>>(Q, ln_q_g, ln_q_b, pQh, pQl);
    ln_split_kernel<<<NTOK, 256>>>(K, ln_kv_g, ln_kv_b, pKh, nullptr);
    wconv_kernel<<<4096, 256>>>(Wq, Wk, Wv, Wo, pWqh, pWkh, pWvh, pWoh, pWol);

    dim3 ggrid(Dc / 128, NTOK / 128, 4);  // (8, 32, 4) = 1024 CTAs
    gemm_all_kernel<<<ggrid, 256, GSMEM>>>(pQh, pQl, pKh,
                                           pWqh, pWkh, pWvh, pWoh, pWol,
                                           bq, bk, bv, bo,
                                           pQ1b, pK1b, pV1b, pO2);

    dim3 agrid(SQc / 128, Hc, Bc);        // (16, 16, 2)
    attn_mma_kernel<<<agrid, 256, ASMEM>>>(pQ1b, pK1b, pV1b, padm, pO1);

    final_ln_kernel<<<NTOK, 256>>>(Q, pO1, pO2, ln_f_g, ln_f_b, out);
}

// round 10
// speedup vs baseline: 10.9456x; 1.2863x over previous
#include <cuda_runtime.h>
#include <cuda_bf16.h>
#include <cstdint>
#include <math.h>

#define Bc  2
#define SQc 2048
#define SKc 2048
#define Dc  1024
#define Hc  16
#define DHc 64
#define NTOK (Bc*SQc)
#define ELEMS (Bc*SQc*Dc)

typedef __nv_bfloat16 bf16;

// ---------------- scratch (static device arrays; no allocation) ----------------
__device__ bf16  g_Qh[ELEMS], g_Ql[ELEMS];     // LN(Q) split hi/lo (lo for Wo path)
__device__ bf16  g_Kh[ELEMS];                  // LN(K), compacted per batch
__device__ bf16  g_Wqh[Dc*Dc], g_Wkh[Dc*Dc], g_Wvh[Dc*Dc];
__device__ bf16  g_Woh[Dc*Dc], g_Wol[Dc*Dc];
__device__ bf16  g_Q1b[ELEMS], g_K1b[ELEMS], g_V1b[ELEMS];  // projections (bf16)
__device__ float g_O1[ELEMS];   // attention output
__device__ float g_O2[ELEMS];   // relu(Qn @ Wo^T + bo)
__device__ int   g_pos[NTOK];   // within-batch exclusive prefix of mask
__device__ int   g_cmask[NTOK]; // compact-domain validity mask (j < cnt[b])
__device__ int   g_cnt[Bc];     // unmasked count per batch

// ---------------- PTX helpers (plain sm_80-era; compute_103 virtual arch) -------
__device__ __forceinline__ uint32_t smem_u32(const void* p) {
    uint32_t a;
    asm("{ .reg .u64 t; cvta.to.shared.u64 t, %1; cvt.u32.u64 %0, t; }" : "=r"(a) : "l"(p));
    return a;
}
__device__ __forceinline__ void cpa16(uint32_t saddr, const void* g) {
    asm volatile("cp.async.cg.shared.global [%0], [%1], 16;" :: "r"(saddr), "l"(g) : "memory");
}
__device__ __forceinline__ void cp_commit() {
    asm volatile("cp.async.commit_group;" ::: "memory");
}
template<int N> __device__ __forceinline__ void cp_wait() {
    asm volatile("cp.async.wait_group %0;" :: "n"(N) : "memory");
}
__device__ __forceinline__ void ldm4(uint32_t* r, uint32_t a) {
    asm volatile("ldmatrix.sync.aligned.m8n8.x4.shared.b16 {%0,%1,%2,%3}, [%4];"
        : "=r"(r[0]), "=r"(r[1]), "=r"(r[2]), "=r"(r[3]) : "r"(a));
}
__device__ __forceinline__ void ldm4t(uint32_t* r, uint32_t a) {
    asm volatile("ldmatrix.sync.aligned.m8n8.x4.trans.shared.b16 {%0,%1,%2,%3}, [%4];"
        : "=r"(r[0]), "=r"(r[1]), "=r"(r[2]), "=r"(r[3]) : "r"(a));
}
__device__ __forceinline__ void mmabf(float* d, const uint32_t* a, const uint32_t* b) {
    asm volatile("mma.sync.aligned.m16n8k16.row.col.f32.bf16.bf16.f32 "
        "{%0,%1,%2,%3}, {%4,%5,%6,%7}, {%8,%9}, {%0,%1,%2,%3};"
        : "+f"(d[0]), "+f"(d[1]), "+f"(d[2]), "+f"(d[3])
        : "r"(a[0]), "r"(a[1]), "r"(a[2]), "r"(a[3]), "r"(b[0]), "r"(b[1]));
}
__device__ __forceinline__ uint32_t packbf2(float lo, float hi) {
    __nv_bfloat162 t = __floats2bfloat162_rn(lo, hi);
    return *(uint32_t*)&t;
}

// ---------------- mask prefix + compact-domain mask + pad zeroing ---------------
// one block per batch, 1024 threads, 2 elements/thread
__global__ __launch_bounds__(1024) void prefix_kernel(const int* __restrict__ mask,
                                                      int* __restrict__ pos,
                                                      int* __restrict__ cmask,
                                                      int* __restrict__ cnt,
                                                      bf16* __restrict__ Knc) {
    int b = blockIdx.x;
    const int* m = mask + b * SKc;
    int t = threadIdx.x;
    int lane = t & 31, w = t >> 5;
    int v0 = m[2 * t], v1 = m[2 * t + 1];
    int s = v0 + v1;
    int sc = s;
    #pragma unroll
    for (int o = 1; o < 32; o <<= 1) {
        int n = __shfl_up_sync(0xffffffffu, sc, o);
        if (lane >= o) sc += n;
    }
    __shared__ int wt[32];
    if (lane == 31) wt[w] = sc;
    __syncthreads();
    if (w == 0) {
        int x = wt[lane];
        #pragma unroll
        for (int o = 1; o < 32; o <<= 1) {
            int n = __shfl_up_sync(0xffffffffu, x, o);
            if (lane >= o) x += n;
        }
        wt[lane] = x;
    }
    __syncthreads();
    int base = ((w > 0) ? wt[w - 1] : 0) + (sc - s);
    pos[b * SKc + 2 * t]     = base;
    pos[b * SKc + 2 * t + 1] = base + v0;
    int total = wt[31];
    if (t == 0) cnt[b] = total;
    cmask[b * SKc + 2 * t]     = (2 * t     < total) ? 1 : 0;
    cmask[b * SKc + 2 * t + 1] = (2 * t + 1 < total) ? 1 : 0;
    // zero pad rows [total, ceil128(total)) of compacted K buffer
    int padN = ((total + 127) >> 7) << 7;
    if (padN > SKc) padN = SKc;
    int nz = (padN - total) * (Dc / 4);   // uint2 (4 bf16) granules per row: 256
    uint2* dst = (uint2*)(Knc + ((size_t)b * SKc + total) * Dc);
    uint2 z; z.x = 0; z.y = 0;
    for (int i = t; i < nz; i += 1024) dst[i] = z;
}

// ---------------- LayerNorm + bf16 (optionally hi/lo split) ---------------------
__global__ __launch_bounds__(256) void ln_split_kernel(const float* __restrict__ x,
                                                       const float* __restrict__ g,
                                                       const float* __restrict__ b,
                                                       bf16* __restrict__ hi,
                                                       bf16* __restrict__ lo) {
    int row = blockIdx.x;
    int t = threadIdx.x;
    const float4* xr = (const float4*)(x + (size_t)row * Dc);
    float4 v = xr[t];
    float s  = v.x + v.y + v.z + v.w;
    float ss = v.x*v.x + v.y*v.y + v.z*v.z + v.w*v.w;
    #pragma unroll
    for (int o = 16; o > 0; o >>= 1) {
        s  += __shfl_xor_sync(0xffffffffu, s,  o);
        ss += __shfl_xor_sync(0xffffffffu, ss, o);
    }
    __shared__ float red[2][8];
    int w = t >> 5, l = t & 31;
    if (l == 0) { red[0][w] = s; red[1][w] = ss; }
    __syncthreads();
    float st = 0.f, sst = 0.f;
    #pragma unroll
    for (int i = 0; i < 8; i++) { st += red[0][i]; sst += red[1][i]; }
    float mean = st * (1.0f / Dc);
    float var  = sst * (1.0f / Dc) - mean * mean;
    float rstd = rsqrtf(var + 1e-5f);
    float4 gg = ((const float4*)g)[t];
    float4 bb = ((const float4*)b)[t];
    float o0 = (v.x - mean) * rstd * gg.x + bb.x;
    float o1 = (v.y - mean) * rstd * gg.y + bb.y;
    float o2 = (v.z - mean) * rstd * gg.z + bb.z;
    float o3 = (v.w - mean) * rstd * gg.w + bb.w;
    size_t base = (size_t)row * Dc + t * 4;
    bf16 h0 = __float2bfloat16_rn(o0), h1 = __float2bfloat16_rn(o1);
    bf16 h2 = __float2bfloat16_rn(o2), h3 = __float2bfloat16_rn(o3);
    __nv_bfloat162 hA; hA.x = h0; hA.y = h1;
    __nv_bfloat162 hB; hB.x = h2; hB.y = h3;
    *(__nv_bfloat162*)(hi + base)     = hA;
    *(__nv_bfloat162*)(hi + base + 2) = hB;
    if (lo) {
        bf16 l0 = __float2bfloat16_rn(o0 - __bfloat162float(h0));
        bf16 l1 = __float2bfloat16_rn(o1 - __bfloat162float(h1));
        bf16 l2 = __float2bfloat16_rn(o2 - __bfloat162float(h2));
        bf16 l3 = __float2bfloat16_rn(o3 - __bfloat162float(h3));
        __nv_bfloat162 lA; lA.x = l0; lA.y = l1;
        __nv_bfloat162 lB; lB.x = l2; lB.y = l3;
        *(__nv_bfloat162*)(lo + base)     = lA;
        *(__nv_bfloat162*)(lo + base + 2) = lB;
    }
}

// ---------------- LayerNorm for K with compaction scatter -----------------------
__global__ __launch_bounds__(256) void ln_k_compact_kernel(const float* __restrict__ x,
                                                           const float* __restrict__ g,
                                                           const float* __restrict__ b,
                                                           const int* __restrict__ mask,
                                                           const int* __restrict__ pos,
                                                           bf16* __restrict__ hi) {
    int row = blockIdx.x;
    if (!mask[row]) return;                   // masked token: contributes nothing
    int t = threadIdx.x;
    const float4* xr = (const float4*)(x + (size_t)row * Dc);
    float4 v = xr[t];
    float s  = v.x + v.y + v.z + v.w;
    float ss = v.x*v.x + v.y*v.y + v.z*v.z + v.w*v.w;
    #pragma unroll
    for (int o = 16; o > 0; o >>= 1) {
        s  += __shfl_xor_sync(0xffffffffu, s,  o);
        ss += __shfl_xor_sync(0xffffffffu, ss, o);
    }
    __shared__ float red[2][8];
    int w = t >> 5, l = t & 31;
    if (l == 0) { red[0][w] = s; red[1][w] = ss; }
    __syncthreads();
    float st = 0.f, sst = 0.f;
    #pragma unroll
    for (int i = 0; i < 8; i++) { st += red[0][i]; sst += red[1][i]; }
    float mean = st * (1.0f / Dc);
    float var  = sst * (1.0f / Dc) - mean * mean;
    float rstd = rsqrtf(var + 1e-5f);
    float4 gg = ((const float4*)g)[t];
    float4 bb = ((const float4*)b)[t];
    float o0 = (v.x - mean) * rstd * gg.x + bb.x;
    float o1 = (v.y - mean) * rstd * gg.y + bb.y;
    float o2 = (v.z - mean) * rstd * gg.z + bb.z;
    float o3 = (v.w - mean) * rstd * gg.w + bb.w;
    int bb_ = row >> 11;
    size_t crow = (size_t)bb_ * SKc + pos[row];
    size_t base = crow * Dc + t * 4;
    __nv_bfloat162 hA = __floats2bfloat162_rn(o0, o1);
    __nv_bfloat162 hB = __floats2bfloat162_rn(o2, o3);
    *(__nv_bfloat162*)(hi + base)     = hA;
    *(__nv_bfloat162*)(hi + base + 2) = hB;
}

// ---------------- merged weight conversion --------------------------------------
__global__ __launch_bounds__(256) void wconv_kernel(const float* __restrict__ Wq,
                                                    const float* __restrict__ Wk,
                                                    const float* __restrict__ Wv,
                                                    const float* __restrict__ Wo,
                                                    bf16* __restrict__ qh,
                                                    bf16* __restrict__ kh,
                                                    bf16* __restrict__ vh,
                                                    bf16* __restrict__ oh,
                                                    bf16* __restrict__ ol) {
    int m = blockIdx.x >> 10;
    int i = (blockIdx.x & 1023) * 256 + threadIdx.x;
    const float* W = (m == 0) ? Wq : (m == 1) ? Wk : (m == 2) ? Wv : Wo;
    bf16* hi = (m == 0) ? qh : (m == 1) ? kh : (m == 2) ? vh : oh;
    float4 v = ((const float4*)W)[i];
    bf16 h0 = __float2bfloat16_rn(v.x), h1 = __float2bfloat16_rn(v.y);
    bf16 h2 = __float2bfloat16_rn(v.z), h3 = __float2bfloat16_rn(v.w);
    __nv_bfloat162 hA; hA.x = h0; hA.y = h1;
    __nv_bfloat162 hB; hB.x = h2; hB.y = h3;
    size_t base = (size_t)i * 4;
    *(__nv_bfloat162*)(hi + base)     = hA;
    *(__nv_bfloat162*)(hi + base + 2) = hB;
    if (m == 3) {
        bf16 l0 = __float2bfloat16_rn(v.x - __bfloat162float(h0));
        bf16 l1 = __float2bfloat16_rn(v.y - __bfloat162float(h1));
        bf16 l2 = __float2bfloat16_rn(v.z - __bfloat162float(h2));
        bf16 l3 = __float2bfloat16_rn(v.w - __bfloat162float(h3));
        __nv_bfloat162 lA; lA.x = l0; lA.y = l1;
        __nv_bfloat162 lB; lB.x = l2; lB.y = l3;
        *(__nv_bfloat162*)(ol + base)     = lA;
        *(__nv_bfloat162*)(ol + base + 2) = lB;
    }
}

// ---------------- HMMA GEMM, all 4 projections in one launch --------------------
// grid (8, 32, 4); z: 0=Q1, 1=K1 (compact), 2=V1 (compact), 3=O2 (x3, relu)
#define GSTG 40960
#define GSMEM (2*GSTG)
__global__ __launch_bounds__(256) void gemm_all_kernel(const bf16* __restrict__ Qh,
                                                       const bf16* __restrict__ Ql,
                                                       const bf16* __restrict__ Kh,
                                                       const bf16* __restrict__ Wqh,
                                                       const bf16* __restrict__ Wkh,
                                                       const bf16* __restrict__ Wvh,
                                                       const bf16* __restrict__ Woh,
                                                       const bf16* __restrict__ Wol,
                                                       const float* __restrict__ bq,
                                                       const float* __restrict__ bk,
                                                       const float* __restrict__ bv,
                                                       const float* __restrict__ bo,
                                                       const int* __restrict__ cnt,
                                                       bf16* __restrict__ Q1b,
                                                       bf16* __restrict__ K1b,
                                                       bf16* __restrict__ V1b,
                                                       float* __restrict__ O2) {
    int z = blockIdx.z;
    int m0 = blockIdx.y * 128, n0 = blockIdx.x * 128;
    if (z == 1 || z == 2) {
        int batch = m0 >> 11;
        int ml = m0 & 2047;
        int padN = ((cnt[batch] + 127) >> 7) << 7;
        if (ml >= padN) return;               // beyond compacted rows: skip
    }
    extern __shared__ char sm[];
    uint32_t sb = smem_u32(sm);
    int tid = threadIdx.x, lane = tid & 31, warp = tid >> 5;

    const bf16* A  = (z == 0 || z == 3) ? Qh : Kh;
    const bf16* Al = Ql;
    const bf16* Wh = (z == 0) ? Wqh : (z == 1) ? Wkh : (z == 2) ? Wvh : Woh;
    const bf16* Wl = Wol;
    const float* bias = (z == 0) ? bq : (z == 1) ? bk : (z == 2) ? bv : bo;
    bf16* Cb = (z == 0) ? Q1b : (z == 1) ? K1b : V1b;
    int triple = (z == 3);

    const bf16* Ahg = A  + (size_t)m0 * Dc;
    const bf16* Alg = Al + (size_t)m0 * Dc;
    const bf16* Whg = Wh + (size_t)n0 * Dc;
    const bf16* Wlg = Wl + (size_t)n0 * Dc;

    auto ldstage = [&](int st, int k0) {
        uint32_t s0 = sb + st * GSTG;
        #pragma unroll
        for (int i = 0; i < 2; i++) {
            int idx = tid + i * 256;
            int r = idx >> 2, c = idx & 3;
            uint32_t so = r * 80 + c * 16;
            size_t   go = (size_t)r * Dc + k0 + c * 8;
            cpa16(s0 +         so, Ahg + go);
            cpa16(s0 + 20480 + so, Whg + go);
            if (triple) {
                cpa16(s0 + 10240 + so, Alg + go);
                cpa16(s0 + 30720 + so, Wlg + go);
            }
        }
    };

    ldstage(0, 0);
    cp_commit();

    int wm = (warp >> 1) * 32, wn = (warp & 1) * 64;
    int g8 = lane >> 3, r8 = lane & 7;
    uint32_t aoffl = (lane & 15) * 80 + (lane >> 4) * 16;
    uint32_t boffl = ((g8 >> 1) * 8 + r8) * 80 + (g8 & 1) * 16;

    float acc[2][8][4];
    #pragma unroll
    for (int mt = 0; mt < 2; mt++)
        #pragma unroll
        for (int nt = 0; nt < 8; nt++)
            #pragma unroll
            for (int j = 0; j < 4; j++) acc[mt][nt][j] = 0.f;

    #pragma unroll 1
    for (int c = 0; c < 32; c++) {
        int st = c & 1;
        if (c + 1 < 32) { ldstage(st ^ 1, (c + 1) * 32); cp_commit(); cp_wait<1>(); }
        else            { cp_wait<0>(); }
        __syncthreads();

        uint32_t SA = sb + st * GSTG;
        #pragma unroll
        for (int ks = 0; ks < 2; ks++) {
            uint32_t ah[2][4], al[2][4];
            #pragma unroll
            for (int mt = 0; mt < 2; mt++) {
                uint32_t abase = SA + (wm + mt * 16) * 80 + aoffl + ks * 32;
                ldm4(ah[mt], abase);
                if (triple) ldm4(al[mt], abase + 10240);
            }
            #pragma unroll
            for (int np = 0; np < 4; np++) {
                uint32_t bh[4], bl[4];
                uint32_t bbase = SA + 20480 + (wn + np * 16) * 80 + boffl + ks * 32;
                ldm4(bh, bbase);
                if (triple) ldm4(bl, bbase + 10240);
                #pragma unroll
                for (int mt = 0; mt < 2; mt++) {
                    mmabf(acc[mt][2*np],   ah[mt], bh);
                    mmabf(acc[mt][2*np+1], ah[mt], bh + 2);
                    if (triple) {
                        mmabf(acc[mt][2*np],   ah[mt], bl);
                        mmabf(acc[mt][2*np+1], ah[mt], bl + 2);
                        mmabf(acc[mt][2*np],   al[mt], bh);
                        mmabf(acc[mt][2*np+1], al[mt], bh + 2);
                    }
                }
            }
        }
        __syncthreads();
    }

    int cq = 2 * (lane & 3);
    #pragma unroll
    for (int mt = 0; mt < 2; mt++) {
        int row0 = m0 + wm + mt * 16 + (lane >> 2);
        #pragma unroll
        for (int nt = 0; nt < 8; nt++) {
            int col = n0 + wn + nt * 8 + cq;
            float b0 = bias[col], b1 = bias[col + 1];
            float c00 = acc[mt][nt][0] + b0, c01 = acc[mt][nt][1] + b1;
            float c10 = acc[mt][nt][2] + b0, c11 = acc[mt][nt][3] + b1;
            if (triple) {
                c00 = fmaxf(c00, 0.f); c01 = fmaxf(c01, 0.f);
                c10 = fmaxf(c10, 0.f); c11 = fmaxf(c11, 0.f);
                float2 v0 = make_float2(c00, c01);
                float2 v1 = make_float2(c10, c11);
                *(float2*)(O2 + (size_t)row0 * Dc + col)       = v0;
                *(float2*)(O2 + (size_t)(row0 + 8) * Dc + col) = v1;
            } else {
                *(uint32_t*)(Cb + (size_t)row0 * Dc + col)       = packbf2(c00, c01);
                *(uint32_t*)(Cb + (size_t)(row0 + 8) * Dc + col) = packbf2(c10, c11);
            }
        }
    }
}

// ---------------- HMMA flash attention (compact keys, no-max) -------------------
#define AQ_OFF   0
#define AK_OFF   18432
#define AV_OFF   36864
#define AM_OFF   55296
#define ASMEM    55808
__global__ __launch_bounds__(256) void attn_mma_kernel(const bf16* __restrict__ Qb,
                                                       const bf16* __restrict__ Kb,
                                                       const bf16* __restrict__ Vb,
                                                       const int* __restrict__ cmask,
                                                       const int* __restrict__ cnt,
                                                       float* __restrict__ O1) {
    extern __shared__ char sm[];
    uint32_t sb = smem_u32(sm);
    int tid = threadIdx.x, lane = tid & 31, warp = tid >> 5;
    int q0 = blockIdx.x * 128;
    int h  = blockIdx.y;
    int b  = blockIdx.z;
    const bf16* Qg = Qb + ((size_t)(b * SQc + q0)) * Dc + h * DHc;
    const bf16* Kg = Kb + ((size_t)b * SKc) * Dc + h * DHc;
    const bf16* Vg = Vb + ((size_t)b * SKc) * Dc + h * DHc;
    const int*  mg = cmask + b * SKc;
    int nch = (cnt[b] + 63) >> 6;            // dynamic chunk count over compact keys

    auto ldkv = [&](int st, int k0) {
        #pragma unroll
        for (int i = 0; i < 2; i++) {
            int idx = tid + i * 256;
            int r = idx >> 3, c = idx & 7;
            uint32_t so = r * 144 + c * 16;
            size_t   go = (size_t)(k0 + r) * Dc + c * 8;
            cpa16(sb + AK_OFF + st * 9216 + so, Kg + go);
            cpa16(sb + AV_OFF + st * 9216 + so, Vg + go);
        }
        if (tid < 16) cpa16(sb + AM_OFF + st * 256 + tid * 16, mg + k0 + tid * 4);
    };

    #pragma unroll
    for (int i = 0; i < 4; i++) {
        int idx = tid + i * 256;
        int r = idx >> 3, c = idx & 7;
        cpa16(sb + AQ_OFF + r * 144 + c * 16, Qg + (size_t)r * Dc + c * 8);
    }
    ldkv(0, 0);
    cp_commit();

    int m0 = warp * 16;
    int g8 = lane >> 3, r8 = lane & 7;
    int cq = 2 * (lane & 3);
    uint32_t qaddr = sb + AQ_OFF + (m0 + (lane & 15)) * 144 + (lane >> 4) * 16;
    uint32_t klane = ((g8 >> 1) * 8 + r8) * 144 + (g8 & 1) * 16;
    uint32_t vlane = ((g8 & 1) * 8 + r8) * 144 + (g8 >> 1) * 16;
    const float SC = 0.03125f;

    float o[8][4];
    #pragma unroll
    for (int dt = 0; dt < 8; dt++)
        #pragma unroll
        for (int j = 0; j < 4; j++) o[dt][j] = 0.f;
    float ls0 = 0.f, ls1 = 0.f;

    #pragma unroll 1
    for (int c = 0; c < nch; c++) {
        int st = c & 1;
        if (c + 1 < nch) { ldkv(st ^ 1, (c + 1) * 64); cp_commit(); cp_wait<1>(); }
        else             { cp_wait<0>(); }
        __syncthreads();

        uint32_t Kst = sb + AK_OFF + st * 9216 + klane;
        uint32_t Vst = sb + AV_OFF + st * 9216 + vlane;
        const int* mp = (const int*)(sm + AM_OFF + st * 256);

        float s_[8][4];
        #pragma unroll
        for (int nt = 0; nt < 8; nt++)
            #pragma unroll
            for (int j = 0; j < 4; j++) s_[nt][j] = 0.f;
        #pragma unroll
        for (int ks = 0; ks < 4; ks++) {
            uint32_t aq[4];
            ldm4(aq, qaddr + ks * 32);
            #pragma unroll
            for (int np = 0; np < 4; np++) {
                uint32_t bk[4];
                ldm4(bk, Kst + np * 2304 + ks * 32);
                mmabf(s_[2*np],   aq, bk);
                mmabf(s_[2*np+1], aq, bk + 2);
            }
        }

        uint32_t pr0[8], pr1[8];
        #pragma unroll
        for (int nt = 0; nt < 8; nt++) {
            float f0 = (float)mp[nt * 8 + cq];
            float f1 = (float)mp[nt * 8 + cq + 1];
            float p0 = __expf(s_[nt][0] * SC) * f0;
            float p1 = __expf(s_[nt][1] * SC) * f1;
            float p2 = __expf(s_[nt][2] * SC) * f0;
            float p3 = __expf(s_[nt][3] * SC) * f1;
            ls0 += p0 + p1;
            ls1 += p2 + p3;
            pr0[nt] = packbf2(p0, p1);
            pr1[nt] = packbf2(p2, p3);
        }

        #pragma unroll
        for (int ks2 = 0; ks2 < 4; ks2++) {
            uint32_t pf[4] = { pr0[2*ks2], pr1[2*ks2], pr0[2*ks2+1], pr1[2*ks2+1] };
            #pragma unroll
            for (int dp = 0; dp < 4; dp++) {
                uint32_t bv[4];
                ldm4t(bv, Vst + ks2 * 2304 + dp * 32);
                mmabf(o[2*dp],   pf, bv);
                mmabf(o[2*dp+1], pf, bv + 2);
            }
        }
        __syncthreads();
    }

    ls0 += __shfl_xor_sync(0xffffffffu, ls0, 1);
    ls0 += __shfl_xor_sync(0xffffffffu, ls0, 2);
    ls1 += __shfl_xor_sync(0xffffffffu, ls1, 1);
    ls1 += __shfl_xor_sync(0xffffffffu, ls1, 2);
    float i0 = 1.f / ls0, i1 = 1.f / ls1;
    int row0 = q0 + m0 + (lane >> 2);
    float* Or0 = O1 + ((size_t)(b * SQc) + row0) * Dc + h * DHc + cq;
    float* Or1 = Or0 + (size_t)8 * Dc;
    #pragma unroll
    for (int dt = 0; dt < 8; dt++) {
        float2 v0 = make_float2(o[dt][0] * i0, o[dt][1] * i0);
        float2 v1 = make_float2(o[dt][2] * i1, o[dt][3] * i1);
        *(float2*)(Or0 + dt * 8) = v0;
        *(float2*)(Or1 + dt * 8) = v1;
    }
}

// ---------------- fused residual-add + LayerNorm (final) ------------------------
__global__ __launch_bounds__(256) void final_ln_kernel(const float* __restrict__ Q,
                                                       const float* __restrict__ O1,
                                                       const float* __restrict__ O2,
                                                       const float* __restrict__ g,
                                                       const float* __restrict__ b,
                                                       float* __restrict__ out) {
    int row = blockIdx.x;
    int t = threadIdx.x;
    size_t base = (size_t)row * Dc;
    float4 q  = ((const float4*)(Q  + base))[t];
    float4 o1 = ((const float4*)(O1 + base))[t];
    float4 o2 = ((const float4*)(O2 + base))[t];
    float4 v;
    v.x = q.x + o1.x + o2.x;
    v.y = q.y + o1.y + o2.y;
    v.z = q.z + o1.z + o2.z;
    v.w = q.w + o1.w + o2.w;
    float s  = v.x + v.y + v.z + v.w;
    float ss = v.x*v.x + v.y*v.y + v.z*v.z + v.w*v.w;
    #pragma unroll
    for (int o = 16; o > 0; o >>= 1) {
        s  += __shfl_xor_sync(0xffffffffu, s,  o);
        ss += __shfl_xor_sync(0xffffffffu, ss, o);
    }
    __shared__ float red[2][8];
    int w = t >> 5, l = t & 31;
    if (l == 0) { red[0][w] = s; red[1][w] = ss; }
    __syncthreads();
    float st = 0.f, sst = 0.f;
    #pragma unroll
    for (int i = 0; i < 8; i++) { st += red[0][i]; sst += red[1][i]; }
    float mean = st * (1.0f / Dc);
    float var  = sst * (1.0f / Dc) - mean * mean;
    float rstd = rsqrtf(var + 1e-5f);
    float4 gg = ((const float4*)g)[t];
    float4 bb = ((const float4*)b)[t];
    float4 o;
    o.x = (v.x - mean) * rstd * gg.x + bb.x;
    o.y = (v.y - mean) * rstd * gg.y + bb.y;
    o.z = (v.z - mean) * rstd * gg.z + bb.z;
    o.w = (v.w - mean) * rstd * gg.w + bb.w;
    ((float4*)(out + base))[t] = o;
}

// ---------------- launch -------------------------------------------------------
extern "C" void kernel_launch(void* const* d_in, const int* in_sizes, int n_in,
                              void* d_out, int out_size) {
    const float* Q       = (const float*)d_in[0];
    const float* K       = (const float*)d_in[1];
    const int*   padm    = (const int*)d_in[2];
    const float* Wq      = (const float*)d_in[3];
    const float* Wk      = (const float*)d_in[4];
    const float* Wv      = (const float*)d_in[5];
    const float* Wo      = (const float*)d_in[6];
    const float* bq      = (const float*)d_in[7];
    const float* bk      = (const float*)d_in[8];
    const float* bv      = (const float*)d_in[9];
    const float* bo      = (const float*)d_in[10];
    const float* ln_q_g  = (const float*)d_in[11];
    const float* ln_q_b  = (const float*)d_in[12];
    const float* ln_kv_g = (const float*)d_in[13];
    const float* ln_kv_b = (const float*)d_in[14];
    const float* ln_f_g  = (const float*)d_in[15];
    const float* ln_f_b  = (const float*)d_in[16];
    float* out = (float*)d_out;

    bf16 *pQh, *pQl, *pKh;
    bf16 *pWqh, *pWkh, *pWvh, *pWoh, *pWol;
    bf16 *pQ1b, *pK1b, *pV1b;
    float *pO1, *pO2;
    int *pPos, *pCmask, *pCnt;
    cudaGetSymbolAddress((void**)&pQh, g_Qh);   cudaGetSymbolAddress((void**)&pQl, g_Ql);
    cudaGetSymbolAddress((void**)&pKh, g_Kh);
    cudaGetSymbolAddress((void**)&pWqh, g_Wqh);
    cudaGetSymbolAddress((void**)&pWkh, g_Wkh);
    cudaGetSymbolAddress((void**)&pWvh, g_Wvh);
    cudaGetSymbolAddress((void**)&pWoh, g_Woh); cudaGetSymbolAddress((void**)&pWol, g_Wol);
    cudaGetSymbolAddress((void**)&pQ1b, g_Q1b);
    cudaGetSymbolAddress((void**)&pK1b, g_K1b);
    cudaGetSymbolAddress((void**)&pV1b, g_V1b);
    cudaGetSymbolAddress((void**)&pO1, g_O1);
    cudaGetSymbolAddress((void**)&pO2, g_O2);
    cudaGetSymbolAddress((void**)&pPos, g_pos);
    cudaGetSymbolAddress((void**)&pCmask, g_cmask);
    cudaGetSymbolAddress((void**)&pCnt, g_cnt);

    cudaFuncSetAttribute(gemm_all_kernel, cudaFuncAttributeMaxDynamicSharedMemorySize, GSMEM);
    cudaFuncSetAttribute(attn_mma_kernel, cudaFuncAttributeMaxDynamicSharedMemorySize, ASMEM);

    prefix_kernel<<<Bc, 1024>>>(padm, pPos, pCmask, pCnt, pKh);
    ln_split_kernel<<<NTOK, 256>>>(Q, ln_q_g, ln_q_b, pQh, pQl);
    ln_k_compact_kernel<<<NTOK, 256>>>(K, ln_kv_g, ln_kv_b, padm, pPos, pKh);
    wconv_kernel<<<4096, 256>>>(Wq, Wk, Wv, Wo, pWqh, pWkh, pWvh, pWoh, pWol);

    dim3 ggrid(Dc / 128, NTOK / 128, 4);  // (8, 32, 4)
    gemm_all_kernel<<<ggrid, 256, GSMEM>>>(pQh, pQl, pKh,
                                           pWqh, pWkh, pWvh, pWoh, pWol,
                                           bq, bk, bv, bo, pCnt,
                                           pQ1b, pK1b, pV1b, pO2);

    dim3 agrid(SQc / 128, Hc, Bc);        // (16, 16, 2)
    attn_mma_kernel<<<agrid, 256, ASMEM>>>(pQ1b, pK1b, pV1b, pCmask, pCnt, pO1);

    final_ln_kernel<<<NTOK, 256>>>(Q, pO1, pO2, ln_f_g, ln_f_b, out);
}

// round 11
// speedup vs baseline: 14.0611x; 1.2846x over previous
#include <cuda_runtime.h>
#include <cuda_bf16.h>
#include <cstdint>
#include <math.h>

#define Bc  2
#define SQc 2048
#define SKc 2048
#define Dc  1024
#define Hc  16
#define DHc 64
#define NTOK (Bc*SQc)
#define ELEMS (Bc*SQc*Dc)

typedef __nv_bfloat16 bf16;

// ---------------- scratch (static device arrays; no allocation) ----------------
__device__ bf16  g_Qh[ELEMS];                  // LN(Q) bf16 (Q1 projection input)
__device__ float g_Qn[ELEMS];                  // LN(Q) fp32 (Wo tf32 path input)
__device__ bf16  g_Kh[ELEMS];                  // LN(K), compacted per batch
__device__ bf16  g_Wqh[Dc*Dc], g_Wkh[Dc*Dc], g_Wvh[Dc*Dc];
__device__ bf16  g_Q1b[ELEMS], g_K1b[ELEMS], g_V1b[ELEMS];  // projections (bf16)
__device__ float g_O1[ELEMS];   // attention output
__device__ float g_O2[ELEMS];   // Q + relu(Qn @ Wo^T + bo)   (residual folded in)
__device__ int   g_pos[NTOK];   // within-batch exclusive prefix of mask
__device__ int   g_cmask[NTOK]; // compact-domain validity mask (j < cnt[b])
__device__ int   g_cnt[Bc];     // unmasked count per batch

// ---------------- PTX helpers (plain sm_80-era; compute_103 virtual arch) -------
__device__ __forceinline__ uint32_t smem_u32(const void* p) {
    uint32_t a;
    asm("{ .reg .u64 t; cvta.to.shared.u64 t, %1; cvt.u32.u64 %0, t; }" : "=r"(a) : "l"(p));
    return a;
}
__device__ __forceinline__ void cpa16(uint32_t saddr, const void* g) {
    asm volatile("cp.async.cg.shared.global [%0], [%1], 16;" :: "r"(saddr), "l"(g) : "memory");
}
__device__ __forceinline__ void cp_commit() {
    asm volatile("cp.async.commit_group;" ::: "memory");
}
template<int N> __device__ __forceinline__ void cp_wait() {
    asm volatile("cp.async.wait_group %0;" :: "n"(N) : "memory");
}
__device__ __forceinline__ void ldm4(uint32_t* r, uint32_t a) {
    asm volatile("ldmatrix.sync.aligned.m8n8.x4.shared.b16 {%0,%1,%2,%3}, [%4];"
        : "=r"(r[0]), "=r"(r[1]), "=r"(r[2]), "=r"(r[3]) : "r"(a));
}
__device__ __forceinline__ void ldm4t(uint32_t* r, uint32_t a) {
    asm volatile("ldmatrix.sync.aligned.m8n8.x4.trans.shared.b16 {%0,%1,%2,%3}, [%4];"
        : "=r"(r[0]), "=r"(r[1]), "=r"(r[2]), "=r"(r[3]) : "r"(a));
}
__device__ __forceinline__ void mmabf(float* d, const uint32_t* a, const uint32_t* b) {
    asm volatile("mma.sync.aligned.m16n8k16.row.col.f32.bf16.bf16.f32 "
        "{%0,%1,%2,%3}, {%4,%5,%6,%7}, {%8,%9}, {%0,%1,%2,%3};"
        : "+f"(d[0]), "+f"(d[1]), "+f"(d[2]), "+f"(d[3])
        : "r"(a[0]), "r"(a[1]), "r"(a[2]), "r"(a[3]), "r"(b[0]), "r"(b[1]));
}
__device__ __forceinline__ void mmatf(float* d, const uint32_t* a, uint32_t b0, uint32_t b1) {
    asm volatile("mma.sync.aligned.m16n8k8.row.col.f32.tf32.tf32.f32 "
        "{%0,%1,%2,%3}, {%4,%5,%6,%7}, {%8,%9}, {%0,%1,%2,%3};"
        : "+f"(d[0]), "+f"(d[1]), "+f"(d[2]), "+f"(d[3])
        : "r"(a[0]), "r"(a[1]), "r"(a[2]), "r"(a[3]), "r"(b0), "r"(b1));
}
__device__ __forceinline__ uint32_t cvt_tf32(uint32_t v) {
    uint32_t y; float f = __uint_as_float(v);
    asm("cvt.rna.tf32.f32 %0, %1;" : "=r"(y) : "f"(f));
    return y;
}
__device__ __forceinline__ uint32_t packbf2(float lo, float hi) {
    __nv_bfloat162 t = __floats2bfloat162_rn(lo, hi);
    return *(uint32_t*)&t;
}

// ---------------- mask prefix + compact-domain mask + pad zeroing ---------------
__global__ __launch_bounds__(1024) void prefix_kernel(const int* __restrict__ mask,
                                                      int* __restrict__ pos,
                                                      int* __restrict__ cmask,
                                                      int* __restrict__ cnt,
                                                      bf16* __restrict__ Knc) {
    int b = blockIdx.x;
    const int* m = mask + b * SKc;
    int t = threadIdx.x;
    int lane = t & 31, w = t >> 5;
    int v0 = m[2 * t], v1 = m[2 * t + 1];
    int s = v0 + v1;
    int sc = s;
    #pragma unroll
    for (int o = 1; o < 32; o <<= 1) {
        int n = __shfl_up_sync(0xffffffffu, sc, o);
        if (lane >= o) sc += n;
    }
    __shared__ int wt[32];
    if (lane == 31) wt[w] = sc;
    __syncthreads();
    if (w == 0) {
        int x = wt[lane];
        #pragma unroll
        for (int o = 1; o < 32; o <<= 1) {
            int n = __shfl_up_sync(0xffffffffu, x, o);
            if (lane >= o) x += n;
        }
        wt[lane] = x;
    }
    __syncthreads();
    int base = ((w > 0) ? wt[w - 1] : 0) + (sc - s);
    pos[b * SKc + 2 * t]     = base;
    pos[b * SKc + 2 * t + 1] = base + v0;
    int total = wt[31];
    if (t == 0) cnt[b] = total;
    cmask[b * SKc + 2 * t]     = (2 * t     < total) ? 1 : 0;
    cmask[b * SKc + 2 * t + 1] = (2 * t + 1 < total) ? 1 : 0;
    int padN = ((total + 127) >> 7) << 7;
    if (padN > SKc) padN = SKc;
    int nz = (padN - total) * (Dc / 4);
    uint2* dst = (uint2*)(Knc + ((size_t)b * SKc + total) * Dc);
    uint2 z; z.x = 0; z.y = 0;
    for (int i = t; i < nz; i += 1024) dst[i] = z;
}

// ---------------- LayerNorm for Q: bf16 + fp32 outputs --------------------------
__global__ __launch_bounds__(256) void ln_q_kernel(const float* __restrict__ x,
                                                   const float* __restrict__ g,
                                                   const float* __restrict__ b,
                                                   bf16* __restrict__ hi,
                                                   float* __restrict__ f32o) {
    int row = blockIdx.x;
    int t = threadIdx.x;
    const float4* xr = (const float4*)(x + (size_t)row * Dc);
    float4 v = xr[t];
    float s  = v.x + v.y + v.z + v.w;
    float ss = v.x*v.x + v.y*v.y + v.z*v.z + v.w*v.w;
    #pragma unroll
    for (int o = 16; o > 0; o >>= 1) {
        s  += __shfl_xor_sync(0xffffffffu, s,  o);
        ss += __shfl_xor_sync(0xffffffffu, ss, o);
    }
    __shared__ float red[2][8];
    int w = t >> 5, l = t & 31;
    if (l == 0) { red[0][w] = s; red[1][w] = ss; }
    __syncthreads();
    float st = 0.f, sst = 0.f;
    #pragma unroll
    for (int i = 0; i < 8; i++) { st += red[0][i]; sst += red[1][i]; }
    float mean = st * (1.0f / Dc);
    float var  = sst * (1.0f / Dc) - mean * mean;
    float rstd = rsqrtf(var + 1e-5f);
    float4 gg = ((const float4*)g)[t];
    float4 bb = ((const float4*)b)[t];
    float4 o;
    o.x = (v.x - mean) * rstd * gg.x + bb.x;
    o.y = (v.y - mean) * rstd * gg.y + bb.y;
    o.z = (v.z - mean) * rstd * gg.z + bb.z;
    o.w = (v.w - mean) * rstd * gg.w + bb.w;
    size_t base = (size_t)row * Dc + t * 4;
    *(float4*)(f32o + base) = o;
    __nv_bfloat162 hA = __floats2bfloat162_rn(o.x, o.y);
    __nv_bfloat162 hB = __floats2bfloat162_rn(o.z, o.w);
    *(__nv_bfloat162*)(hi + base)     = hA;
    *(__nv_bfloat162*)(hi + base + 2) = hB;
}

// ---------------- LayerNorm for K with compaction scatter -----------------------
__global__ __launch_bounds__(256) void ln_k_compact_kernel(const float* __restrict__ x,
                                                           const float* __restrict__ g,
                                                           const float* __restrict__ b,
                                                           const int* __restrict__ mask,
                                                           const int* __restrict__ pos,
                                                           bf16* __restrict__ hi) {
    int row = blockIdx.x;
    if (!mask[row]) return;
    int t = threadIdx.x;
    const float4* xr = (const float4*)(x + (size_t)row * Dc);
    float4 v = xr[t];
    float s  = v.x + v.y + v.z + v.w;
    float ss = v.x*v.x + v.y*v.y + v.z*v.z + v.w*v.w;
    #pragma unroll
    for (int o = 16; o > 0; o >>= 1) {
        s  += __shfl_xor_sync(0xffffffffu, s,  o);
        ss += __shfl_xor_sync(0xffffffffu, ss, o);
    }
    __shared__ float red[2][8];
    int w = t >> 5, l = t & 31;
    if (l == 0) { red[0][w] = s; red[1][w] = ss; }
    __syncthreads();
    float st = 0.f, sst = 0.f;
    #pragma unroll
    for (int i = 0; i < 8; i++) { st += red[0][i]; sst += red[1][i]; }
    float mean = st * (1.0f / Dc);
    float var  = sst * (1.0f / Dc) - mean * mean;
    float rstd = rsqrtf(var + 1e-5f);
    float4 gg = ((const float4*)g)[t];
    float4 bb = ((const float4*)b)[t];
    float o0 = (v.x - mean) * rstd * gg.x + bb.x;
    float o1 = (v.y - mean) * rstd * gg.y + bb.y;
    float o2 = (v.z - mean) * rstd * gg.z + bb.z;
    float o3 = (v.w - mean) * rstd * gg.w + bb.w;
    int bb_ = row >> 11;
    size_t crow = (size_t)bb_ * SKc + pos[row];
    size_t base = crow * Dc + t * 4;
    __nv_bfloat162 hA = __floats2bfloat162_rn(o0, o1);
    __nv_bfloat162 hB = __floats2bfloat162_rn(o2, o3);
    *(__nv_bfloat162*)(hi + base)     = hA;
    *(__nv_bfloat162*)(hi + base + 2) = hB;
}

// ---------------- weight conversion (Wq, Wk, Wv -> bf16) ------------------------
__global__ __launch_bounds__(256) void wconv3_kernel(const float* __restrict__ Wq,
                                                     const float* __restrict__ Wk,
                                                     const float* __restrict__ Wv,
                                                     bf16* __restrict__ qh,
                                                     bf16* __restrict__ kh,
                                                     bf16* __restrict__ vh) {
    int m = blockIdx.x >> 10;
    int i = (blockIdx.x & 1023) * 256 + threadIdx.x;
    const float* W = (m == 0) ? Wq : (m == 1) ? Wk : Wv;
    bf16* hi = (m == 0) ? qh : (m == 1) ? kh : vh;
    float4 v = ((const float4*)W)[i];
    __nv_bfloat162 hA = __floats2bfloat162_rn(v.x, v.y);
    __nv_bfloat162 hB = __floats2bfloat162_rn(v.z, v.w);
    size_t base = (size_t)i * 4;
    *(__nv_bfloat162*)(hi + base)     = hA;
    *(__nv_bfloat162*)(hi + base + 2) = hB;
}

// ---------------- HMMA bf16 GEMM: Q1/K1/V1 projections (single pass) ------------
// grid (8, 32, 3); z: 0=Q1, 1=K1 (compact), 2=V1 (compact). 40KB smem, 2 CTA/SM.
#define GS2 20480
__global__ __launch_bounds__(256, 2) void gemm_single_kernel(const bf16* __restrict__ Qh,
                                                             const bf16* __restrict__ Kh,
                                                             const bf16* __restrict__ Wqh,
                                                             const bf16* __restrict__ Wkh,
                                                             const bf16* __restrict__ Wvh,
                                                             const float* __restrict__ bq,
                                                             const float* __restrict__ bk,
                                                             const float* __restrict__ bv,
                                                             const int* __restrict__ cnt,
                                                             bf16* __restrict__ Q1b,
                                                             bf16* __restrict__ K1b,
                                                             bf16* __restrict__ V1b) {
    int z = blockIdx.z;
    int m0 = blockIdx.y * 128, n0 = blockIdx.x * 128;
    if (z >= 1) {
        int batch = m0 >> 11;
        int ml = m0 & 2047;
        int padN = ((cnt[batch] + 127) >> 7) << 7;
        if (ml >= padN) return;
    }
    extern __shared__ char sm[];
    uint32_t sb = smem_u32(sm);
    int tid = threadIdx.x, lane = tid & 31, warp = tid >> 5;

    const bf16* A  = (z == 0) ? Qh : Kh;
    const bf16* Wh = (z == 0) ? Wqh : (z == 1) ? Wkh : Wvh;
    const float* bias = (z == 0) ? bq : (z == 1) ? bk : bv;
    bf16* Cb = (z == 0) ? Q1b : (z == 1) ? K1b : V1b;

    const bf16* Ahg = A  + (size_t)m0 * Dc;
    const bf16* Whg = Wh + (size_t)n0 * Dc;

    auto ldstage = [&](int st, int k0) {
        uint32_t s0 = sb + st * GS2;
        #pragma unroll
        for (int i = 0; i < 2; i++) {
            int idx = tid + i * 256;
            int r = idx >> 2, c = idx & 3;
            uint32_t so = r * 80 + c * 16;
            size_t   go = (size_t)r * Dc + k0 + c * 8;
            cpa16(s0 +         so, Ahg + go);
            cpa16(s0 + 10240 + so, Whg + go);
        }
    };

    ldstage(0, 0);
    cp_commit();

    int wm = (warp >> 1) * 32, wn = (warp & 1) * 64;
    int g8 = lane >> 3, r8 = lane & 7;
    uint32_t aoffl = (lane & 15) * 80 + (lane >> 4) * 16;
    uint32_t boffl = ((g8 >> 1) * 8 + r8) * 80 + (g8 & 1) * 16;

    float acc[2][8][4];
    #pragma unroll
    for (int mt = 0; mt < 2; mt++)
        #pragma unroll
        for (int nt = 0; nt < 8; nt++)
            #pragma unroll
            for (int j = 0; j < 4; j++) acc[mt][nt][j] = 0.f;

    #pragma unroll 1
    for (int c = 0; c < 32; c++) {
        int st = c & 1;
        if (c + 1 < 32) { ldstage(st ^ 1, (c + 1) * 32); cp_commit(); cp_wait<1>(); }
        else            { cp_wait<0>(); }
        __syncthreads();

        uint32_t SA = sb + st * GS2;
        #pragma unroll
        for (int ks = 0; ks < 2; ks++) {
            uint32_t ah[2][4];
            #pragma unroll
            for (int mt = 0; mt < 2; mt++)
                ldm4(ah[mt], SA + (wm + mt * 16) * 80 + aoffl + ks * 32);
            #pragma unroll
            for (int np = 0; np < 4; np++) {
                uint32_t bh[4];
                ldm4(bh, SA + 10240 + (wn + np * 16) * 80 + boffl + ks * 32);
                #pragma unroll
                for (int mt = 0; mt < 2; mt++) {
                    mmabf(acc[mt][2*np],   ah[mt], bh);
                    mmabf(acc[mt][2*np+1], ah[mt], bh + 2);
                }
            }
        }
        __syncthreads();
    }

    int cq = 2 * (lane & 3);
    #pragma unroll
    for (int mt = 0; mt < 2; mt++) {
        int row0 = m0 + wm + mt * 16 + (lane >> 2);
        #pragma unroll
        for (int nt = 0; nt < 8; nt++) {
            int col = n0 + wn + nt * 8 + cq;
            float b0 = bias[col], b1 = bias[col + 1];
            *(uint32_t*)(Cb + (size_t)row0 * Dc + col)       = packbf2(acc[mt][nt][0] + b0, acc[mt][nt][1] + b1);
            *(uint32_t*)(Cb + (size_t)(row0 + 8) * Dc + col) = packbf2(acc[mt][nt][2] + b0, acc[mt][nt][3] + b1);
        }
    }
}

// ---------------- tf32 GEMM: O2 = Q + relu(Qn @ Wo^T + bo) ----------------------
// fp32 smem tiles (pitch 144B), ldmatrix-b16 trick for tf32 fragments,
// in-register cvt.rna.tf32. grid (8, 32). smem = 2 * 36864 = 72KB.
#define WSTG 36864
#define WSMEM (2*WSTG)
__global__ __launch_bounds__(256) void gemm_wo_tf32_kernel(const float* __restrict__ Qn,
                                                           const float* __restrict__ Wo,
                                                           const float* __restrict__ bo,
                                                           const float* __restrict__ Qres,
                                                           float* __restrict__ O2) {
    extern __shared__ char sm[];
    uint32_t sb = smem_u32(sm);
    int tid = threadIdx.x, lane = tid & 31, warp = tid >> 5;
    int m0 = blockIdx.y * 128, n0 = blockIdx.x * 128;
    const float* Ag = Qn + (size_t)m0 * Dc;
    const float* Wg = Wo + (size_t)n0 * Dc;

    auto ldstage = [&](int st, int k0) {
        uint32_t s0 = sb + st * WSTG;
        #pragma unroll
        for (int i = 0; i < 4; i++) {
            int idx = tid + i * 256;       // 0..1023 over one tile's chunks
            int r = idx >> 3, c = idx & 7; // 128 rows x 8 chunks of 16B
            uint32_t so = r * 144 + c * 16;
            size_t   go = (size_t)r * Dc + k0 + c * 4;
            cpa16(s0 +         so, Ag + go);
            cpa16(s0 + 18432 + so, Wg + go);
        }
    };

    ldstage(0, 0);
    cp_commit();

    int wm = (warp >> 1) * 32, wn = (warp & 1) * 64;
    uint32_t aoffl = (lane & 15) * 144 + (lane >> 4) * 16;
    uint32_t boffl = ((lane & 7) + ((lane >> 4) << 3)) * 144 + ((lane >> 3) & 1) * 16;

    float acc[2][8][4];
    #pragma unroll
    for (int mt = 0; mt < 2; mt++)
        #pragma unroll
        for (int nt = 0; nt < 8; nt++)
            #pragma unroll
            for (int j = 0; j < 4; j++) acc[mt][nt][j] = 0.f;

    #pragma unroll 1
    for (int c = 0; c < 32; c++) {
        int st = c & 1;
        if (c + 1 < 32) { ldstage(st ^ 1, (c + 1) * 32); cp_commit(); cp_wait<1>(); }
        else            { cp_wait<0>(); }
        __syncthreads();

        uint32_t SA = sb + st * WSTG;
        #pragma unroll
        for (int ks = 0; ks < 4; ks++) {           // 4 k8 steps per BK=32
            uint32_t ar[2][4];
            #pragma unroll
            for (int mt = 0; mt < 2; mt++) {
                ldm4(ar[mt], SA + (wm + mt * 16) * 144 + aoffl + ks * 32);
                #pragma unroll
                for (int j = 0; j < 4; j++) ar[mt][j] = cvt_tf32(ar[mt][j]);
            }
            #pragma unroll
            for (int np = 0; np < 4; np++) {
                uint32_t br[4];
                ldm4(br, SA + 18432 + (wn + np * 16) * 144 + boffl + ks * 32);
                #pragma unroll
                for (int j = 0; j < 4; j++) br[j] = cvt_tf32(br[j]);
                #pragma unroll
                for (int mt = 0; mt < 2; mt++) {
                    mmatf(acc[mt][2*np],   ar[mt], br[0], br[1]);
                    mmatf(acc[mt][2*np+1], ar[mt], br[2], br[3]);
                }
            }
        }
        __syncthreads();
    }

    int cq = 2 * (lane & 3);
    #pragma unroll
    for (int mt = 0; mt < 2; mt++) {
        int row0 = m0 + wm + mt * 16 + (lane >> 2);
        #pragma unroll
        for (int nt = 0; nt < 8; nt++) {
            int col = n0 + wn + nt * 8 + cq;
            float b0 = bo[col], b1 = bo[col + 1];
            float2 q0 = *(const float2*)(Qres + (size_t)row0 * Dc + col);
            float2 q1 = *(const float2*)(Qres + (size_t)(row0 + 8) * Dc + col);
            float2 v0 = make_float2(q0.x + fmaxf(acc[mt][nt][0] + b0, 0.f),
                                    q0.y + fmaxf(acc[mt][nt][1] + b1, 0.f));
            float2 v1 = make_float2(q1.x + fmaxf(acc[mt][nt][2] + b0, 0.f),
                                    q1.y + fmaxf(acc[mt][nt][3] + b1, 0.f));
            *(float2*)(O2 + (size_t)row0 * Dc + col)       = v0;
            *(float2*)(O2 + (size_t)(row0 + 8) * Dc + col) = v1;
        }
    }
}

// ---------------- HMMA flash attention (compact keys, no-max) -------------------
#define AQ_OFF   0
#define AK_OFF   18432
#define AV_OFF   36864
#define AM_OFF   55296
#define ASMEM    55808
__global__ __launch_bounds__(256) void attn_mma_kernel(const bf16* __restrict__ Qb,
                                                       const bf16* __restrict__ Kb,
                                                       const bf16* __restrict__ Vb,
                                                       const int* __restrict__ cmask,
                                                       const int* __restrict__ cnt,
                                                       float* __restrict__ O1) {
    extern __shared__ char sm[];
    uint32_t sb = smem_u32(sm);
    int tid = threadIdx.x, lane = tid & 31, warp = tid >> 5;
    int q0 = blockIdx.x * 128;
    int h  = blockIdx.y;
    int b  = blockIdx.z;
    const bf16* Qg = Qb + ((size_t)(b * SQc + q0)) * Dc + h * DHc;
    const bf16* Kg = Kb + ((size_t)b * SKc) * Dc + h * DHc;
    const bf16* Vg = Vb + ((size_t)b * SKc) * Dc + h * DHc;
    const int*  mg = cmask + b * SKc;
    int nch = (cnt[b] + 63) >> 6;

    auto ldkv = [&](int st, int k0) {
        #pragma unroll
        for (int i = 0; i < 2; i++) {
            int idx = tid + i * 256;
            int r = idx >> 3, c = idx & 7;
            uint32_t so = r * 144 + c * 16;
            size_t   go = (size_t)(k0 + r) * Dc + c * 8;
            cpa16(sb + AK_OFF + st * 9216 + so, Kg + go);
            cpa16(sb + AV_OFF + st * 9216 + so, Vg + go);
        }
        if (tid < 16) cpa16(sb + AM_OFF + st * 256 + tid * 16, mg + k0 + tid * 4);
    };

    #pragma unroll
    for (int i = 0; i < 4; i++) {
        int idx = tid + i * 256;
        int r = idx >> 3, c = idx & 7;
        cpa16(sb + AQ_OFF + r * 144 + c * 16, Qg + (size_t)r * Dc + c * 8);
    }
    ldkv(0, 0);
    cp_commit();

    int m0 = warp * 16;
    int g8 = lane >> 3, r8 = lane & 7;
    int cq = 2 * (lane & 3);
    uint32_t qaddr = sb + AQ_OFF + (m0 + (lane & 15)) * 144 + (lane >> 4) * 16;
    uint32_t klane = ((g8 >> 1) * 8 + r8) * 144 + (g8 & 1) * 16;
    uint32_t vlane = ((g8 & 1) * 8 + r8) * 144 + (g8 >> 1) * 16;
    const float SC = 0.03125f;

    float o[8][4];
    #pragma unroll
    for (int dt = 0; dt < 8; dt++)
        #pragma unroll
        for (int j = 0; j < 4; j++) o[dt][j] = 0.f;
    float ls0 = 0.f, ls1 = 0.f;

    #pragma unroll 1
    for (int c = 0; c < nch; c++) {
        int st = c & 1;
        if (c + 1 < nch) { ldkv(st ^ 1, (c + 1) * 64); cp_commit(); cp_wait<1>(); }
        else             { cp_wait<0>(); }
        __syncthreads();

        uint32_t Kst = sb + AK_OFF + st * 9216 + klane;
        uint32_t Vst = sb + AV_OFF + st * 9216 + vlane;
        const int* mp = (const int*)(sm + AM_OFF + st * 256);

        float s_[8][4];
        #pragma unroll
        for (int nt = 0; nt < 8; nt++)
            #pragma unroll
            for (int j = 0; j < 4; j++) s_[nt][j] = 0.f;
        #pragma unroll
        for (int ks = 0; ks < 4; ks++) {
            uint32_t aq[4];
            ldm4(aq, qaddr + ks * 32);
            #pragma unroll
            for (int np = 0; np < 4; np++) {
                uint32_t bk[4];
                ldm4(bk, Kst + np * 2304 + ks * 32);
                mmabf(s_[2*np],   aq, bk);
                mmabf(s_[2*np+1], aq, bk + 2);
            }
        }

        uint32_t pr0[8], pr1[8];
        #pragma unroll
        for (int nt = 0; nt < 8; nt++) {
            float f0 = (float)mp[nt * 8 + cq];
            float f1 = (float)mp[nt * 8 + cq + 1];
            float p0 = __expf(s_[nt][0] * SC) * f0;
            float p1 = __expf(s_[nt][1] * SC) * f1;
            float p2 = __expf(s_[nt][2] * SC) * f0;
            float p3 = __expf(s_[nt][3] * SC) * f1;
            ls0 += p0 + p1;
            ls1 += p2 + p3;
            pr0[nt] = packbf2(p0, p1);
            pr1[nt] = packbf2(p2, p3);
        }

        #pragma unroll
        for (int ks2 = 0; ks2 < 4; ks2++) {
            uint32_t pf[4] = { pr0[2*ks2], pr1[2*ks2], pr0[2*ks2+1], pr1[2*ks2+1] };
            #pragma unroll
            for (int dp = 0; dp < 4; dp++) {
                uint32_t bv[4];
                ldm4t(bv, Vst + ks2 * 2304 + dp * 32);
                mmabf(o[2*dp],   pf, bv);
                mmabf(o[2*dp+1], pf, bv + 2);
            }
        }
        __syncthreads();
    }

    ls0 += __shfl_xor_sync(0xffffffffu, ls0, 1);
    ls0 += __shfl_xor_sync(0xffffffffu, ls0, 2);
    ls1 += __shfl_xor_sync(0xffffffffu, ls1, 1);
    ls1 += __shfl_xor_sync(0xffffffffu, ls1, 2);
    float i0 = 1.f / ls0, i1 = 1.f / ls1;
    int row0 = q0 + m0 + (lane >> 2);
    float* Or0 = O1 + ((size_t)(b * SQc) + row0) * Dc + h * DHc + cq;
    float* Or1 = Or0 + (size_t)8 * Dc;
    #pragma unroll
    for (int dt = 0; dt < 8; dt++) {
        float2 v0 = make_float2(o[dt][0] * i0, o[dt][1] * i0);
        float2 v1 = make_float2(o[dt][2] * i1, o[dt][3] * i1);
        *(float2*)(Or0 + dt * 8) = v0;
        *(float2*)(Or1 + dt * 8) = v1;
    }
}

// ---------------- final LayerNorm over (O1 + O2s) -------------------------------
__global__ __launch_bounds__(256) void final_ln_kernel(const float* __restrict__ O1,
                                                       const float* __restrict__ O2s,
                                                       const float* __restrict__ g,
                                                       const float* __restrict__ b,
                                                       float* __restrict__ out) {
    int row = blockIdx.x;
    int t = threadIdx.x;
    size_t base = (size_t)row * Dc;
    float4 o1 = ((const float4*)(O1  + base))[t];
    float4 o2 = ((const float4*)(O2s + base))[t];
    float4 v;
    v.x = o1.x + o2.x;
    v.y = o1.y + o2.y;
    v.z = o1.z + o2.z;
    v.w = o1.w + o2.w;
    float s  = v.x + v.y + v.z + v.w;
    float ss = v.x*v.x + v.y*v.y + v.z*v.z + v.w*v.w;
    #pragma unroll
    for (int o = 16; o > 0; o >>= 1) {
        s  += __shfl_xor_sync(0xffffffffu, s,  o);
        ss += __shfl_xor_sync(0xffffffffu, ss, o);
    }
    __shared__ float red[2][8];
    int w = t >> 5, l = t & 31;
    if (l == 0) { red[0][w] = s; red[1][w] = ss; }
    __syncthreads();
    float st = 0.f, sst = 0.f;
    #pragma unroll
    for (int i = 0; i < 8; i++) { st += red[0][i]; sst += red[1][i]; }
    float mean = st * (1.0f / Dc);
    float var  = sst * (1.0f / Dc) - mean * mean;
    float rstd = rsqrtf(var + 1e-5f);
    float4 gg = ((const float4*)g)[t];
    float4 bb = ((const float4*)b)[t];
    float4 o;
    o.x = (v.x - mean) * rstd * gg.x + bb.x;
    o.y = (v.y - mean) * rstd * gg.y + bb.y;
    o.z = (v.z - mean) * rstd * gg.z + bb.z;
    o.w = (v.w - mean) * rstd * gg.w + bb.w;
    ((float4*)(out + base))[t] = o;
}

// ---------------- launch -------------------------------------------------------
extern "C" void kernel_launch(void* const* d_in, const int* in_sizes, int n_in,
                              void* d_out, int out_size) {
    const float* Q       = (const float*)d_in[0];
    const float* K       = (const float*)d_in[1];
    const int*   padm    = (const int*)d_in[2];
    const float* Wq      = (const float*)d_in[3];
    const float* Wk      = (const float*)d_in[4];
    const float* Wv      = (const float*)d_in[5];
    const float* Wo      = (const float*)d_in[6];
    const float* bq      = (const float*)d_in[7];
    const float* bk      = (const float*)d_in[8];
    const float* bv      = (const float*)d_in[9];
    const float* bo      = (const float*)d_in[10];
    const float* ln_q_g  = (const float*)d_in[11];
    const float* ln_q_b  = (const float*)d_in[12];
    const float* ln_kv_g = (const float*)d_in[13];
    const float* ln_kv_b = (const float*)d_in[14];
    const float* ln_f_g  = (const float*)d_in[15];
    const float* ln_f_b  = (const float*)d_in[16];
    float* out = (float*)d_out;

    bf16 *pQh, *pKh, *pWqh, *pWkh, *pWvh, *pQ1b, *pK1b, *pV1b;
    float *pQn, *pO1, *pO2;
    int *pPos, *pCmask, *pCnt;
    cudaGetSymbolAddress((void**)&pQh, g_Qh);
    cudaGetSymbolAddress((void**)&pQn, g_Qn);
    cudaGetSymbolAddress((void**)&pKh, g_Kh);
    cudaGetSymbolAddress((void**)&pWqh, g_Wqh);
    cudaGetSymbolAddress((void**)&pWkh, g_Wkh);
    cudaGetSymbolAddress((void**)&pWvh, g_Wvh);
    cudaGetSymbolAddress((void**)&pQ1b, g_Q1b);
    cudaGetSymbolAddress((void**)&pK1b, g_K1b);
    cudaGetSymbolAddress((void**)&pV1b, g_V1b);
    cudaGetSymbolAddress((void**)&pO1, g_O1);
    cudaGetSymbolAddress((void**)&pO2, g_O2);
    cudaGetSymbolAddress((void**)&pPos, g_pos);
    cudaGetSymbolAddress((void**)&pCmask, g_cmask);
    cudaGetSymbolAddress((void**)&pCnt, g_cnt);

    cudaFuncSetAttribute(gemm_single_kernel, cudaFuncAttributeMaxDynamicSharedMemorySize, 2*GS2);
    cudaFuncSetAttribute(gemm_wo_tf32_kernel, cudaFuncAttributeMaxDynamicSharedMemorySize, WSMEM);
    cudaFuncSetAttribute(attn_mma_kernel, cudaFuncAttributeMaxDynamicSharedMemorySize, ASMEM);

    prefix_kernel<<<Bc, 1024>>>(padm, pPos, pCmask, pCnt, pKh);
    ln_q_kernel<<<NTOK, 256>>>(Q, ln_q_g, ln_q_b, pQh, pQn);
    ln_k_compact_kernel<<<NTOK, 256>>>(K, ln_kv_g, ln_kv_b, padm, pPos, pKh);
    wconv3_kernel<<<3072, 256>>>(Wq, Wk, Wv, pWqh, pWkh, pWvh);

    dim3 gs(Dc / 128, NTOK / 128, 3);    // (8, 32, 3)
    gemm_single_kernel<<<gs, 256, 2*GS2>>>(pQh, pKh, pWqh, pWkh, pWvh,
                                           bq, bk, bv, pCnt, pQ1b, pK1b, pV1b);

    dim3 gw(Dc / 128, NTOK / 128);       // (8, 32)
    gemm_wo_tf32_kernel<<<gw, 256, WSMEM>>>(pQn, Wo, bo, Q, pO2);

    dim3 agrid(SQc / 128, Hc, Bc);       // (16, 16, 2)
    attn_mma_kernel<<<agrid, 256, ASMEM>>>(pQ1b, pK1b, pV1b, pCmask, pCnt, pO1);

    final_ln_kernel<<<NTOK, 256>>>(pO1, pO2, ln_f_g, ln_f_b, out);
}

// round 12
// speedup vs baseline: 15.3233x; 1.0898x over previous
#include <cuda_runtime.h>
#include <cuda_bf16.h>
#include <cstdint>
#include <math.h>

#define Bc  2
#define SQc 2048
#define SKc 2048
#define Dc  1024
#define Hc  16
#define DHc 64
#define NTOK (Bc*SQc)
#define ELEMS (Bc*SQc*Dc)

typedef __nv_bfloat16 bf16;

// ---------------- scratch (static device arrays; no allocation) ----------------
__device__ bf16    g_Qh[ELEMS];                // LN(Q) bf16 (Q1 projection input)
__device__ float   g_Qn[ELEMS];                // LN(Q) fp32 (Wo tf32 path input)
__device__ bf16    g_Kh[ELEMS];                // LN(K), compacted per batch
__device__ bf16    g_Wqh[Dc*Dc], g_Wkh[Dc*Dc], g_Wvh[Dc*Dc];
__device__ uint8_t g_Q1f8[ELEMS], g_K1f8[ELEMS];  // Q/K projections (e4m3, x16 scale)
__device__ bf16    g_V1b[ELEMS];               // V projection (bf16)
__device__ float   g_O1[ELEMS];                // attention output
__device__ float   g_O2[ELEMS];                // Q + relu(Qn @ Wo^T + bo)
__device__ int     g_pos[NTOK];
__device__ int     g_cmask[NTOK];
__device__ int     g_cnt[Bc];

// ---------------- PTX helpers ---------------------------------------------------
__device__ __forceinline__ uint32_t smem_u32(const void* p) {
    uint32_t a;
    asm("{ .reg .u64 t; cvta.to.shared.u64 t, %1; cvt.u32.u64 %0, t; }" : "=r"(a) : "l"(p));
    return a;
}
__device__ __forceinline__ void cpa16(uint32_t saddr, const void* g) {
    asm volatile("cp.async.cg.shared.global [%0], [%1], 16;" :: "r"(saddr), "l"(g) : "memory");
}
__device__ __forceinline__ void cp_commit() {
    asm volatile("cp.async.commit_group;" ::: "memory");
}
template<int N> __device__ __forceinline__ void cp_wait() {
    asm volatile("cp.async.wait_group %0;" :: "n"(N) : "memory");
}
__device__ __forceinline__ void ldm4(uint32_t* r, uint32_t a) {
    asm volatile("ldmatrix.sync.aligned.m8n8.x4.shared.b16 {%0,%1,%2,%3}, [%4];"
        : "=r"(r[0]), "=r"(r[1]), "=r"(r[2]), "=r"(r[3]) : "r"(a));
}
__device__ __forceinline__ void ldm4t(uint32_t* r, uint32_t a) {
    asm volatile("ldmatrix.sync.aligned.m8n8.x4.trans.shared.b16 {%0,%1,%2,%3}, [%4];"
        : "=r"(r[0]), "=r"(r[1]), "=r"(r[2]), "=r"(r[3]) : "r"(a));
}
__device__ __forceinline__ void mmabf(float* d, const uint32_t* a, const uint32_t* b) {
    asm volatile("mma.sync.aligned.m16n8k16.row.col.f32.bf16.bf16.f32 "
        "{%0,%1,%2,%3}, {%4,%5,%6,%7}, {%8,%9}, {%0,%1,%2,%3};"
        : "+f"(d[0]), "+f"(d[1]), "+f"(d[2]), "+f"(d[3])
        : "r"(a[0]), "r"(a[1]), "r"(a[2]), "r"(a[3]), "r"(b[0]), "r"(b[1]));
}
__device__ __forceinline__ void mmaf8(float* d, const uint32_t* a, const uint32_t* b) {
    asm volatile("mma.sync.aligned.m16n8k32.row.col.f32.e4m3.e4m3.f32 "
        "{%0,%1,%2,%3}, {%4,%5,%6,%7}, {%8,%9}, {%0,%1,%2,%3};"
        : "+f"(d[0]), "+f"(d[1]), "+f"(d[2]), "+f"(d[3])
        : "r"(a[0]), "r"(a[1]), "r"(a[2]), "r"(a[3]), "r"(b[0]), "r"(b[1]));
}
__device__ __forceinline__ void mmatf(float* d, const uint32_t* a, uint32_t b0, uint32_t b1) {
    asm volatile("mma.sync.aligned.m16n8k8.row.col.f32.tf32.tf32.f32 "
        "{%0,%1,%2,%3}, {%4,%5,%6,%7}, {%8,%9}, {%0,%1,%2,%3};"
        : "+f"(d[0]), "+f"(d[1]), "+f"(d[2]), "+f"(d[3])
        : "r"(a[0]), "r"(a[1]), "r"(a[2]), "r"(a[3]), "r"(b0), "r"(b1));
}
__device__ __forceinline__ uint32_t cvt_tf32(uint32_t v) {
    uint32_t y; float f = __uint_as_float(v);
    asm("cvt.rna.tf32.f32 %0, %1;" : "=r"(y) : "f"(f));
    return y;
}
__device__ __forceinline__ uint32_t packbf2(float lo, float hi) {
    __nv_bfloat162 t = __floats2bfloat162_rn(lo, hi);
    return *(uint32_t*)&t;
}
__device__ __forceinline__ uint16_t packf8(float lo, float hi) {
    uint16_t r;
    asm("cvt.rn.satfinite.e4m3x2.f32 %0, %1, %2;" : "=h"(r) : "f"(hi), "f"(lo));
    return r;
}

// ---------------- mask prefix + compact-domain mask + pad zeroing ---------------
__global__ __launch_bounds__(1024) void prefix_kernel(const int* __restrict__ mask,
                                                      int* __restrict__ pos,
                                                      int* __restrict__ cmask,
                                                      int* __restrict__ cnt,
                                                      bf16* __restrict__ Knc) {
    int b = blockIdx.x;
    const int* m = mask + b * SKc;
    int t = threadIdx.x;
    int lane = t & 31, w = t >> 5;
    int v0 = m[2 * t], v1 = m[2 * t + 1];
    int s = v0 + v1;
    int sc = s;
    #pragma unroll
    for (int o = 1; o < 32; o <<= 1) {
        int n = __shfl_up_sync(0xffffffffu, sc, o);
        if (lane >= o) sc += n;
    }
    __shared__ int wt[32];
    if (lane == 31) wt[w] = sc;
    __syncthreads();
    if (w == 0) {
        int x = wt[lane];
        #pragma unroll
        for (int o = 1; o < 32; o <<= 1) {
            int n = __shfl_up_sync(0xffffffffu, x, o);
            if (lane >= o) x += n;
        }
        wt[lane] = x;
    }
    __syncthreads();
    int base = ((w > 0) ? wt[w - 1] : 0) + (sc - s);
    pos[b * SKc + 2 * t]     = base;
    pos[b * SKc + 2 * t + 1] = base + v0;
    int total = wt[31];
    if (t == 0) cnt[b] = total;
    cmask[b * SKc + 2 * t]     = (2 * t     < total) ? 1 : 0;
    cmask[b * SKc + 2 * t + 1] = (2 * t + 1 < total) ? 1 : 0;
    int padN = ((total + 127) >> 7) << 7;
    if (padN > SKc) padN = SKc;
    int nz = (padN - total) * (Dc / 4);
    uint2* dst = (uint2*)(Knc + ((size_t)b * SKc + total) * Dc);
    uint2 z; z.x = 0; z.y = 0;
    for (int i = t; i < nz; i += 1024) dst[i] = z;
}

// ---------------- merged LayerNorm (Q rows + compacted K rows) ------------------
// blocks [0,NTOK): Q (bf16 + fp32 out); [NTOK,2*NTOK): K (compact bf16)
__global__ __launch_bounds__(256) void ln_both_kernel(const float* __restrict__ Qx,
                                                      const float* __restrict__ Kx,
                                                      const float* __restrict__ gq,
                                                      const float* __restrict__ bq,
                                                      const float* __restrict__ gk,
                                                      const float* __restrict__ bk,
                                                      const int* __restrict__ mask,
                                                      const int* __restrict__ pos,
                                                      bf16* __restrict__ Qhi,
                                                      float* __restrict__ Qf32,
                                                      bf16* __restrict__ Khi) {
    int blk = blockIdx.x;
    int isK = (blk >= NTOK);
    int row = isK ? (blk - NTOK) : blk;
    if (isK && !mask[row]) return;
    const float* x = isK ? Kx : Qx;
    const float* g = isK ? gk : gq;
    const float* b = isK ? bk : bq;
    int t = threadIdx.x;
    const float4* xr = (const float4*)(x + (size_t)row * Dc);
    float4 v = xr[t];
    float s  = v.x + v.y + v.z + v.w;
    float ss = v.x*v.x + v.y*v.y + v.z*v.z + v.w*v.w;
    #pragma unroll
    for (int o = 16; o > 0; o >>= 1) {
        s  += __shfl_xor_sync(0xffffffffu, s,  o);
        ss += __shfl_xor_sync(0xffffffffu, ss, o);
    }
    __shared__ float red[2][8];
    int w = t >> 5, l = t & 31;
    if (l == 0) { red[0][w] = s; red[1][w] = ss; }
    __syncthreads();
    float st = 0.f, sst = 0.f;
    #pragma unroll
    for (int i = 0; i < 8; i++) { st += red[0][i]; sst += red[1][i]; }
    float mean = st * (1.0f / Dc);
    float var  = sst * (1.0f / Dc) - mean * mean;
    float rstd = rsqrtf(var + 1e-5f);
    float4 gg = ((const float4*)g)[t];
    float4 bb = ((const float4*)b)[t];
    float4 o;
    o.x = (v.x - mean) * rstd * gg.x + bb.x;
    o.y = (v.y - mean) * rstd * gg.y + bb.y;
    o.z = (v.z - mean) * rstd * gg.z + bb.z;
    o.w = (v.w - mean) * rstd * gg.w + bb.w;
    __nv_bfloat162 hA = __floats2bfloat162_rn(o.x, o.y);
    __nv_bfloat162 hB = __floats2bfloat162_rn(o.z, o.w);
    if (!isK) {
        size_t base = (size_t)row * Dc + t * 4;
        *(float4*)(Qf32 + base) = o;
        *(__nv_bfloat162*)(Qhi + base)     = hA;
        *(__nv_bfloat162*)(Qhi + base + 2) = hB;
    } else {
        int bb_ = row >> 11;
        size_t base = ((size_t)bb_ * SKc + pos[row]) * Dc + t * 4;
        *(__nv_bfloat162*)(Khi + base)     = hA;
        *(__nv_bfloat162*)(Khi + base + 2) = hB;
    }
}

// ---------------- weight conversion (Wq, Wk, Wv -> bf16) ------------------------
__global__ __launch_bounds__(256) void wconv3_kernel(const float* __restrict__ Wq,
                                                     const float* __restrict__ Wk,
                                                     const float* __restrict__ Wv,
                                                     bf16* __restrict__ qh,
                                                     bf16* __restrict__ kh,
                                                     bf16* __restrict__ vh) {
    int m = blockIdx.x >> 10;
    int i = (blockIdx.x & 1023) * 256 + threadIdx.x;
    const float* W = (m == 0) ? Wq : (m == 1) ? Wk : Wv;
    bf16* hi = (m == 0) ? qh : (m == 1) ? kh : vh;
    float4 v = ((const float4*)W)[i];
    __nv_bfloat162 hA = __floats2bfloat162_rn(v.x, v.y);
    __nv_bfloat162 hB = __floats2bfloat162_rn(v.z, v.w);
    size_t base = (size_t)i * 4;
    *(__nv_bfloat162*)(hi + base)     = hA;
    *(__nv_bfloat162*)(hi + base + 2) = hB;
}

// ---------------- unified GEMM launch -------------------------------------------
// grid (8, 32, 4); z=0: O2 = Q + relu(tf32 Qn@Wo^T + bo)   (heavy, schedules first)
//                  z=1: Q1 (bf16 -> e4m3 x16)   z=2: K1 compact (-> e4m3 x16)
//                  z=3: V1 compact (-> bf16)
#define GS2  20480              // bf16: per-stage bytes (A 128x80B + W 128x80B)
#define WSTG 36864              // tf32: per-stage bytes (A 128x144B + W 128x144B)
#define GSMEM (2*WSTG)          // 73728
__global__ __launch_bounds__(256, 2) void gemm_all_kernel(const bf16* __restrict__ Qh,
                                                          const bf16* __restrict__ Kh,
                                                          const float* __restrict__ Qn,
                                                          const float* __restrict__ Wo,
                                                          const bf16* __restrict__ Wqh,
                                                          const bf16* __restrict__ Wkh,
                                                          const bf16* __restrict__ Wvh,
                                                          const float* __restrict__ bq,
                                                          const float* __restrict__ bk,
                                                          const float* __restrict__ bv,
                                                          const float* __restrict__ bo,
                                                          const float* __restrict__ Qres,
                                                          const int* __restrict__ cnt,
                                                          uint8_t* __restrict__ Q1f8,
                                                          uint8_t* __restrict__ K1f8,
                                                          bf16* __restrict__ V1b,
                                                          float* __restrict__ O2) {
    int z = blockIdx.z;
    int m0 = blockIdx.y * 128, n0 = blockIdx.x * 128;
    if (z >= 2) {
        int batch = m0 >> 11;
        int ml = m0 & 2047;
        int padN = ((cnt[batch] + 127) >> 7) << 7;
        if (ml >= padN) return;
    }
    extern __shared__ char sm[];
    uint32_t sb = smem_u32(sm);
    int tid = threadIdx.x, lane = tid & 31, warp = tid >> 5;
    int wm = (warp >> 1) * 32, wn = (warp & 1) * 64;
    int cq = 2 * (lane & 3);

    float acc[2][8][4];
    #pragma unroll
    for (int mt = 0; mt < 2; mt++)
        #pragma unroll
        for (int nt = 0; nt < 8; nt++)
            #pragma unroll
            for (int j = 0; j < 4; j++) acc[mt][nt][j] = 0.f;

    if (z == 0) {
        // ---- tf32 Wo path ----
        const float* Ag = Qn + (size_t)m0 * Dc;
        const float* Wg = Wo + (size_t)n0 * Dc;
        auto ldstage = [&](int st, int k0) {
            uint32_t s0 = sb + st * WSTG;
            #pragma unroll
            for (int i = 0; i < 4; i++) {
                int idx = tid + i * 256;
                int r = idx >> 3, c = idx & 7;
                uint32_t so = r * 144 + c * 16;
                size_t   go = (size_t)r * Dc + k0 + c * 4;
                cpa16(s0 +         so, Ag + go);
                cpa16(s0 + 18432 + so, Wg + go);
            }
        };
        ldstage(0, 0);
        cp_commit();
        uint32_t aoffl = (lane & 15) * 144 + (lane >> 4) * 16;
        uint32_t boffl = ((lane & 7) + ((lane >> 4) << 3)) * 144 + ((lane >> 3) & 1) * 16;
        #pragma unroll 1
        for (int c = 0; c < 32; c++) {
            int st = c & 1;
            if (c + 1 < 32) { ldstage(st ^ 1, (c + 1) * 32); cp_commit(); cp_wait<1>(); }
            else            { cp_wait<0>(); }
            __syncthreads();
            uint32_t SA = sb + st * WSTG;
            #pragma unroll
            for (int ks = 0; ks < 4; ks++) {
                uint32_t ar[2][4];
                #pragma unroll
                for (int mt = 0; mt < 2; mt++) {
                    ldm4(ar[mt], SA + (wm + mt * 16) * 144 + aoffl + ks * 32);
                    #pragma unroll
                    for (int j = 0; j < 4; j++) ar[mt][j] = cvt_tf32(ar[mt][j]);
                }
                #pragma unroll
                for (int np = 0; np < 4; np++) {
                    uint32_t br[4];
                    ldm4(br, SA + 18432 + (wn + np * 16) * 144 + boffl + ks * 32);
                    #pragma unroll
                    for (int j = 0; j < 4; j++) br[j] = cvt_tf32(br[j]);
                    #pragma unroll
                    for (int mt = 0; mt < 2; mt++) {
                        mmatf(acc[mt][2*np],   ar[mt], br[0], br[1]);
                        mmatf(acc[mt][2*np+1], ar[mt], br[2], br[3]);
                    }
                }
            }
            __syncthreads();
        }
        #pragma unroll
        for (int mt = 0; mt < 2; mt++) {
            int row0 = m0 + wm + mt * 16 + (lane >> 2);
            #pragma unroll
            for (int nt = 0; nt < 8; nt++) {
                int col = n0 + wn + nt * 8 + cq;
                float b0 = bo[col], b1 = bo[col + 1];
                float2 q0 = *(const float2*)(Qres + (size_t)row0 * Dc + col);
                float2 q1 = *(const float2*)(Qres + (size_t)(row0 + 8) * Dc + col);
                float2 v0 = make_float2(q0.x + fmaxf(acc[mt][nt][0] + b0, 0.f),
                                        q0.y + fmaxf(acc[mt][nt][1] + b1, 0.f));
                float2 v1 = make_float2(q1.x + fmaxf(acc[mt][nt][2] + b0, 0.f),
                                        q1.y + fmaxf(acc[mt][nt][3] + b1, 0.f));
                *(float2*)(O2 + (size_t)row0 * Dc + col)       = v0;
                *(float2*)(O2 + (size_t)(row0 + 8) * Dc + col) = v1;
            }
        }
        return;
    }

    // ---- bf16 single-pass projections ----
    const bf16* A  = (z == 1) ? Qh : Kh;
    const bf16* Wh = (z == 1) ? Wqh : (z == 2) ? Wkh : Wvh;
    const float* bias = (z == 1) ? bq : (z == 2) ? bk : bv;
    const bf16* Ahg = A  + (size_t)m0 * Dc;
    const bf16* Whg = Wh + (size_t)n0 * Dc;

    auto ldstage = [&](int st, int k0) {
        uint32_t s0 = sb + st * GS2;
        #pragma unroll
        for (int i = 0; i < 2; i++) {
            int idx = tid + i * 256;
            int r = idx >> 2, c = idx & 3;
            uint32_t so = r * 80 + c * 16;
            size_t   go = (size_t)r * Dc + k0 + c * 8;
            cpa16(s0 +         so, Ahg + go);
            cpa16(s0 + 10240 + so, Whg + go);
        }
    };
    ldstage(0, 0);
    cp_commit();

    int g8 = lane >> 3, r8 = lane & 7;
    uint32_t aoffl = (lane & 15) * 80 + (lane >> 4) * 16;
    uint32_t boffl = ((g8 >> 1) * 8 + r8) * 80 + (g8 & 1) * 16;

    #pragma unroll 1
    for (int c = 0; c < 32; c++) {
        int st = c & 1;
        if (c + 1 < 32) { ldstage(st ^ 1, (c + 1) * 32); cp_commit(); cp_wait<1>(); }
        else            { cp_wait<0>(); }
        __syncthreads();
        uint32_t SA = sb + st * GS2;
        #pragma unroll
        for (int ks = 0; ks < 2; ks++) {
            uint32_t ah[2][4];
            #pragma unroll
            for (int mt = 0; mt < 2; mt++)
                ldm4(ah[mt], SA + (wm + mt * 16) * 80 + aoffl + ks * 32);
            #pragma unroll
            for (int np = 0; np < 4; np++) {
                uint32_t bh[4];
                ldm4(bh, SA + 10240 + (wn + np * 16) * 80 + boffl + ks * 32);
                #pragma unroll
                for (int mt = 0; mt < 2; mt++) {
                    mmabf(acc[mt][2*np],   ah[mt], bh);
                    mmabf(acc[mt][2*np+1], ah[mt], bh + 2);
                }
            }
        }
        __syncthreads();
    }

    #pragma unroll
    for (int mt = 0; mt < 2; mt++) {
        int row0 = m0 + wm + mt * 16 + (lane >> 2);
        #pragma unroll
        for (int nt = 0; nt < 8; nt++) {
            int col = n0 + wn + nt * 8 + cq;
            float b0 = bias[col], b1 = bias[col + 1];
            float c00 = acc[mt][nt][0] + b0, c01 = acc[mt][nt][1] + b1;
            float c10 = acc[mt][nt][2] + b0, c11 = acc[mt][nt][3] + b1;
            if (z == 3) {
                *(uint32_t*)(V1b + (size_t)row0 * Dc + col)       = packbf2(c00, c01);
                *(uint32_t*)(V1b + (size_t)(row0 + 8) * Dc + col) = packbf2(c10, c11);
            } else {
                uint8_t* dst = (z == 1) ? Q1f8 : K1f8;
                *(uint16_t*)(dst + (size_t)row0 * Dc + col)       = packf8(c00 * 16.f, c01 * 16.f);
                *(uint16_t*)(dst + (size_t)(row0 + 8) * Dc + col) = packf8(c10 * 16.f, c11 * 16.f);
            }
        }
    }
}

// ---------------- flash attention: fp8 QK + bf16 PV (compact keys, no-max) ------
// smem: Q 128x80B | K[2] 64x80B | V[2] 64x144B | mask[2] 64 ints
#define AQ_OFF   0
#define AK_OFF   10240
#define AV_OFF   20480
#define AM_OFF   38912
#define ASMEM    39424
__global__ __launch_bounds__(256, 2) void attn_mma_kernel(const uint8_t* __restrict__ Qf8,
                                                          const uint8_t* __restrict__ Kf8,
                                                          const bf16* __restrict__ Vb,
                                                          const int* __restrict__ cmask,
                                                          const int* __restrict__ cnt,
                                                          float* __restrict__ O1) {
    extern __shared__ char sm[];
    uint32_t sb = smem_u32(sm);
    int tid = threadIdx.x, lane = tid & 31, warp = tid >> 5;
    int q0 = blockIdx.x * 128;
    int h  = blockIdx.y;
    int b  = blockIdx.z;
    const uint8_t* Qg = Qf8 + ((size_t)(b * SQc + q0)) * Dc + h * DHc;
    const uint8_t* Kg = Kf8 + ((size_t)b * SKc) * Dc + h * DHc;
    const bf16*    Vg = Vb  + ((size_t)b * SKc) * Dc + h * DHc;
    const int*     mg = cmask + b * SKc;
    int nch = (cnt[b] + 63) >> 6;

    auto ldkv = [&](int st, int k0) {
        // K: 64 rows x 64B (4 chunks/row) = 256 chunks
        {
            int r = tid >> 2, c = tid & 3;
            cpa16(sb + AK_OFF + st * 5120 + r * 80 + c * 16,
                  Kg + (size_t)(k0 + r) * Dc + c * 16);
        }
        // V: 64 rows x 128B (8 chunks/row) = 512 chunks
        #pragma unroll
        for (int i = 0; i < 2; i++) {
            int idx = tid + i * 256;
            int r = idx >> 3, c = idx & 7;
            cpa16(sb + AV_OFF + st * 9216 + r * 144 + c * 16,
                  Vg + (size_t)(k0 + r) * Dc + c * 8);
        }
        if (tid < 16) cpa16(sb + AM_OFF + st * 256 + tid * 16, mg + k0 + tid * 4);
    };

    // Q: 128 rows x 64B (4 chunks/row) = 512 chunks
    #pragma unroll
    for (int i = 0; i < 2; i++) {
        int idx = tid + i * 256;
        int r = idx >> 2, c = idx & 3;
        cpa16(sb + AQ_OFF + r * 80 + c * 16, Qg + (size_t)r * Dc + c * 16);
    }
    ldkv(0, 0);
    cp_commit();

    int m0 = warp * 16;
    int g8 = lane >> 3, r8 = lane & 7;
    int cq = 2 * (lane & 3);
    uint32_t qaddr = sb + AQ_OFF + (m0 + (lane & 15)) * 80 + (lane >> 4) * 16;
    uint32_t klane = ((g8 >> 1) * 8 + r8) * 80 + (g8 & 1) * 16;
    uint32_t vlane = ((g8 & 1) * 8 + r8) * 144 + (g8 >> 1) * 16;
    const float SC2 = 0.03125f / 256.f;   // 1/sqrt(1024) / (16*16 fp8 scale)

    float o[8][4];
    #pragma unroll
    for (int dt = 0; dt < 8; dt++)
        #pragma unroll
        for (int j = 0; j < 4; j++) o[dt][j] = 0.f;
    float ls0 = 0.f, ls1 = 0.f;

    #pragma unroll 1
    for (int c = 0; c < nch; c++) {
        int st = c & 1;
        if (c + 1 < nch) { ldkv(st ^ 1, (c + 1) * 64); cp_commit(); cp_wait<1>(); }
        else             { cp_wait<0>(); }
        __syncthreads();

        uint32_t Kst = sb + AK_OFF + st * 5120 + klane;
        uint32_t Vst = sb + AV_OFF + st * 9216 + vlane;
        const int* mp = (const int*)(sm + AM_OFF + st * 256);

        float s_[8][4];
        #pragma unroll
        for (int nt = 0; nt < 8; nt++)
            #pragma unroll
            for (int j = 0; j < 4; j++) s_[nt][j] = 0.f;
        #pragma unroll
        for (int ks = 0; ks < 2; ks++) {            // k32 fp8 per step, DH=64 -> 2 steps
            uint32_t aq[4];
            ldm4(aq, qaddr + ks * 32);
            #pragma unroll
            for (int np = 0; np < 4; np++) {
                uint32_t bk[4];
                ldm4(bk, Kst + np * 1280 + ks * 32);
                mmaf8(s_[2*np],   aq, bk);
                mmaf8(s_[2*np+1], aq, bk + 2);
            }
        }

        uint32_t pr0[8], pr1[8];
        #pragma unroll
        for (int nt = 0; nt < 8; nt++) {
            float f0 = (float)mp[nt * 8 + cq];
            float f1 = (float)mp[nt * 8 + cq + 1];
            float p0 = __expf(s_[nt][0] * SC2) * f0;
            float p1 = __expf(s_[nt][1] * SC2) * f1;
            float p2 = __expf(s_[nt][2] * SC2) * f0;
            float p3 = __expf(s_[nt][3] * SC2) * f1;
            ls0 += p0 + p1;
            ls1 += p2 + p3;
            pr0[nt] = packbf2(p0, p1);
            pr1[nt] = packbf2(p2, p3);
        }

        #pragma unroll
        for (int ks2 = 0; ks2 < 4; ks2++) {
            uint32_t pf[4] = { pr0[2*ks2], pr1[2*ks2], pr0[2*ks2+1], pr1[2*ks2+1] };
            #pragma unroll
            for (int dp = 0; dp < 4; dp++) {
                uint32_t bv[4];
                ldm4t(bv, Vst + ks2 * 2304 + dp * 32);
                mmabf(o[2*dp],   pf, bv);
                mmabf(o[2*dp+1], pf, bv + 2);
            }
        }
        __syncthreads();
    }

    ls0 += __shfl_xor_sync(0xffffffffu, ls0, 1);
    ls0 += __shfl_xor_sync(0xffffffffu, ls0, 2);
    ls1 += __shfl_xor_sync(0xffffffffu, ls1, 1);
    ls1 += __shfl_xor_sync(0xffffffffu, ls1, 2);
    float i0 = 1.f / ls0, i1 = 1.f / ls1;
    int row0 = q0 + m0 + (lane >> 2);
    float* Or0 = O1 + ((size_t)(b * SQc) + row0) * Dc + h * DHc + cq;
    float* Or1 = Or0 + (size_t)8 * Dc;
    #pragma unroll
    for (int dt = 0; dt < 8; dt++) {
        float2 v0 = make_float2(o[dt][0] * i0, o[dt][1] * i0);
        float2 v1 = make_float2(o[dt][2] * i1, o[dt][3] * i1);
        *(float2*)(Or0 + dt * 8) = v0;
        *(float2*)(Or1 + dt * 8) = v1;
    }
}

// ---------------- final LayerNorm over (O1 + O2s) -------------------------------
__global__ __launch_bounds__(256) void final_ln_kernel(const float* __restrict__ O1,
                                                       const float* __restrict__ O2s,
                                                       const float* __restrict__ g,
                                                       const float* __restrict__ b,
                                                       float* __restrict__ out) {
    int row = blockIdx.x;
    int t = threadIdx.x;
    size_t base = (size_t)row * Dc;
    float4 o1 = ((const float4*)(O1  + base))[t];
    float4 o2 = ((const float4*)(O2s + base))[t];
    float4 v;
    v.x = o1.x + o2.x;
    v.y = o1.y + o2.y;
    v.z = o1.z + o2.z;
    v.w = o1.w + o2.w;
    float s  = v.x + v.y + v.z + v.w;
    float ss = v.x*v.x + v.y*v.y + v.z*v.z + v.w*v.w;
    #pragma unroll
    for (int o = 16; o > 0; o >>= 1) {
        s  += __shfl_xor_sync(0xffffffffu, s,  o);
        ss += __shfl_xor_sync(0xffffffffu, ss, o);
    }
    __shared__ float red[2][8];
    int w = t >> 5, l = t & 31;
    if (l == 0) { red[0][w] = s; red[1][w] = ss; }
    __syncthreads();
    float st = 0.f, sst = 0.f;
    #pragma unroll
    for (int i = 0; i < 8; i++) { st += red[0][i]; sst += red[1][i]; }
    float mean = st * (1.0f / Dc);
    float var  = sst * (1.0f / Dc) - mean * mean;
    float rstd = rsqrtf(var + 1e-5f);
    float4 gg = ((const float4*)g)[t];
    float4 bb = ((const float4*)b)[t];
    float4 o;
    o.x = (v.x - mean) * rstd * gg.x + bb.x;
    o.y = (v.y - mean) * rstd * gg.y + bb.y;
    o.z = (v.z - mean) * rstd * gg.z + bb.z;
    o.w = (v.w - mean) * rstd * gg.w + bb.w;
    ((float4*)(out + base))[t] = o;
}

// ---------------- launch -------------------------------------------------------
extern "C" void kernel_launch(void* const* d_in, const int* in_sizes, int n_in,
                              void* d_out, int out_size) {
    const float* Q       = (const float*)d_in[0];
    const float* K       = (const float*)d_in[1];
    const int*   padm    = (const int*)d_in[2];
    const float* Wq      = (const float*)d_in[3];
    const float* Wk      = (const float*)d_in[4];
    const float* Wv      = (const float*)d_in[5];
    const float* Wo      = (const float*)d_in[6];
    const float* bq      = (const float*)d_in[7];
    const float* bk      = (const float*)d_in[8];
    const float* bv      = (const float*)d_in[9];
    const float* bo      = (const float*)d_in[10];
    const float* ln_q_g  = (const float*)d_in[11];
    const float* ln_q_b  = (const float*)d_in[12];
    const float* ln_kv_g = (const float*)d_in[13];
    const float* ln_kv_b = (const float*)d_in[14];
    const float* ln_f_g  = (const float*)d_in[15];
    const float* ln_f_b  = (const float*)d_in[16];
    float* out = (float*)d_out;

    bf16 *pQh, *pKh, *pWqh, *pWkh, *pWvh, *pV1b;
    uint8_t *pQ1f8, *pK1f8;
    float *pQn, *pO1, *pO2;
    int *pPos, *pCmask, *pCnt;
    cudaGetSymbolAddress((void**)&pQh, g_Qh);
    cudaGetSymbolAddress((void**)&pQn, g_Qn);
    cudaGetSymbolAddress((void**)&pKh, g_Kh);
    cudaGetSymbolAddress((void**)&pWqh, g_Wqh);
    cudaGetSymbolAddress((void**)&pWkh, g_Wkh);
    cudaGetSymbolAddress((void**)&pWvh, g_Wvh);
    cudaGetSymbolAddress((void**)&pQ1f8, g_Q1f8);
    cudaGetSymbolAddress((void**)&pK1f8, g_K1f8);
    cudaGetSymbolAddress((void**)&pV1b, g_V1b);
    cudaGetSymbolAddress((void**)&pO1, g_O1);
    cudaGetSymbolAddress((void**)&pO2, g_O2);
    cudaGetSymbolAddress((void**)&pPos, g_pos);
    cudaGetSymbolAddress((void**)&pCmask, g_cmask);
    cudaGetSymbolAddress((void**)&pCnt, g_cnt);

    cudaFuncSetAttribute(gemm_all_kernel, cudaFuncAttributeMaxDynamicSharedMemorySize, GSMEM);
    cudaFuncSetAttribute(attn_mma_kernel, cudaFuncAttributeMaxDynamicSharedMemorySize, ASMEM);

    prefix_kernel<<<Bc, 1024>>>(padm, pPos, pCmask, pCnt, pKh);
    ln_both_kernel<<<2 * NTOK, 256>>>(Q, K, ln_q_g, ln_q_b, ln_kv_g, ln_kv_b,
                                      padm, pPos, pQh, pQn, pKh);
    wconv3_kernel<<<3072, 256>>>(Wq, Wk, Wv, pWqh, pWkh, pWvh);

    dim3 ggrid(Dc / 128, NTOK / 128, 4);   // (8, 32, 4)
    gemm_all_kernel<<<ggrid, 256, GSMEM>>>(pQh, pKh, pQn, Wo,
                                           pWqh, pWkh, pWvh,
                                           bq, bk, bv, bo, Q, pCnt,
                                           pQ1f8, pK1f8, pV1b, pO2);

    dim3 agrid(SQc / 128, Hc, Bc);         // (16, 16, 2)
    attn_mma_kernel<<<agrid, 256, ASMEM>>>(pQ1f8, pK1f8, pV1b, pCmask, pCnt, pO1);

    final_ln_kernel<<<NTOK, 256>>>(pO1, pO2, ln_f_g, ln_f_b, out);
}

// round 13
// speedup vs baseline: 15.3976x; 1.0049x over previous
#include <cuda_runtime.h>
#include <cuda_bf16.h>
#include <cstdint>
#include <math.h>

#define Bc  2
#define SQc 2048
#define SKc 2048
#define Dc  1024
#define Hc  16
#define DHc 64
#define NTOK (Bc*SQc)
#define ELEMS (Bc*SQc*Dc)

typedef __nv_bfloat16 bf16;

// ---------------- scratch (static device arrays; no allocation) ----------------
__device__ bf16    g_Qh[ELEMS];                // LN(Q) bf16 (Q1 projection input)
__device__ float   g_Qn[ELEMS];                // LN(Q) fp32, tf32-pre-rounded
__device__ bf16    g_Kh[ELEMS];                // LN(K), compacted per batch
__device__ bf16    g_Wqh[Dc*Dc], g_Wkh[Dc*Dc], g_Wvh[Dc*Dc];
__device__ float   g_Wot[Dc*Dc];               // Wo, tf32-pre-rounded fp32
__device__ uint8_t g_Q1f8[ELEMS], g_K1f8[ELEMS];  // Q/K projections (e4m3, x16 scale)
__device__ bf16    g_V1b[ELEMS];               // V projection (bf16)
__device__ bf16    g_O1[ELEMS];                // attention output (bf16)
__device__ float   g_O2[ELEMS];                // Q + relu(Qn @ Wo^T + bo)
__device__ int     g_pos[NTOK];
__device__ int     g_cmask[NTOK];
__device__ int     g_cnt[Bc];

// ---------------- PTX helpers ---------------------------------------------------
__device__ __forceinline__ uint32_t smem_u32(const void* p) {
    uint32_t a;
    asm("{ .reg .u64 t; cvta.to.shared.u64 t, %1; cvt.u32.u64 %0, t; }" : "=r"(a) : "l"(p));
    return a;
}
__device__ __forceinline__ void cpa16(uint32_t saddr, const void* g) {
    asm volatile("cp.async.cg.shared.global [%0], [%1], 16;" :: "r"(saddr), "l"(g) : "memory");
}
__device__ __forceinline__ void cp_commit() {
    asm volatile("cp.async.commit_group;" ::: "memory");
}
template<int N> __device__ __forceinline__ void cp_wait() {
    asm volatile("cp.async.wait_group %0;" :: "n"(N) : "memory");
}
__device__ __forceinline__ void ldm4(uint32_t* r, uint32_t a) {
    asm volatile("ldmatrix.sync.aligned.m8n8.x4.shared.b16 {%0,%1,%2,%3}, [%4];"
        : "=r"(r[0]), "=r"(r[1]), "=r"(r[2]), "=r"(r[3]) : "r"(a));
}
__device__ __forceinline__ void ldm4t(uint32_t* r, uint32_t a) {
    asm volatile("ldmatrix.sync.aligned.m8n8.x4.trans.shared.b16 {%0,%1,%2,%3}, [%4];"
        : "=r"(r[0]), "=r"(r[1]), "=r"(r[2]), "=r"(r[3]) : "r"(a));
}
__device__ __forceinline__ void mmabf(float* d, const uint32_t* a, const uint32_t* b) {
    asm volatile("mma.sync.aligned.m16n8k16.row.col.f32.bf16.bf16.f32 "
        "{%0,%1,%2,%3}, {%4,%5,%6,%7}, {%8,%9}, {%0,%1,%2,%3};"
        : "+f"(d[0]), "+f"(d[1]), "+f"(d[2]), "+f"(d[3])
        : "r"(a[0]), "r"(a[1]), "r"(a[2]), "r"(a[3]), "r"(b[0]), "r"(b[1]));
}
__device__ __forceinline__ void mmaf8(float* d, const uint32_t* a, const uint32_t* b) {
    asm volatile("mma.sync.aligned.m16n8k32.row.col.f32.e4m3.e4m3.f32 "
        "{%0,%1,%2,%3}, {%4,%5,%6,%7}, {%8,%9}, {%0,%1,%2,%3};"
        : "+f"(d[0]), "+f"(d[1]), "+f"(d[2]), "+f"(d[3])
        : "r"(a[0]), "r"(a[1]), "r"(a[2]), "r"(a[3]), "r"(b[0]), "r"(b[1]));
}
__device__ __forceinline__ void mmatf(float* d, const uint32_t* a, uint32_t b0, uint32_t b1) {
    asm volatile("mma.sync.aligned.m16n8k8.row.col.f32.tf32.tf32.f32 "
        "{%0,%1,%2,%3}, {%4,%5,%6,%7}, {%8,%9}, {%0,%1,%2,%3};"
        : "+f"(d[0]), "+f"(d[1]), "+f"(d[2]), "+f"(d[3])
        : "r"(a[0]), "r"(a[1]), "r"(a[2]), "r"(a[3]), "r"(b0), "r"(b1));
}
__device__ __forceinline__ float round_tf32(float f) {
    uint32_t y;
    asm("cvt.rna.tf32.f32 %0, %1;" : "=r"(y) : "f"(f));
    return __uint_as_float(y);
}
__device__ __forceinline__ uint32_t packbf2(float lo, float hi) {
    __nv_bfloat162 t = __floats2bfloat162_rn(lo, hi);
    return *(uint32_t*)&t;
}
__device__ __forceinline__ uint16_t packf8(float lo, float hi) {
    uint16_t r;
    asm("cvt.rn.satfinite.e4m3x2.f32 %0, %1, %2;" : "=h"(r) : "f"(hi), "f"(lo));
    return r;
}

// ---------------- mask prefix + compact-domain mask + pad zeroing ---------------
__global__ __launch_bounds__(1024) void prefix_kernel(const int* __restrict__ mask,
                                                      int* __restrict__ pos,
                                                      int* __restrict__ cmask,
                                                      int* __restrict__ cnt,
                                                      bf16* __restrict__ Knc) {
    int b = blockIdx.x;
    const int* m = mask + b * SKc;
    int t = threadIdx.x;
    int lane = t & 31, w = t >> 5;
    int v0 = m[2 * t], v1 = m[2 * t + 1];
    int s = v0 + v1;
    int sc = s;
    #pragma unroll
    for (int o = 1; o < 32; o <<= 1) {
        int n = __shfl_up_sync(0xffffffffu, sc, o);
        if (lane >= o) sc += n;
    }
    __shared__ int wt[32];
    if (lane == 31) wt[w] = sc;
    __syncthreads();
    if (w == 0) {
        int x = wt[lane];
        #pragma unroll
        for (int o = 1; o < 32; o <<= 1) {
            int n = __shfl_up_sync(0xffffffffu, x, o);
            if (lane >= o) x += n;
        }
        wt[lane] = x;
    }
    __syncthreads();
    int base = ((w > 0) ? wt[w - 1] : 0) + (sc - s);
    pos[b * SKc + 2 * t]     = base;
    pos[b * SKc + 2 * t + 1] = base + v0;
    int total = wt[31];
    if (t == 0) cnt[b] = total;
    cmask[b * SKc + 2 * t]     = (2 * t     < total) ? 1 : 0;
    cmask[b * SKc + 2 * t + 1] = (2 * t + 1 < total) ? 1 : 0;
    int padN = ((total + 127) >> 7) << 7;
    if (padN > SKc) padN = SKc;
    int nz = (padN - total) * (Dc / 4);
    uint2* dst = (uint2*)(Knc + ((size_t)b * SKc + total) * Dc);
    uint2 z; z.x = 0; z.y = 0;
    for (int i = t; i < nz; i += 1024) dst[i] = z;
}

// ---------------- merged LayerNorm (Q rows + compacted K rows) ------------------
__global__ __launch_bounds__(256) void ln_both_kernel(const float* __restrict__ Qx,
                                                      const float* __restrict__ Kx,
                                                      const float* __restrict__ gq,
                                                      const float* __restrict__ bq,
                                                      const float* __restrict__ gk,
                                                      const float* __restrict__ bk,
                                                      const int* __restrict__ mask,
                                                      const int* __restrict__ pos,
                                                      bf16* __restrict__ Qhi,
                                                      float* __restrict__ Qf32,
                                                      bf16* __restrict__ Khi) {
    int blk = blockIdx.x;
    int isK = (blk >= NTOK);
    int row = isK ? (blk - NTOK) : blk;
    if (isK && !mask[row]) return;
    const float* x = isK ? Kx : Qx;
    const float* g = isK ? gk : gq;
    const float* b = isK ? bk : bq;
    int t = threadIdx.x;
    const float4* xr = (const float4*)(x + (size_t)row * Dc);
    float4 v = xr[t];
    float s  = v.x + v.y + v.z + v.w;
    float ss = v.x*v.x + v.y*v.y + v.z*v.z + v.w*v.w;
    #pragma unroll
    for (int o = 16; o > 0; o >>= 1) {
        s  += __shfl_xor_sync(0xffffffffu, s,  o);
        ss += __shfl_xor_sync(0xffffffffu, ss, o);
    }
    __shared__ float red[2][8];
    int w = t >> 5, l = t & 31;
    if (l == 0) { red[0][w] = s; red[1][w] = ss; }
    __syncthreads();
    float st = 0.f, sst = 0.f;
    #pragma unroll
    for (int i = 0; i < 8; i++) { st += red[0][i]; sst += red[1][i]; }
    float mean = st * (1.0f / Dc);
    float var  = sst * (1.0f / Dc) - mean * mean;
    float rstd = rsqrtf(var + 1e-5f);
    float4 gg = ((const float4*)g)[t];
    float4 bb = ((const float4*)b)[t];
    float4 o;
    o.x = (v.x - mean) * rstd * gg.x + bb.x;
    o.y = (v.y - mean) * rstd * gg.y + bb.y;
    o.z = (v.z - mean) * rstd * gg.z + bb.z;
    o.w = (v.w - mean) * rstd * gg.w + bb.w;
    __nv_bfloat162 hA = __floats2bfloat162_rn(o.x, o.y);
    __nv_bfloat162 hB = __floats2bfloat162_rn(o.z, o.w);
    if (!isK) {
        size_t base = (size_t)row * Dc + t * 4;
        float4 r;                                 // tf32-pre-rounded copy for Wo path
        r.x = round_tf32(o.x); r.y = round_tf32(o.y);
        r.z = round_tf32(o.z); r.w = round_tf32(o.w);
        *(float4*)(Qf32 + base) = r;
        *(__nv_bfloat162*)(Qhi + base)     = hA;
        *(__nv_bfloat162*)(Qhi + base + 2) = hB;
    } else {
        int bb_ = row >> 11;
        size_t base = ((size_t)bb_ * SKc + pos[row]) * Dc + t * 4;
        *(__nv_bfloat162*)(Khi + base)     = hA;
        *(__nv_bfloat162*)(Khi + base + 2) = hB;
    }
}

// ---------------- weight conversion: Wq/Wk/Wv -> bf16, Wo -> tf32-rounded fp32 --
__global__ __launch_bounds__(256) void wconv_kernel(const float* __restrict__ Wq,
                                                    const float* __restrict__ Wk,
                                                    const float* __restrict__ Wv,
                                                    const float* __restrict__ Wo,
                                                    bf16* __restrict__ qh,
                                                    bf16* __restrict__ kh,
                                                    bf16* __restrict__ vh,
                                                    float* __restrict__ ot) {
    int m = blockIdx.x >> 10;
    int i = (blockIdx.x & 1023) * 256 + threadIdx.x;
    size_t base = (size_t)i * 4;
    if (m == 3) {
        float4 v = ((const float4*)Wo)[i];
        float4 r;
        r.x = round_tf32(v.x); r.y = round_tf32(v.y);
        r.z = round_tf32(v.z); r.w = round_tf32(v.w);
        *(float4*)(ot + base) = r;
        return;
    }
    const float* W = (m == 0) ? Wq : (m == 1) ? Wk : Wv;
    bf16* hi = (m == 0) ? qh : (m == 1) ? kh : vh;
    float4 v = ((const float4*)W)[i];
    __nv_bfloat162 hA = __floats2bfloat162_rn(v.x, v.y);
    __nv_bfloat162 hB = __floats2bfloat162_rn(v.z, v.w);
    *(__nv_bfloat162*)(hi + base)     = hA;
    *(__nv_bfloat162*)(hi + base + 2) = hB;
}

// ---------------- unified GEMM launch -------------------------------------------
// grid (8, 32, 4); z=0: O2 = Q + relu(tf32 Qn@Wot^T + bo)  (heavy, schedules first)
//                  z=1: Q1 (bf16 -> e4m3 x16)   z=2: K1 compact (-> e4m3 x16)
//                  z=3: V1 compact (-> bf16)
#define GS2  20480
#define WSTG 36864
#define GSMEM (2*WSTG)
__global__ __launch_bounds__(256, 2) void gemm_all_kernel(const bf16* __restrict__ Qh,
                                                          const bf16* __restrict__ Kh,
                                                          const float* __restrict__ Qn,
                                                          const float* __restrict__ Wot,
                                                          const bf16* __restrict__ Wqh,
                                                          const bf16* __restrict__ Wkh,
                                                          const bf16* __restrict__ Wvh,
                                                          const float* __restrict__ bq,
                                                          const float* __restrict__ bk,
                                                          const float* __restrict__ bv,
                                                          const float* __restrict__ bo,
                                                          const float* __restrict__ Qres,
                                                          const int* __restrict__ cnt,
                                                          uint8_t* __restrict__ Q1f8,
                                                          uint8_t* __restrict__ K1f8,
                                                          bf16* __restrict__ V1b,
                                                          float* __restrict__ O2) {
    int z = blockIdx.z;
    int m0 = blockIdx.y * 128, n0 = blockIdx.x * 128;
    if (z >= 2) {
        int batch = m0 >> 11;
        int ml = m0 & 2047;
        int padN = ((cnt[batch] + 127) >> 7) << 7;
        if (ml >= padN) return;
    }
    extern __shared__ char sm[];
    uint32_t sb = smem_u32(sm);
    int tid = threadIdx.x, lane = tid & 31, warp = tid >> 5;
    int wm = (warp >> 1) * 32, wn = (warp & 1) * 64;
    int cq = 2 * (lane & 3);

    float acc[2][8][4];
    #pragma unroll
    for (int mt = 0; mt < 2; mt++)
        #pragma unroll
        for (int nt = 0; nt < 8; nt++)
            #pragma unroll
            for (int j = 0; j < 4; j++) acc[mt][nt][j] = 0.f;

    if (z == 0) {
        // ---- tf32 Wo path (operands pre-rounded; no cvt in the loop) ----
        const float* Ag = Qn  + (size_t)m0 * Dc;
        const float* Wg = Wot + (size_t)n0 * Dc;
        auto ldstage = [&](int st, int k0) {
            uint32_t s0 = sb + st * WSTG;
            #pragma unroll
            for (int i = 0; i < 4; i++) {
                int idx = tid + i * 256;
                int r = idx >> 3, c = idx & 7;
                uint32_t so = r * 144 + c * 16;
                size_t   go = (size_t)r * Dc + k0 + c * 4;
                cpa16(s0 +         so, Ag + go);
                cpa16(s0 + 18432 + so, Wg + go);
            }
        };
        ldstage(0, 0);
        cp_commit();
        uint32_t aoffl = (lane & 15) * 144 + (lane >> 4) * 16;
        uint32_t boffl = ((lane & 7) + ((lane >> 4) << 3)) * 144 + ((lane >> 3) & 1) * 16;
        #pragma unroll 1
        for (int c = 0; c < 32; c++) {
            int st = c & 1;
            if (c + 1 < 32) { ldstage(st ^ 1, (c + 1) * 32); cp_commit(); cp_wait<1>(); }
            else            { cp_wait<0>(); }
            __syncthreads();
            uint32_t SA = sb + st * WSTG;
            #pragma unroll
            for (int ks = 0; ks < 4; ks++) {
                uint32_t ar[2][4];
                #pragma unroll
                for (int mt = 0; mt < 2; mt++)
                    ldm4(ar[mt], SA + (wm + mt * 16) * 144 + aoffl + ks * 32);
                #pragma unroll
                for (int np = 0; np < 4; np++) {
                    uint32_t br[4];
                    ldm4(br, SA + 18432 + (wn + np * 16) * 144 + boffl + ks * 32);
                    #pragma unroll
                    for (int mt = 0; mt < 2; mt++) {
                        mmatf(acc[mt][2*np],   ar[mt], br[0], br[1]);
                        mmatf(acc[mt][2*np+1], ar[mt], br[2], br[3]);
                    }
                }
            }
            __syncthreads();
        }
        #pragma unroll
        for (int mt = 0; mt < 2; mt++) {
            int row0 = m0 + wm + mt * 16 + (lane >> 2);
            #pragma unroll
            for (int nt = 0; nt < 8; nt++) {
                int col = n0 + wn + nt * 8 + cq;
                float b0 = bo[col], b1 = bo[col + 1];
                float2 q0 = *(const float2*)(Qres + (size_t)row0 * Dc + col);
                float2 q1 = *(const float2*)(Qres + (size_t)(row0 + 8) * Dc + col);
                float2 v0 = make_float2(q0.x + fmaxf(acc[mt][nt][0] + b0, 0.f),
                                        q0.y + fmaxf(acc[mt][nt][1] + b1, 0.f));
                float2 v1 = make_float2(q1.x + fmaxf(acc[mt][nt][2] + b0, 0.f),
                                        q1.y + fmaxf(acc[mt][nt][3] + b1, 0.f));
                *(float2*)(O2 + (size_t)row0 * Dc + col)       = v0;
                *(float2*)(O2 + (size_t)(row0 + 8) * Dc + col) = v1;
            }
        }
        return;
    }

    // ---- bf16 single-pass projections ----
    const bf16* A  = (z == 1) ? Qh : Kh;
    const bf16* Wh = (z == 1) ? Wqh : (z == 2) ? Wkh : Wvh;
    const float* bias = (z == 1) ? bq : (z == 2) ? bk : bv;
    const bf16* Ahg = A  + (size_t)m0 * Dc;
    const bf16* Whg = Wh + (size_t)n0 * Dc;

    auto ldstage = [&](int st, int k0) {
        uint32_t s0 = sb + st * GS2;
        #pragma unroll
        for (int i = 0; i < 2; i++) {
            int idx = tid + i * 256;
            int r = idx >> 2, c = idx & 3;
            uint32_t so = r * 80 + c * 16;
            size_t   go = (size_t)r * Dc + k0 + c * 8;
            cpa16(s0 +         so, Ahg + go);
            cpa16(s0 + 10240 + so, Whg + go);
        }
    };
    ldstage(0, 0);
    cp_commit();

    int g8 = lane >> 3, r8 = lane & 7;
    uint32_t aoffl = (lane & 15) * 80 + (lane >> 4) * 16;
    uint32_t boffl = ((g8 >> 1) * 8 + r8) * 80 + (g8 & 1) * 16;

    #pragma unroll 1
    for (int c = 0; c < 32; c++) {
        int st = c & 1;
        if (c + 1 < 32) { ldstage(st ^ 1, (c + 1) * 32); cp_commit(); cp_wait<1>(); }
        else            { cp_wait<0>(); }
        __syncthreads();
        uint32_t SA = sb + st * GS2;
        #pragma unroll
        for (int ks = 0; ks < 2; ks++) {
            uint32_t ah[2][4];
            #pragma unroll
            for (int mt = 0; mt < 2; mt++)
                ldm4(ah[mt], SA + (wm + mt * 16) * 80 + aoffl + ks * 32);
            #pragma unroll
            for (int np = 0; np < 4; np++) {
                uint32_t bh[4];
                ldm4(bh, SA + 10240 + (wn + np * 16) * 80 + boffl + ks * 32);
                #pragma unroll
                for (int mt = 0; mt < 2; mt++) {
                    mmabf(acc[mt][2*np],   ah[mt], bh);
                    mmabf(acc[mt][2*np+1], ah[mt], bh + 2);
                }
            }
        }
        __syncthreads();
    }

    #pragma unroll
    for (int mt = 0; mt < 2; mt++) {
        int row0 = m0 + wm + mt * 16 + (lane >> 2);
        #pragma unroll
        for (int nt = 0; nt < 8; nt++) {
            int col = n0 + wn + nt * 8 + cq;
            float b0 = bias[col], b1 = bias[col + 1];
            float c00 = acc[mt][nt][0] + b0, c01 = acc[mt][nt][1] + b1;
            float c10 = acc[mt][nt][2] + b0, c11 = acc[mt][nt][3] + b1;
            if (z == 3) {
                *(uint32_t*)(V1b + (size_t)row0 * Dc + col)       = packbf2(c00, c01);
                *(uint32_t*)(V1b + (size_t)(row0 + 8) * Dc + col) = packbf2(c10, c11);
            } else {
                uint8_t* dst = (z == 1) ? Q1f8 : K1f8;
                *(uint16_t*)(dst + (size_t)row0 * Dc + col)       = packf8(c00 * 16.f, c01 * 16.f);
                *(uint16_t*)(dst + (size_t)(row0 + 8) * Dc + col) = packf8(c10 * 16.f, c11 * 16.f);
            }
        }
    }
}

// ---------------- flash attention: fp8 QK + bf16 PV (compact keys, no-max) ------
#define AQ_OFF   0
#define AK_OFF   10240
#define AV_OFF   20480
#define AM_OFF   38912
#define ASMEM    39424
__global__ __launch_bounds__(256, 2) void attn_mma_kernel(const uint8_t* __restrict__ Qf8,
                                                          const uint8_t* __restrict__ Kf8,
                                                          const bf16* __restrict__ Vb,
                                                          const int* __restrict__ cmask,
                                                          const int* __restrict__ cnt,
                                                          bf16* __restrict__ O1) {
    extern __shared__ char sm[];
    uint32_t sb = smem_u32(sm);
    int tid = threadIdx.x, lane = tid & 31, warp = tid >> 5;
    int q0 = blockIdx.x * 128;
    int h  = blockIdx.y;
    int b  = blockIdx.z;
    const uint8_t* Qg = Qf8 + ((size_t)(b * SQc + q0)) * Dc + h * DHc;
    const uint8_t* Kg = Kf8 + ((size_t)b * SKc) * Dc + h * DHc;
    const bf16*    Vg = Vb  + ((size_t)b * SKc) * Dc + h * DHc;
    const int*     mg = cmask + b * SKc;
    int nch = (cnt[b] + 63) >> 6;

    auto ldkv = [&](int st, int k0) {
        {
            int r = tid >> 2, c = tid & 3;
            cpa16(sb + AK_OFF + st * 5120 + r * 80 + c * 16,
                  Kg + (size_t)(k0 + r) * Dc + c * 16);
        }
        #pragma unroll
        for (int i = 0; i < 2; i++) {
            int idx = tid + i * 256;
            int r = idx >> 3, c = idx & 7;
            cpa16(sb + AV_OFF + st * 9216 + r * 144 + c * 16,
                  Vg + (size_t)(k0 + r) * Dc + c * 8);
        }
        if (tid < 16) cpa16(sb + AM_OFF + st * 256 + tid * 16, mg + k0 + tid * 4);
    };

    #pragma unroll
    for (int i = 0; i < 2; i++) {
        int idx = tid + i * 256;
        int r = idx >> 2, c = idx & 3;
        cpa16(sb + AQ_OFF + r * 80 + c * 16, Qg + (size_t)r * Dc + c * 16);
    }
    ldkv(0, 0);
    cp_commit();

    int m0 = warp * 16;
    int g8 = lane >> 3, r8 = lane & 7;
    int cq = 2 * (lane & 3);
    uint32_t qaddr = sb + AQ_OFF + (m0 + (lane & 15)) * 80 + (lane >> 4) * 16;
    uint32_t klane = ((g8 >> 1) * 8 + r8) * 80 + (g8 & 1) * 16;
    uint32_t vlane = ((g8 & 1) * 8 + r8) * 144 + (g8 >> 1) * 16;
    const float SC2 = 0.03125f / 256.f;

    float o[8][4];
    #pragma unroll
    for (int dt = 0; dt < 8; dt++)
        #pragma unroll
        for (int j = 0; j < 4; j++) o[dt][j] = 0.f;
    float ls0 = 0.f, ls1 = 0.f;

    #pragma unroll 1
    for (int c = 0; c < nch; c++) {
        int st = c & 1;
        if (c + 1 < nch) { ldkv(st ^ 1, (c + 1) * 64); cp_commit(); cp_wait<1>(); }
        else             { cp_wait<0>(); }
        __syncthreads();

        uint32_t Kst = sb + AK_OFF + st * 5120 + klane;
        uint32_t Vst = sb + AV_OFF + st * 9216 + vlane;
        const int* mp = (const int*)(sm + AM_OFF + st * 256);

        float s_[8][4];
        #pragma unroll
        for (int nt = 0; nt < 8; nt++)
            #pragma unroll
            for (int j = 0; j < 4; j++) s_[nt][j] = 0.f;
        #pragma unroll
        for (int ks = 0; ks < 2; ks++) {
            uint32_t aq[4];
            ldm4(aq, qaddr + ks * 32);
            #pragma unroll
            for (int np = 0; np < 4; np++) {
                uint32_t bk[4];
                ldm4(bk, Kst + np * 1280 + ks * 32);
                mmaf8(s_[2*np],   aq, bk);
                mmaf8(s_[2*np+1], aq, bk + 2);
            }
        }

        uint32_t pr0[8], pr1[8];
        #pragma unroll
        for (int nt = 0; nt < 8; nt++) {
            float f0 = (float)mp[nt * 8 + cq];
            float f1 = (float)mp[nt * 8 + cq + 1];
            float p0 = __expf(s_[nt][0] * SC2) * f0;
            float p1 = __expf(s_[nt][1] * SC2) * f1;
            float p2 = __expf(s_[nt][2] * SC2) * f0;
            float p3 = __expf(s_[nt][3] * SC2) * f1;
            ls0 += p0 + p1;
            ls1 += p2 + p3;
            pr0[nt] = packbf2(p0, p1);
            pr1[nt] = packbf2(p2, p3);
        }

        #pragma unroll
        for (int ks2 = 0; ks2 < 4; ks2++) {
            uint32_t pf[4] = { pr0[2*ks2], pr1[2*ks2], pr0[2*ks2+1], pr1[2*ks2+1] };
            #pragma unroll
            for (int dp = 0; dp < 4; dp++) {
                uint32_t bv[4];
                ldm4t(bv, Vst + ks2 * 2304 + dp * 32);
                mmabf(o[2*dp],   pf, bv);
                mmabf(o[2*dp+1], pf, bv + 2);
            }
        }
        __syncthreads();
    }

    ls0 += __shfl_xor_sync(0xffffffffu, ls0, 1);
    ls0 += __shfl_xor_sync(0xffffffffu, ls0, 2);
    ls1 += __shfl_xor_sync(0xffffffffu, ls1, 1);
    ls1 += __shfl_xor_sync(0xffffffffu, ls1, 2);
    float i0 = 1.f / ls0, i1 = 1.f / ls1;
    int row0 = q0 + m0 + (lane >> 2);
    bf16* Or0 = O1 + ((size_t)(b * SQc) + row0) * Dc + h * DHc + cq;
    bf16* Or1 = Or0 + (size_t)8 * Dc;
    #pragma unroll
    for (int dt = 0; dt < 8; dt++) {
        *(uint32_t*)(Or0 + dt * 8) = packbf2(o[dt][0] * i0, o[dt][1] * i0);
        *(uint32_t*)(Or1 + dt * 8) = packbf2(o[dt][2] * i1, o[dt][3] * i1);
    }
}

// ---------------- final LayerNorm over (bf16 O1 + O2s) --------------------------
__global__ __launch_bounds__(256) void final_ln_kernel(const bf16* __restrict__ O1,
                                                       const float* __restrict__ O2s,
                                                       const float* __restrict__ g,
                                                       const float* __restrict__ b,
                                                       float* __restrict__ out) {
    int row = blockIdx.x;
    int t = threadIdx.x;
    size_t base = (size_t)row * Dc;
    __nv_bfloat162 a0 = *(const __nv_bfloat162*)(O1 + base + t * 4);
    __nv_bfloat162 a1 = *(const __nv_bfloat162*)(O1 + base + t * 4 + 2);
    float4 o2 = ((const float4*)(O2s + base))[t];
    float4 v;
    v.x = __bfloat162float(a0.x) + o2.x;
    v.y = __bfloat162float(a0.y) + o2.y;
    v.z = __bfloat162float(a1.x) + o2.z;
    v.w = __bfloat162float(a1.y) + o2.w;
    float s  = v.x + v.y + v.z + v.w;
    float ss = v.x*v.x + v.y*v.y + v.z*v.z + v.w*v.w;
    #pragma unroll
    for (int o = 16; o > 0; o >>= 1) {
        s  += __shfl_xor_sync(0xffffffffu, s,  o);
        ss += __shfl_xor_sync(0xffffffffu, ss, o);
    }
    __shared__ float red[2][8];
    int w = t >> 5, l = t & 31;
    if (l == 0) { red[0][w] = s; red[1][w] = ss; }
    __syncthreads();
    float st = 0.f, sst = 0.f;
    #pragma unroll
    for (int i = 0; i < 8; i++) { st += red[0][i]; sst += red[1][i]; }
    float mean = st * (1.0f / Dc);
    float var  = sst * (1.0f / Dc) - mean * mean;
    float rstd = rsqrtf(var + 1e-5f);
    float4 gg = ((const float4*)g)[t];
    float4 bb = ((const float4*)b)[t];
    float4 o;
    o.x = (v.x - mean) * rstd * gg.x + bb.x;
    o.y = (v.y - mean) * rstd * gg.y + bb.y;
    o.z = (v.z - mean) * rstd * gg.z + bb.z;
    o.w = (v.w - mean) * rstd * gg.w + bb.w;
    ((float4*)(out + base))[t] = o;
}

// ---------------- launch -------------------------------------------------------
extern "C" void kernel_launch(void* const* d_in, const int* in_sizes, int n_in,
                              void* d_out, int out_size) {
    const float* Q       = (const float*)d_in[0];
    const float* K       = (const float*)d_in[1];
    const int*   padm    = (const int*)d_in[2];
    const float* Wq      = (const float*)d_in[3];
    const float* Wk      = (const float*)d_in[4];
    const float* Wv      = (const float*)d_in[5];
    const float* Wo      = (const float*)d_in[6];
    const float* bq      = (const float*)d_in[7];
    const float* bk      = (const float*)d_in[8];
    const float* bv      = (const float*)d_in[9];
    const float* bo      = (const float*)d_in[10];
    const float* ln_q_g  = (const float*)d_in[11];
    const float* ln_q_b  = (const float*)d_in[12];
    const float* ln_kv_g = (const float*)d_in[13];
    const float* ln_kv_b = (const float*)d_in[14];
    const float* ln_f_g  = (const float*)d_in[15];
    const float* ln_f_b  = (const float*)d_in[16];
    float* out = (float*)d_out;

    bf16 *pQh, *pKh, *pWqh, *pWkh, *pWvh, *pV1b, *pO1;
    uint8_t *pQ1f8, *pK1f8;
    float *pQn, *pWot, *pO2;
    int *pPos, *pCmask, *pCnt;
    cudaGetSymbolAddress((void**)&pQh, g_Qh);
    cudaGetSymbolAddress((void**)&pQn, g_Qn);
    cudaGetSymbolAddress((void**)&pKh, g_Kh);
    cudaGetSymbolAddress((void**)&pWqh, g_Wqh);
    cudaGetSymbolAddress((void**)&pWkh, g_Wkh);
    cudaGetSymbolAddress((void**)&pWvh, g_Wvh);
    cudaGetSymbolAddress((void**)&pWot, g_Wot);
    cudaGetSymbolAddress((void**)&pQ1f8, g_Q1f8);
    cudaGetSymbolAddress((void**)&pK1f8, g_K1f8);
    cudaGetSymbolAddress((void**)&pV1b, g_V1b);
    cudaGetSymbolAddress((void**)&pO1, g_O1);
    cudaGetSymbolAddress((void**)&pO2, g_O2);
    cudaGetSymbolAddress((void**)&pPos, g_pos);
    cudaGetSymbolAddress((void**)&pCmask, g_cmask);
    cudaGetSymbolAddress((void**)&pCnt, g_cnt);

    cudaFuncSetAttribute(gemm_all_kernel, cudaFuncAttributeMaxDynamicSharedMemorySize, GSMEM);
    cudaFuncSetAttribute(attn_mma_kernel, cudaFuncAttributeMaxDynamicSharedMemorySize, ASMEM);

    prefix_kernel<<<Bc, 1024>>>(padm, pPos, pCmask, pCnt, pKh);
    ln_both_kernel<<<2 * NTOK, 256>>>(Q, K, ln_q_g, ln_q_b, ln_kv_g, ln_kv_b,
                                      padm, pPos, pQh, pQn, pKh);
    wconv_kernel<<<4096, 256>>>(Wq, Wk, Wv, Wo, pWqh, pWkh, pWvh, pWot);

    dim3 ggrid(Dc / 128, NTOK / 128, 4);   // (8, 32, 4)
    gemm_all_kernel<<<ggrid, 256, GSMEM>>>(pQh, pKh, pQn, pWot,
                                           pWqh, pWkh, pWvh,
                                           bq, bk, bv, bo, Q, pCnt,
                                           pQ1f8, pK1f8, pV1b, pO2);

    dim3 agrid(SQc / 128, Hc, Bc);         // (16, 16, 2)
    attn_mma_kernel<<<agrid, 256, ASMEM>>>(pQ1f8, pK1f8, pV1b, pCmask, pCnt, pO1);

    final_ln_kernel<<<NTOK, 256>>>(pO1, pO2, ln_f_g, ln_f_b, out);
}

// round 14
// speedup vs baseline: 16.1562x; 1.0493x over previous
#include <cuda_runtime.h>
#include <cuda_bf16.h>
#include <cstdint>
#include <math.h>

#define Bc  2
#define SQc 2048
#define SKc 2048
#define Dc  1024
#define Hc  16
#define DHc 64
#define NTOK (Bc*SQc)
#define ELEMS (Bc*SQc*Dc)

typedef __nv_bfloat16 bf16;

// ---------------- scratch (static device arrays; no allocation) ----------------
__device__ bf16    g_Qh[ELEMS];                // LN(Q) bf16 (Q1 projection input)
__device__ float   g_Qn[ELEMS];                // LN(Q) fp32, tf32-pre-rounded
__device__ bf16    g_Kh[ELEMS];                // LN(K), compacted per batch
__device__ bf16    g_Wqh[Dc*Dc], g_Wkh[Dc*Dc], g_Wvh[Dc*Dc];
__device__ float   g_Wot[Dc*Dc];               // Wo, tf32-pre-rounded fp32
__device__ uint8_t g_Q1f8[ELEMS], g_K1f8[ELEMS];  // Q/K projections (e4m3, x16 scale)
__device__ bf16    g_V1b[ELEMS];               // V projection (bf16)
__device__ bf16    g_O1[ELEMS];                // attention output (bf16)
__device__ float   g_O2[ELEMS];                // Q + relu(Qn @ Wo^T + bo)
__device__ int     g_pos[NTOK];
__device__ int     g_cmask[NTOK];
__device__ int     g_cnt[Bc];

// ---------------- PTX helpers ---------------------------------------------------
__device__ __forceinline__ uint32_t smem_u32(const void* p) {
    uint32_t a;
    asm("{ .reg .u64 t; cvta.to.shared.u64 t, %1; cvt.u32.u64 %0, t; }" : "=r"(a) : "l"(p));
    return a;
}
__device__ __forceinline__ void cpa16(uint32_t saddr, const void* g) {
    asm volatile("cp.async.cg.shared.global [%0], [%1], 16;" :: "r"(saddr), "l"(g) : "memory");
}
__device__ __forceinline__ void cp_commit() {
    asm volatile("cp.async.commit_group;" ::: "memory");
}
template<int N> __device__ __forceinline__ void cp_wait() {
    asm volatile("cp.async.wait_group %0;" :: "n"(N) : "memory");
}
__device__ __forceinline__ void ldm4(uint32_t* r, uint32_t a) {
    asm volatile("ldmatrix.sync.aligned.m8n8.x4.shared.b16 {%0,%1,%2,%3}, [%4];"
        : "=r"(r[0]), "=r"(r[1]), "=r"(r[2]), "=r"(r[3]) : "r"(a));
}
__device__ __forceinline__ void ldm4t(uint32_t* r, uint32_t a) {
    asm volatile("ldmatrix.sync.aligned.m8n8.x4.trans.shared.b16 {%0,%1,%2,%3}, [%4];"
        : "=r"(r[0]), "=r"(r[1]), "=r"(r[2]), "=r"(r[3]) : "r"(a));
}
__device__ __forceinline__ void mmabf(float* d, const uint32_t* a, const uint32_t* b) {
    asm volatile("mma.sync.aligned.m16n8k16.row.col.f32.bf16.bf16.f32 "
        "{%0,%1,%2,%3}, {%4,%5,%6,%7}, {%8,%9}, {%0,%1,%2,%3};"
        : "+f"(d[0]), "+f"(d[1]), "+f"(d[2]), "+f"(d[3])
        : "r"(a[0]), "r"(a[1]), "r"(a[2]), "r"(a[3]), "r"(b[0]), "r"(b[1]));
}
__device__ __forceinline__ void mmaf8(float* d, const uint32_t* a, const uint32_t* b) {
    asm volatile("mma.sync.aligned.m16n8k32.row.col.f32.e4m3.e4m3.f32 "
        "{%0,%1,%2,%3}, {%4,%5,%6,%7}, {%8,%9}, {%0,%1,%2,%3};"
        : "+f"(d[0]), "+f"(d[1]), "+f"(d[2]), "+f"(d[3])
        : "r"(a[0]), "r"(a[1]), "r"(a[2]), "r"(a[3]), "r"(b[0]), "r"(b[1]));
}
__device__ __forceinline__ void mmatf(float* d, const uint32_t* a, uint32_t b0, uint32_t b1) {
    asm volatile("mma.sync.aligned.m16n8k8.row.col.f32.tf32.tf32.f32 "
        "{%0,%1,%2,%3}, {%4,%5,%6,%7}, {%8,%9}, {%0,%1,%2,%3};"
        : "+f"(d[0]), "+f"(d[1]), "+f"(d[2]), "+f"(d[3])
        : "r"(a[0]), "r"(a[1]), "r"(a[2]), "r"(a[3]), "r"(b0), "r"(b1));
}
__device__ __forceinline__ float round_tf32(float f) {
    uint32_t y;
    asm("cvt.rna.tf32.f32 %0, %1;" : "=r"(y) : "f"(f));
    return __uint_as_float(y);
}
__device__ __forceinline__ uint32_t packbf2(float lo, float hi) {
    __nv_bfloat162 t = __floats2bfloat162_rn(lo, hi);
    return *(uint32_t*)&t;
}
__device__ __forceinline__ uint16_t packf8(float lo, float hi) {
    uint16_t r;
    asm("cvt.rn.satfinite.e4m3x2.f32 %0, %1, %2;" : "=h"(r) : "f"(hi), "f"(lo));
    return r;
}

// ---------------- mask prefix + compact-domain mask + pad zeroing ---------------
__global__ __launch_bounds__(1024) void prefix_kernel(const int* __restrict__ mask,
                                                      int* __restrict__ pos,
                                                      int* __restrict__ cmask,
                                                      int* __restrict__ cnt,
                                                      bf16* __restrict__ Knc) {
    int b = blockIdx.x;
    const int* m = mask + b * SKc;
    int t = threadIdx.x;
    int lane = t & 31, w = t >> 5;
    int v0 = m[2 * t], v1 = m[2 * t + 1];
    int s = v0 + v1;
    int sc = s;
    #pragma unroll
    for (int o = 1; o < 32; o <<= 1) {
        int n = __shfl_up_sync(0xffffffffu, sc, o);
        if (lane >= o) sc += n;
    }
    __shared__ int wt[32];
    if (lane == 31) wt[w] = sc;
    __syncthreads();
    if (w == 0) {
        int x = wt[lane];
        #pragma unroll
        for (int o = 1; o < 32; o <<= 1) {
            int n = __shfl_up_sync(0xffffffffu, x, o);
            if (lane >= o) x += n;
        }
        wt[lane] = x;
    }
    __syncthreads();
    int base = ((w > 0) ? wt[w - 1] : 0) + (sc - s);
    pos[b * SKc + 2 * t]     = base;
    pos[b * SKc + 2 * t + 1] = base + v0;
    int total = wt[31];
    if (t == 0) cnt[b] = total;
    cmask[b * SKc + 2 * t]     = (2 * t     < total) ? 1 : 0;
    cmask[b * SKc + 2 * t + 1] = (2 * t + 1 < total) ? 1 : 0;
    int padN = ((total + 127) >> 7) << 7;
    if (padN > SKc) padN = SKc;
    int nz = (padN - total) * (Dc / 4);
    uint2* dst = (uint2*)(Knc + ((size_t)b * SKc + total) * Dc);
    uint2 z; z.x = 0; z.y = 0;
    for (int i = t; i < nz; i += 1024) dst[i] = z;
}

// ---------------- merged LayerNorm (Q rows + compacted K rows) ------------------
__global__ __launch_bounds__(256) void ln_both_kernel(const float* __restrict__ Qx,
                                                      const float* __restrict__ Kx,
                                                      const float* __restrict__ gq,
                                                      const float* __restrict__ bq,
                                                      const float* __restrict__ gk,
                                                      const float* __restrict__ bk,
                                                      const int* __restrict__ mask,
                                                      const int* __restrict__ pos,
                                                      bf16* __restrict__ Qhi,
                                                      float* __restrict__ Qf32,
                                                      bf16* __restrict__ Khi) {
    int blk = blockIdx.x;
    int isK = (blk >= NTOK);
    int row = isK ? (blk - NTOK) : blk;
    if (isK && !mask[row]) return;
    const float* x = isK ? Kx : Qx;
    const float* g = isK ? gk : gq;
    const float* b = isK ? bk : bq;
    int t = threadIdx.x;
    const float4* xr = (const float4*)(x + (size_t)row * Dc);
    float4 v = xr[t];
    float s  = v.x + v.y + v.z + v.w;
    float ss = v.x*v.x + v.y*v.y + v.z*v.z + v.w*v.w;
    #pragma unroll
    for (int o = 16; o > 0; o >>= 1) {
        s  += __shfl_xor_sync(0xffffffffu, s,  o);
        ss += __shfl_xor_sync(0xffffffffu, ss, o);
    }
    __shared__ float red[2][8];
    int w = t >> 5, l = t & 31;
    if (l == 0) { red[0][w] = s; red[1][w] = ss; }
    __syncthreads();
    float st = 0.f, sst = 0.f;
    #pragma unroll
    for (int i = 0; i < 8; i++) { st += red[0][i]; sst += red[1][i]; }
    float mean = st * (1.0f / Dc);
    float var  = sst * (1.0f / Dc) - mean * mean;
    float rstd = rsqrtf(var + 1e-5f);
    float4 gg = ((const float4*)g)[t];
    float4 bb = ((const float4*)b)[t];
    float4 o;
    o.x = (v.x - mean) * rstd * gg.x + bb.x;
    o.y = (v.y - mean) * rstd * gg.y + bb.y;
    o.z = (v.z - mean) * rstd * gg.z + bb.z;
    o.w = (v.w - mean) * rstd * gg.w + bb.w;
    __nv_bfloat162 hA = __floats2bfloat162_rn(o.x, o.y);
    __nv_bfloat162 hB = __floats2bfloat162_rn(o.z, o.w);
    if (!isK) {
        size_t base = (size_t)row * Dc + t * 4;
        float4 r;
        r.x = round_tf32(o.x); r.y = round_tf32(o.y);
        r.z = round_tf32(o.z); r.w = round_tf32(o.w);
        *(float4*)(Qf32 + base) = r;
        *(__nv_bfloat162*)(Qhi + base)     = hA;
        *(__nv_bfloat162*)(Qhi + base + 2) = hB;
    } else {
        int bb_ = row >> 11;
        size_t base = ((size_t)bb_ * SKc + pos[row]) * Dc + t * 4;
        *(__nv_bfloat162*)(Khi + base)     = hA;
        *(__nv_bfloat162*)(Khi + base + 2) = hB;
    }
}

// ---------------- weight conversion: Wq/Wk/Wv -> bf16, Wo -> tf32-rounded fp32 --
__global__ __launch_bounds__(256) void wconv_kernel(const float* __restrict__ Wq,
                                                    const float* __restrict__ Wk,
                                                    const float* __restrict__ Wv,
                                                    const float* __restrict__ Wo,
                                                    bf16* __restrict__ qh,
                                                    bf16* __restrict__ kh,
                                                    bf16* __restrict__ vh,
                                                    float* __restrict__ ot) {
    int m = blockIdx.x >> 10;
    int i = (blockIdx.x & 1023) * 256 + threadIdx.x;
    size_t base = (size_t)i * 4;
    if (m == 3) {
        float4 v = ((const float4*)Wo)[i];
        float4 r;
        r.x = round_tf32(v.x); r.y = round_tf32(v.y);
        r.z = round_tf32(v.z); r.w = round_tf32(v.w);
        *(float4*)(ot + base) = r;
        return;
    }
    const float* W = (m == 0) ? Wq : (m == 1) ? Wk : Wv;
    bf16* hi = (m == 0) ? qh : (m == 1) ? kh : vh;
    float4 v = ((const float4*)W)[i];
    __nv_bfloat162 hA = __floats2bfloat162_rn(v.x, v.y);
    __nv_bfloat162 hB = __floats2bfloat162_rn(v.z, v.w);
    *(__nv_bfloat162*)(hi + base)     = hA;
    *(__nv_bfloat162*)(hi + base + 2) = hB;
}

// ---------------- unified GEMM launch (3-stage pipeline, 1 barrier/chunk) -------
// grid (8, 32, 4); z=0: O2 = Q + relu(tf32 Qn@Wot^T + bo), BK=32, 32 chunks
//                  z=1: Q1 (bf16 -> e4m3 x16), BK=64, 16 chunks
//                  z=2: K1 compact (-> e4m3 x16)   z=3: V1 compact (-> bf16)
// Unified stage: A tile 128 rows x 128B (pitch 144) + W tile same = 36864 B.
#define STG   36864
#define GSMEM (3*STG)
__global__ __launch_bounds__(256, 2) void gemm_all_kernel(const bf16* __restrict__ Qh,
                                                          const bf16* __restrict__ Kh,
                                                          const float* __restrict__ Qn,
                                                          const float* __restrict__ Wot,
                                                          const bf16* __restrict__ Wqh,
                                                          const bf16* __restrict__ Wkh,
                                                          const bf16* __restrict__ Wvh,
                                                          const float* __restrict__ bq,
                                                          const float* __restrict__ bk,
                                                          const float* __restrict__ bv,
                                                          const float* __restrict__ bo,
                                                          const float* __restrict__ Qres,
                                                          const int* __restrict__ cnt,
                                                          uint8_t* __restrict__ Q1f8,
                                                          uint8_t* __restrict__ K1f8,
                                                          bf16* __restrict__ V1b,
                                                          float* __restrict__ O2) {
    int z = blockIdx.z;
    int m0 = blockIdx.y * 128, n0 = blockIdx.x * 128;
    if (z >= 2) {
        int batch = m0 >> 11;
        int ml = m0 & 2047;
        int padN = ((cnt[batch] + 127) >> 7) << 7;
        if (ml >= padN) return;
    }
    extern __shared__ char sm[];
    uint32_t sb = smem_u32(sm);
    int tid = threadIdx.x, lane = tid & 31, warp = tid >> 5;
    int wm = (warp >> 1) * 32, wn = (warp & 1) * 64;
    int cq = 2 * (lane & 3);

    float acc[2][8][4];
    #pragma unroll
    for (int mt = 0; mt < 2; mt++)
        #pragma unroll
        for (int nt = 0; nt < 8; nt++)
            #pragma unroll
            for (int j = 0; j < 4; j++) acc[mt][nt][j] = 0.f;

    if (z == 0) {
        // ---- tf32 Wo path: BK=32 (row 128B), 32 chunks ----
        const float* Ag = Qn  + (size_t)m0 * Dc;
        const float* Wg = Wot + (size_t)n0 * Dc;
        auto ldstage = [&](int st, int k0) {
            uint32_t s0 = sb + st * STG;
            #pragma unroll
            for (int i = 0; i < 4; i++) {
                int idx = tid + i * 256;
                int r = idx >> 3, c = idx & 7;
                uint32_t so = r * 144 + c * 16;
                size_t   go = (size_t)r * Dc + k0 + c * 4;
                cpa16(s0 +         so, Ag + go);
                cpa16(s0 + 18432 + so, Wg + go);
            }
        };
        ldstage(0, 0);  cp_commit();
        ldstage(1, 32); cp_commit();
        uint32_t aoffl = (lane & 15) * 144 + (lane >> 4) * 16;
        uint32_t boffl = ((lane & 7) + ((lane >> 4) << 3)) * 144 + ((lane >> 3) & 1) * 16;
        int st = 0, ld = 2;
        #pragma unroll 1
        for (int c = 0; c < 32; c++) {
            if (c + 1 < 32) cp_wait<1>(); else cp_wait<0>();
            __syncthreads();
            if (c + 2 < 32) { ldstage(ld, (c + 2) * 32); cp_commit(); }
            uint32_t SA = sb + st * STG;
            #pragma unroll
            for (int ks = 0; ks < 4; ks++) {
                uint32_t ar[2][4];
                #pragma unroll
                for (int mt = 0; mt < 2; mt++)
                    ldm4(ar[mt], SA + (wm + mt * 16) * 144 + aoffl + ks * 32);
                #pragma unroll
                for (int np = 0; np < 4; np++) {
                    uint32_t br[4];
                    ldm4(br, SA + 18432 + (wn + np * 16) * 144 + boffl + ks * 32);
                    #pragma unroll
                    for (int mt = 0; mt < 2; mt++) {
                        mmatf(acc[mt][2*np],   ar[mt], br[0], br[1]);
                        mmatf(acc[mt][2*np+1], ar[mt], br[2], br[3]);
                    }
                }
            }
            st = (st == 2) ? 0 : st + 1;
            ld = (ld == 2) ? 0 : ld + 1;
        }
        #pragma unroll
        for (int mt = 0; mt < 2; mt++) {
            int row0 = m0 + wm + mt * 16 + (lane >> 2);
            #pragma unroll
            for (int nt = 0; nt < 8; nt++) {
                int col = n0 + wn + nt * 8 + cq;
                float b0 = bo[col], b1 = bo[col + 1];
                float2 q0 = *(const float2*)(Qres + (size_t)row0 * Dc + col);
                float2 q1 = *(const float2*)(Qres + (size_t)(row0 + 8) * Dc + col);
                float2 v0 = make_float2(q0.x + fmaxf(acc[mt][nt][0] + b0, 0.f),
                                        q0.y + fmaxf(acc[mt][nt][1] + b1, 0.f));
                float2 v1 = make_float2(q1.x + fmaxf(acc[mt][nt][2] + b0, 0.f),
                                        q1.y + fmaxf(acc[mt][nt][3] + b1, 0.f));
                *(float2*)(O2 + (size_t)row0 * Dc + col)       = v0;
                *(float2*)(O2 + (size_t)(row0 + 8) * Dc + col) = v1;
            }
        }
        return;
    }

    // ---- bf16 single-pass projections: BK=64 (row 128B), 16 chunks ----
    const bf16* A  = (z == 1) ? Qh : Kh;
    const bf16* Wh = (z == 1) ? Wqh : (z == 2) ? Wkh : Wvh;
    const float* bias = (z == 1) ? bq : (z == 2) ? bk : bv;
    const bf16* Ahg = A  + (size_t)m0 * Dc;
    const bf16* Whg = Wh + (size_t)n0 * Dc;

    auto ldstage = [&](int st, int k0) {
        uint32_t s0 = sb + st * STG;
        #pragma unroll
        for (int i = 0; i < 4; i++) {
            int idx = tid + i * 256;
            int r = idx >> 3, c = idx & 7;
            uint32_t so = r * 144 + c * 16;
            size_t   go = (size_t)r * Dc + k0 + c * 8;
            cpa16(s0 +         so, Ahg + go);
            cpa16(s0 + 18432 + so, Whg + go);
        }
    };
    ldstage(0, 0);  cp_commit();
    ldstage(1, 64); cp_commit();

    int g8 = lane >> 3, r8 = lane & 7;
    uint32_t aoffl = (lane & 15) * 144 + (lane >> 4) * 16;
    uint32_t boffl = ((g8 >> 1) * 8 + r8) * 144 + (g8 & 1) * 16;
    int st = 0, ld = 2;

    #pragma unroll 1
    for (int c = 0; c < 16; c++) {
        if (c + 1 < 16) cp_wait<1>(); else cp_wait<0>();
        __syncthreads();
        if (c + 2 < 16) { ldstage(ld, (c + 2) * 64); cp_commit(); }
        uint32_t SA = sb + st * STG;
        #pragma unroll
        for (int ks = 0; ks < 4; ks++) {
            uint32_t ah[2][4];
            #pragma unroll
            for (int mt = 0; mt < 2; mt++)
                ldm4(ah[mt], SA + (wm + mt * 16) * 144 + aoffl + ks * 32);
            #pragma unroll
            for (int np = 0; np < 4; np++) {
                uint32_t bh[4];
                ldm4(bh, SA + 18432 + (wn + np * 16) * 144 + boffl + ks * 32);
                #pragma unroll
                for (int mt = 0; mt < 2; mt++) {
                    mmabf(acc[mt][2*np],   ah[mt], bh);
                    mmabf(acc[mt][2*np+1], ah[mt], bh + 2);
                }
            }
        }
        st = (st == 2) ? 0 : st + 1;
        ld = (ld == 2) ? 0 : ld + 1;
    }

    #pragma unroll
    for (int mt = 0; mt < 2; mt++) {
        int row0 = m0 + wm + mt * 16 + (lane >> 2);
        #pragma unroll
        for (int nt = 0; nt < 8; nt++) {
            int col = n0 + wn + nt * 8 + cq;
            float b0 = bias[col], b1 = bias[col + 1];
            float c00 = acc[mt][nt][0] + b0, c01 = acc[mt][nt][1] + b1;
            float c10 = acc[mt][nt][2] + b0, c11 = acc[mt][nt][3] + b1;
            if (z == 3) {
                *(uint32_t*)(V1b + (size_t)row0 * Dc + col)       = packbf2(c00, c01);
                *(uint32_t*)(V1b + (size_t)(row0 + 8) * Dc + col) = packbf2(c10, c11);
            } else {
                uint8_t* dst = (z == 1) ? Q1f8 : K1f8;
                *(uint16_t*)(dst + (size_t)row0 * Dc + col)       = packf8(c00 * 16.f, c01 * 16.f);
                *(uint16_t*)(dst + (size_t)(row0 + 8) * Dc + col) = packf8(c10 * 16.f, c11 * 16.f);
            }
        }
    }
}

// ---------------- flash attention: fp8 QK + bf16 PV, 3-stage, 1 barrier/chunk ---
// smem: Q 128x80B | K[3] 64x80B | V[3] 64x144B | mask[3] 64 ints
#define AQ_OFF   0
#define AK_OFF   10240
#define AV_OFF   25600
#define AM_OFF   53248
#define ASMEM    54016
__global__ __launch_bounds__(256, 2) void attn_mma_kernel(const uint8_t* __restrict__ Qf8,
                                                          const uint8_t* __restrict__ Kf8,
                                                          const bf16* __restrict__ Vb,
                                                          const int* __restrict__ cmask,
                                                          const int* __restrict__ cnt,
                                                          bf16* __restrict__ O1) {
    extern __shared__ char sm[];
    uint32_t sb = smem_u32(sm);
    int tid = threadIdx.x, lane = tid & 31, warp = tid >> 5;
    int q0 = blockIdx.x * 128;
    int h  = blockIdx.y;
    int b  = blockIdx.z;
    const uint8_t* Qg = Qf8 + ((size_t)(b * SQc + q0)) * Dc + h * DHc;
    const uint8_t* Kg = Kf8 + ((size_t)b * SKc) * Dc + h * DHc;
    const bf16*    Vg = Vb  + ((size_t)b * SKc) * Dc + h * DHc;
    const int*     mg = cmask + b * SKc;
    int nch = (cnt[b] + 63) >> 6;

    auto ldkv = [&](int st, int k0) {
        {
            int r = tid >> 2, c = tid & 3;
            cpa16(sb + AK_OFF + st * 5120 + r * 80 + c * 16,
                  Kg + (size_t)(k0 + r) * Dc + c * 16);
        }
        #pragma unroll
        for (int i = 0; i < 2; i++) {
            int idx = tid + i * 256;
            int r = idx >> 3, c = idx & 7;
            cpa16(sb + AV_OFF + st * 9216 + r * 144 + c * 16,
                  Vg + (size_t)(k0 + r) * Dc + c * 8);
        }
        if (tid < 16) cpa16(sb + AM_OFF + st * 256 + tid * 16, mg + k0 + tid * 4);
    };

    #pragma unroll
    for (int i = 0; i < 2; i++) {
        int idx = tid + i * 256;
        int r = idx >> 2, c = idx & 3;
        cpa16(sb + AQ_OFF + r * 80 + c * 16, Qg + (size_t)r * Dc + c * 16);
    }
    ldkv(0, 0);
    cp_commit();
    if (nch > 1) { ldkv(1, 64); cp_commit(); }

    int m0 = warp * 16;
    int g8 = lane >> 3, r8 = lane & 7;
    int cq = 2 * (lane & 3);
    uint32_t qaddr = sb + AQ_OFF + (m0 + (lane & 15)) * 80 + (lane >> 4) * 16;
    uint32_t klane = ((g8 >> 1) * 8 + r8) * 80 + (g8 & 1) * 16;
    uint32_t vlane = ((g8 & 1) * 8 + r8) * 144 + (g8 >> 1) * 16;
    const float SC2 = 0.03125f / 256.f;

    float o[8][4];
    #pragma unroll
    for (int dt = 0; dt < 8; dt++)
        #pragma unroll
        for (int j = 0; j < 4; j++) o[dt][j] = 0.f;
    float ls0 = 0.f, ls1 = 0.f;
    int st = 0, ld = 2;

    #pragma unroll 1
    for (int c = 0; c < nch; c++) {
        if (c + 1 < nch) cp_wait<1>(); else cp_wait<0>();
        __syncthreads();
        if (c + 2 < nch) { ldkv(ld, (c + 2) * 64); cp_commit(); }

        uint32_t Kst = sb + AK_OFF + st * 5120 + klane;
        uint32_t Vst = sb + AV_OFF + st * 9216 + vlane;
        const int* mp = (const int*)(sm + AM_OFF + st * 256);

        float s_[8][4];
        #pragma unroll
        for (int nt = 0; nt < 8; nt++)
            #pragma unroll
            for (int j = 0; j < 4; j++) s_[nt][j] = 0.f;
        #pragma unroll
        for (int ks = 0; ks < 2; ks++) {
            uint32_t aq[4];
            ldm4(aq, qaddr + ks * 32);
            #pragma unroll
            for (int np = 0; np < 4; np++) {
                uint32_t bk[4];
                ldm4(bk, Kst + np * 1280 + ks * 32);
                mmaf8(s_[2*np],   aq, bk);
                mmaf8(s_[2*np+1], aq, bk + 2);
            }
        }

        uint32_t pr0[8], pr1[8];
        #pragma unroll
        for (int nt = 0; nt < 8; nt++) {
            float f0 = (float)mp[nt * 8 + cq];
            float f1 = (float)mp[nt * 8 + cq + 1];
            float p0 = __expf(s_[nt][0] * SC2) * f0;
            float p1 = __expf(s_[nt][1] * SC2) * f1;
            float p2 = __expf(s_[nt][2] * SC2) * f0;
            float p3 = __expf(s_[nt][3] * SC2) * f1;
            ls0 += p0 + p1;
            ls1 += p2 + p3;
            pr0[nt] = packbf2(p0, p1);
            pr1[nt] = packbf2(p2, p3);
        }

        #pragma unroll
        for (int ks2 = 0; ks2 < 4; ks2++) {
            uint32_t pf[4] = { pr0[2*ks2], pr1[2*ks2], pr0[2*ks2+1], pr1[2*ks2+1] };
            #pragma unroll
            for (int dp = 0; dp < 4; dp++) {
                uint32_t bv[4];
                ldm4t(bv, Vst + ks2 * 2304 + dp * 32);
                mmabf(o[2*dp],   pf, bv);
                mmabf(o[2*dp+1], pf, bv + 2);
            }
        }
        st = (st == 2) ? 0 : st + 1;
        ld = (ld == 2) ? 0 : ld + 1;
    }

    ls0 += __shfl_xor_sync(0xffffffffu, ls0, 1);
    ls0 += __shfl_xor_sync(0xffffffffu, ls0, 2);
    ls1 += __shfl_xor_sync(0xffffffffu, ls1, 1);
    ls1 += __shfl_xor_sync(0xffffffffu, ls1, 2);
    float i0 = 1.f / ls0, i1 = 1.f / ls1;
    int row0 = q0 + m0 + (lane >> 2);
    bf16* Or0 = O1 + ((size_t)(b * SQc) + row0) * Dc + h * DHc + cq;
    bf16* Or1 = Or0 + (size_t)8 * Dc;
    #pragma unroll
    for (int dt = 0; dt < 8; dt++) {
        *(uint32_t*)(Or0 + dt * 8) = packbf2(o[dt][0] * i0, o[dt][1] * i0);
        *(uint32_t*)(Or1 + dt * 8) = packbf2(o[dt][2] * i1, o[dt][3] * i1);
    }
}

// ---------------- final LayerNorm over (bf16 O1 + O2s) --------------------------
__global__ __launch_bounds__(256) void final_ln_kernel(const bf16* __restrict__ O1,
                                                       const float* __restrict__ O2s,
                                                       const float* __restrict__ g,
                                                       const float* __restrict__ b,
                                                       float* __restrict__ out) {
    int row = blockIdx.x;
    int t = threadIdx.x;
    size_t base = (size_t)row * Dc;
    __nv_bfloat162 a0 = *(const __nv_bfloat162*)(O1 + base + t * 4);
    __nv_bfloat162 a1 = *(const __nv_bfloat162*)(O1 + base + t * 4 + 2);
    float4 o2 = ((const float4*)(O2s + base))[t];
    float4 v;
    v.x = __bfloat162float(a0.x) + o2.x;
    v.y = __bfloat162float(a0.y) + o2.y;
    v.z = __bfloat162float(a1.x) + o2.z;
    v.w = __bfloat162float(a1.y) + o2.w;
    float s  = v.x + v.y + v.z + v.w;
    float ss = v.x*v.x + v.y*v.y + v.z*v.z + v.w*v.w;
    #pragma unroll
    for (int o = 16; o > 0; o >>= 1) {
        s  += __shfl_xor_sync(0xffffffffu, s,  o);
        ss += __shfl_xor_sync(0xffffffffu, ss, o);
    }
    __shared__ float red[2][8];
    int w = t >> 5, l = t & 31;
    if (l == 0) { red[0][w] = s; red[1][w] = ss; }
    __syncthreads();
    float st = 0.f, sst = 0.f;
    #pragma unroll
    for (int i = 0; i < 8; i++) { st += red[0][i]; sst += red[1][i]; }
    float mean = st * (1.0f / Dc);
    float var  = sst * (1.0f / Dc) - mean * mean;
    float rstd = rsqrtf(var + 1e-5f);
    float4 gg = ((const float4*)g)[t];
    float4 bb = ((const float4*)b)[t];
    float4 o;
    o.x = (v.x - mean) * rstd * gg.x + bb.x;
    o.y = (v.y - mean) * rstd * gg.y + bb.y;
    o.z = (v.z - mean) * rstd * gg.z + bb.z;
    o.w = (v.w - mean) * rstd * gg.w + bb.w;
    ((float4*)(out + base))[t] = o;
}

// ---------------- launch -------------------------------------------------------
extern "C" void kernel_launch(void* const* d_in, const int* in_sizes, int n_in,
                              void* d_out, int out_size) {
    const float* Q       = (const float*)d_in[0];
    const float* K       = (const float*)d_in[1];
    const int*   padm    = (const int*)d_in[2];
    const float* Wq      = (const float*)d_in[3];
    const float* Wk      = (const float*)d_in[4];
    const float* Wv      = (const float*)d_in[5];
    const float* Wo      = (const float*)d_in[6];
    const float* bq      = (const float*)d_in[7];
    const float* bk      = (const float*)d_in[8];
    const float* bv      = (const float*)d_in[9];
    const float* bo      = (const float*)d_in[10];
    const float* ln_q_g  = (const float*)d_in[11];
    const float* ln_q_b  = (const float*)d_in[12];
    const float* ln_kv_g = (const float*)d_in[13];
    const float* ln_kv_b = (const float*)d_in[14];
    const float* ln_f_g  = (const float*)d_in[15];
    const float* ln_f_b  = (const float*)d_in[16];
    float* out = (float*)d_out;

    bf16 *pQh, *pKh, *pWqh, *pWkh, *pWvh, *pV1b, *pO1;
    uint8_t *pQ1f8, *pK1f8;
    float *pQn, *pWot, *pO2;
    int *pPos, *pCmask, *pCnt;
    cudaGetSymbolAddress((void**)&pQh, g_Qh);
    cudaGetSymbolAddress((void**)&pQn, g_Qn);
    cudaGetSymbolAddress((void**)&pKh, g_Kh);
    cudaGetSymbolAddress((void**)&pWqh, g_Wqh);
    cudaGetSymbolAddress((void**)&pWkh, g_Wkh);
    cudaGetSymbolAddress((void**)&pWvh, g_Wvh);
    cudaGetSymbolAddress((void**)&pWot, g_Wot);
    cudaGetSymbolAddress((void**)&pQ1f8, g_Q1f8);
    cudaGetSymbolAddress((void**)&pK1f8, g_K1f8);
    cudaGetSymbolAddress((void**)&pV1b, g_V1b);
    cudaGetSymbolAddress((void**)&pO1, g_O1);
    cudaGetSymbolAddress((void**)&pO2, g_O2);
    cudaGetSymbolAddress((void**)&pPos, g_pos);
    cudaGetSymbolAddress((void**)&pCmask, g_cmask);
    cudaGetSymbolAddress((void**)&pCnt, g_cnt);

    cudaFuncSetAttribute(gemm_all_kernel, cudaFuncAttributeMaxDynamicSharedMemorySize, GSMEM);
    cudaFuncSetAttribute(attn_mma_kernel, cudaFuncAttributeMaxDynamicSharedMemorySize, ASMEM);

    prefix_kernel<<<Bc, 1024>>>(padm, pPos, pCmask, pCnt, pKh);
    ln_both_kernel<<<2 * NTOK, 256>>>(Q, K, ln_q_g, ln_q_b, ln_kv_g, ln_kv_b,
                                      padm, pPos, pQh, pQn, pKh);
    wconv_kernel<<<4096, 256>>>(Wq, Wk, Wv, Wo, pWqh, pWkh, pWvh, pWot);

    dim3 ggrid(Dc / 128, NTOK / 128, 4);   // (8, 32, 4)
    gemm_all_kernel<<<ggrid, 256, GSMEM>>>(pQh, pKh, pQn, pWot,
                                           pWqh, pWkh, pWvh,
                                           bq, bk, bv, bo, Q, pCnt,
                                           pQ1f8, pK1f8, pV1b, pO2);

    dim3 agrid(SQc / 128, Hc, Bc);         // (16, 16, 2)
    attn_mma_kernel<<<agrid, 256, ASMEM>>>(pQ1f8, pK1f8, pV1b, pCmask, pCnt, pO1);

    final_ln_kernel<<<NTOK, 256>>>(pO1, pO2, ln_f_g, ln_f_b, out);
}